// round 12
// baseline (speedup 1.0000x reference)
#include <cuda_runtime.h>
#include <cuda_fp16.h>
#include <math.h>

#define B_    2
#define LF_   2048
#define TS_   512
#define D2_   512
#define H_    8
#define HD_   64
#define POOLH 2048

typedef unsigned long long u64;
typedef unsigned int u32;
typedef unsigned short u16;

// ---------------------------------------------------------------------------
// fp16 split/pack + MMA + ldmatrix + cp.async helpers
// ---------------------------------------------------------------------------
__device__ __forceinline__ void split_f16(float x, float &hi, float &lo) {
    hi = __half2float(__float2half_rn(x));
    lo = x - hi;
}
__device__ __forceinline__ u32 pack_f16(float a, float b) {
    __half2 t = __floats2half2_rn(a, b);
    return *(u32*)&t;
}
__device__ __forceinline__ u64 pack4_f16(float a, float b, float c, float d) {
    return (u64)pack_f16(a, b) | ((u64)pack_f16(c, d) << 32);
}
__device__ __forceinline__ float exp2a(float x) {
    float r;
    asm("ex2.approx.f32 %0, %1;" : "=f"(r) : "f"(x));
    return r;
}
__device__ __forceinline__ void mma_f16(float c[4], u32 a0, u32 a1, u32 a2, u32 a3,
                                        u32 b0, u32 b1) {
    asm volatile(
        "mma.sync.aligned.m16n8k16.row.col.f32.f16.f16.f32 "
        "{%0,%1,%2,%3}, {%4,%5,%6,%7}, {%8,%9}, {%0,%1,%2,%3};\n"
        : "+f"(c[0]), "+f"(c[1]), "+f"(c[2]), "+f"(c[3])
        : "r"(a0), "r"(a1), "r"(a2), "r"(a3), "r"(b0), "r"(b1));
}
__device__ __forceinline__ u32 smaddr(const void* p) {
    return (u32)__cvta_generic_to_shared(p);
}
__device__ __forceinline__ void ldsm4(u32 r[4], u32 addr) {
    asm volatile("ldmatrix.sync.aligned.m8n8.x4.shared.b16 {%0,%1,%2,%3}, [%4];"
                 : "=r"(r[0]), "=r"(r[1]), "=r"(r[2]), "=r"(r[3]) : "r"(addr));
}
__device__ __forceinline__ void ldsm4t(u32 r[4], u32 addr) {
    asm volatile("ldmatrix.sync.aligned.m8n8.x4.trans.shared.b16 {%0,%1,%2,%3}, [%4];"
                 : "=r"(r[0]), "=r"(r[1]), "=r"(r[2]), "=r"(r[3]) : "r"(addr));
}
__device__ __forceinline__ void cp_async16(u32 dst, const void* src) {
    asm volatile("cp.async.cg.shared.global [%0], [%1], 16;" :: "r"(dst), "l"(src));
}
__device__ __forceinline__ void cp_async16z(u32 dst, const void* src, u32 sz) {
    asm volatile("cp.async.cg.shared.global [%0], [%1], 16, %2;"
                 :: "r"(dst), "l"(src), "r"(sz));
}
#define CP_COMMIT() asm volatile("cp.async.commit_group;")
#define CP_WAIT(n)  asm volatile("cp.async.wait_group %0;" :: "n"(n))

// XOR-swizzled smem addressing: 64 u16 per row (128B), chunk ^= row&7.
__device__ __forceinline__ u16* swp(u16* base, int row, int col) {
    return base + row * 64 + ((((col >> 3) ^ (row & 7)) << 3) | (col & 7));
}
__device__ __forceinline__ const u16* swp(const u16* base, int row, int col) {
    return base + row * 64 + ((((col >> 3) ^ (row & 7)) << 3) | (col & 7));
}

// combined softmax scale: 1/sqrt(64) * log2(e)
#define QSCALE 0.18033688011112042f

// ---------------------------------------------------------------------------
// Scratch layout (float units).
// ---------------------------------------------------------------------------
static const size_t O_XF    = 0;
static const size_t O_XS    = 4194304;
static const size_t O_WFS   = 5242880;
static const size_t O_WFC   = 6029312;
static const size_t O_WSS   = 6815744;
static const size_t O_WSC   = 7602176;
static const size_t O_WOF   = 8388608;
static const size_t O_WOC   = 8650752;
static const size_t O_WOS   = 8912896;
static const size_t O_WOSC  = 9175040;
static const size_t O_WL    = 9437184;
static const size_t O_WP1   = 9961472;
static const size_t O_WP2   = 18350080;
static const size_t O_Y     = 19398656;
static const size_t O_QKV_F = 19922944;
static const size_t O_Q_FC  = 26214400;
static const size_t O_KV_FC = 28311552;
static const size_t O_O1    = 29360128;
static const size_t O_O2    = 31457280;
static const size_t O_H1    = 33554432;
static const size_t O_S     = 35651584;
static const size_t O_QKV_S = 36175872;
static const size_t O_Q_SC  = 37748736;
static const size_t O_KV_SC = 38273024;
static const size_t O_O3    = 39321600;
static const size_t O_O4    = 39845888;
static const size_t SCRATCH_FLOATS = 40370176;

__device__ float g_scratch[SCRATCH_FLOATS];

// ---------------------------------------------------------------------------
// Batched split pass: fp32 -> fp16 hi/lo planes
// ---------------------------------------------------------------------------
#define SD_MAX 14
struct SplitDesc { const float* src; u16* dst; int nelem; int blk0; };
struct SplitBatch { SplitDesc d[SD_MAX]; int n; };

__global__ __launch_bounds__(256) void split_kernel(SplitBatch b)
{
    int pi = 0;
    #pragma unroll
    for (int i = 1; i < SD_MAX; i++)
        if (i < b.n && (int)blockIdx.x >= b.d[i].blk0) pi = i;
    const SplitDesc D = b.d[pi];
    const int idx = ((blockIdx.x - D.blk0) * 256 + threadIdx.x) * 4;
    float4 v = *(const float4*)(D.src + idx);
    float h0, l0, h1, l1, h2, l2, h3, l3;
    split_f16(v.x, h0, l0); split_f16(v.y, h1, l1);
    split_f16(v.z, h2, l2); split_f16(v.w, h3, l3);
    *(u64*)&D.dst[idx]           = pack4_f16(h0, h1, h2, h3);
    *(u64*)&D.dst[idx + D.nelem] = pack4_f16(l0, l1, l2, l3);
}

// ---------------------------------------------------------------------------
// Batched GEMM v5: A = fp16 hi/lo (2 terms), W = fp16 hi only.
// Block tile 128x128 (traffic/output 1.67x lower than 128x64), K-chunk 32,
// 256 threads (8 warps 4x2, warp tile 32x64). W smem = two 32x64 sub-tiles
// (warp_n selects sub-tile) so all swizzle/LDSM patterns stay verified.
// 3-stage cp.async pipeline, one sync per K-chunk.
// ---------------------------------------------------------------------------
#define GD_MAX 6
struct GemmDesc {
    const u16 *A, *W;
    const float *bias;
    void *C;
    int lda, aoff, aplane, ldw, woff, wplane, ldc, coff, K;
    int ashift, nbx, blk0, outmode, qcols, oplane;
};
struct GemmBatch { GemmDesc d[GD_MAX]; int n; };

#define GT_A  (128 * 64)              // A: 128 rows x [hi k0..31 | lo k0..31]
#define GT_W0 (32 * 64)               // one W sub-tile: 32 k-rows x 64 n
#define GT_STAGE (GT_A + 2 * GT_W0)   // 12288 u16 = 24576 B
#define SMEM_GEMM (3 * GT_STAGE * 2)  // 73728 B

__global__ __launch_bounds__(256) void gemm_batch_kernel(GemmBatch batch)
{
    extern __shared__ __align__(16) u16 smg[];

    int pi = 0;
    #pragma unroll
    for (int i = 1; i < GD_MAX; i++)
        if (i < batch.n && (int)blockIdx.x >= batch.d[i].blk0) pi = i;
    const GemmDesc D = batch.d[pi];
    const int lb = blockIdx.x - D.blk0;
    const int m0 = (lb / D.nbx) * 128;
    const int n0 = (lb % D.nbx) * 128;

    const int tid  = threadIdx.x;
    const int lane = tid & 31;
    const int warp = tid >> 5;
    const int warp_m = warp >> 1;     // 0..3
    const int warp_n = warp & 1;      // 0..1 (selects 64-wide n half)
    const int g  = lane >> 2;
    const int tg = lane & 3;

    const int l15 = lane & 15;
    const int l7  = lane & 7;
    const int ka8 = (lane >> 4) * 8;
    const int wk8 = ((lane >> 3) & 1) * 8;
    const int wn8 = (lane >> 4) * 8;

    float acc[2][8][4];
    #pragma unroll
    for (int mt = 0; mt < 2; mt++)
        #pragma unroll
        for (int nt = 0; nt < 8; nt++)
            #pragma unroll
            for (int r = 0; r < 4; r++) acc[mt][nt][r] = 0.f;

    auto fill = [&](int k0, int st) {
        u16* sb = smg + st * GT_STAGE;
        // A tile: 128 rows x 8 chunks (0-3 hi, 4-7 lo)
        #pragma unroll
        for (int i = 0; i < 4; i++) {
            const int idx = tid + i * 256;
            const int row = idx >> 3, ch = idx & 7;
            const int kc = (ch & 3) * 8;
            const int pl = (ch >> 2) ? D.aplane : 0;
            int mg = m0 + row;
            u32 sz = 16;
            if (D.ashift) {
                if ((mg & 511) == 0) { sz = 0; }
                else mg -= 1;
            }
            const u16* src = D.A + pl + (size_t)(sz ? mg : 0) * D.lda + D.aoff + k0 + kc;
            cp_async16z(smaddr(swp(sb, row, ch * 8)), src, sz);
        }
        // W tiles: two sub-tiles of 32 k-rows x 64 n (hi plane only)
        u16* wb = sb + GT_A;
        #pragma unroll
        for (int i = 0; i < 2; i++) {
            const int idx = tid + i * 256;            // 0..511
            const int sub = idx >> 8;                 // 0,1
            const int rr  = (idx >> 3) & 31;          // k-row 0..31
            const int ch  = idx & 7;
            const u16* src = D.W + (size_t)(k0 + rr) * D.ldw + D.woff + n0 + sub * 64 + ch * 8;
            cp_async16(smaddr(swp(wb + sub * GT_W0, rr, ch * 8)), src);
        }
    };

    auto do_mma = [&](int st) {
        const u16* As = smg + st * GT_STAGE;
        const u16* Ws = As + GT_A + warp_n * GT_W0;   // this warp's 64-n sub-tile
        #pragma unroll
        for (int kk = 0; kk < 2; kk++) {
            u32 afr[2][2][4];
            #pragma unroll
            for (int s = 0; s < 2; s++)
                #pragma unroll
                for (int mt = 0; mt < 2; mt++)
                    ldsm4(afr[s][mt],
                          smaddr(swp(As, warp_m * 32 + mt * 16 + l15, s * 32 + kk * 16 + ka8)));
            u32 bfr[8][2];
            #pragma unroll
            for (int ntp = 0; ntp < 4; ntp++) {
                u32 t[4];
                ldsm4t(t, smaddr(swp(Ws, kk * 16 + l7 + wk8, ntp * 16 + wn8)));
                bfr[2 * ntp][0]     = t[0]; bfr[2 * ntp][1]     = t[1];
                bfr[2 * ntp + 1][0] = t[2]; bfr[2 * ntp + 1][1] = t[3];
            }
            #pragma unroll
            for (int mt = 0; mt < 2; mt++)
                #pragma unroll
                for (int nt = 0; nt < 8; nt++) {
                    mma_f16(acc[mt][nt], afr[0][mt][0], afr[0][mt][1], afr[0][mt][2], afr[0][mt][3],
                            bfr[nt][0], bfr[nt][1]);
                    mma_f16(acc[mt][nt], afr[1][mt][0], afr[1][mt][1], afr[1][mt][2], afr[1][mt][3],
                            bfr[nt][0], bfr[nt][1]);
                }
        }
    };

    const int nk = D.K >> 5;
    fill(0, 0);
    CP_COMMIT();
    if (nk > 1) fill(32, 1);
    CP_COMMIT();

    for (int ki = 0; ki < nk; ki++) {
        CP_WAIT(1);
        __syncthreads();
        if (ki + 2 < nk) fill((ki + 2) * 32, (ki + 2) % 3);
        CP_COMMIT();
        do_mma(ki % 3);
    }

    if (D.outmode == 0) {
        float* C = (float*)D.C;
        #pragma unroll
        for (int mt = 0; mt < 2; mt++) {
            #pragma unroll
            for (int nt = 0; nt < 8; nt++) {
                const int m = m0 + warp_m * 32 + mt * 16 + g;
                const int n = n0 + warp_n * 64 + nt * 8 + tg * 2;
                const float bb0 = D.bias[n], bb1 = D.bias[n + 1];
                *(float2*)(C + (size_t)m * D.ldc + D.coff + n) =
                    make_float2(acc[mt][nt][0] + bb0, acc[mt][nt][1] + bb1);
                *(float2*)(C + (size_t)(m + 8) * D.ldc + D.coff + n) =
                    make_float2(acc[mt][nt][2] + bb0, acc[mt][nt][3] + bb1);
            }
        }
    } else {
        u16* Ch = (u16*)D.C;
        #pragma unroll
        for (int mt = 0; mt < 2; mt++) {
            #pragma unroll
            for (int nt = 0; nt < 8; nt++) {
                const int m = m0 + warp_m * 32 + mt * 16 + g;
                const int n = n0 + warp_n * 64 + nt * 8 + tg * 2;
                const float sc = (D.outmode == 2 && n < D.qcols) ? QSCALE : 1.0f;
                const float bb0 = D.bias[n], bb1 = D.bias[n + 1];
                float v[4] = {(acc[mt][nt][0] + bb0) * sc, (acc[mt][nt][1] + bb1) * sc,
                              (acc[mt][nt][2] + bb0) * sc, (acc[mt][nt][3] + bb1) * sc};
                if (D.outmode == 3) {
                    #pragma unroll
                    for (int r = 0; r < 4; r++) {
                        float x = v[r];
                        float u = 0.7978845608028654f * (x + 0.044715f * x * x * x);
                        v[r] = 0.5f * x * (1.0f + tanhf(u));
                    }
                }
                float h0, l0, h1, l1, h2, l2, h3, l3;
                split_f16(v[0], h0, l0); split_f16(v[1], h1, l1);
                split_f16(v[2], h2, l2); split_f16(v[3], h3, l3);
                const size_t o0 = (size_t)m * D.ldc + D.coff + n;
                const size_t o1 = (size_t)(m + 8) * D.ldc + D.coff + n;
                *(u32*)&Ch[o0]            = pack_f16(h0, h1);
                *(u32*)&Ch[o0 + D.oplane] = pack_f16(l0, l1);
                *(u32*)&Ch[o1]            = pack_f16(h2, h3);
                *(u32*)&Ch[o1 + D.oplane] = pack_f16(l2, l3);
            }
        }
    }
}

// ---------------------------------------------------------------------------
// Batched flash attention v5: q-tile 128 (256 threads, 8 warps) — each K/V
// tile now serves 2x the q-rows, halving gmem traffic. Q hi/lo (2 terms),
// K hi only, V hi/lo with single-fp16 P. Per-warp code identical to R10.
// ---------------------------------------------------------------------------
#define AD_MAX 4
struct AttnDesc {
    const u16 *Q, *K, *V;
    u16 *O;
    int ldq, qoff, qplane, ldk, koff, kplane, ldv, voff, vplane;
    int ldo, oplane, Tq, Tk, nbx, blk0;
};
struct AttnBatch { AttnDesc d[AD_MAX]; int n; };

#define STAGE_U16 (192 * 64)            // K hi (64 rows) + V hi/lo (128 rows)
#define SMEM_ATTN (2 * STAGE_U16 * 2)   // 49152 bytes

__global__ __launch_bounds__(256) void attn_batch_kernel(AttnBatch batch)
{
    extern __shared__ __align__(16) u16 smu[];

    int pi = 0;
    #pragma unroll
    for (int i = 1; i < AD_MAX; i++)
        if (i < batch.n && (int)blockIdx.x >= batch.d[i].blk0) pi = i;
    const AttnDesc D = batch.d[pi];
    const int lb = blockIdx.x - D.blk0;
    const int qt = lb % D.nbx;
    const int h  = (lb / D.nbx) % H_;
    const int b  = lb / (D.nbx * H_);

    const int tid  = threadIdx.x;
    const int lane = tid & 31;
    const int warp = tid >> 5;        // 0..7
    const int g  = lane >> 2;
    const int tg = lane & 3;
    const int mrow = warp * 16;       // 0..112

    const int l15 = lane & 15;
    const int l7  = lane & 7;
    const int qc8 = (lane >> 4) * 8;
    const int kk8 = (lane >> 4) * 8;
    const int kd8 = ((lane >> 3) & 1) * 8;
    const int vk8 = ((lane >> 3) & 1) * 8;
    const int vd8 = (lane >> 4) * 8;

    const u16* Qb = D.Q + (size_t)(b * D.Tq + qt * 128) * D.ldq + D.qoff + h * HD_;
    const u16* Kb = D.K + (size_t)(b * D.Tk) * D.ldk + D.koff + h * HD_;
    const u16* Vb = D.V + (size_t)(b * D.Tk) * D.ldv + D.voff + h * HD_;

    // fill one KV tile: K hi (rows 0-63), V hi (64-127), V lo (128-191)
    auto fill = [&](int kt, int st) {
        u16* sb = smu + st * STAGE_U16;
        #pragma unroll
        for (int i = 0; i < 6; i++) {
            const int idx = tid + i * 256;          // 0..1535
            const int plane = idx >> 9;             // 0 Khi, 1 Vhi, 2 Vlo
            const int sub = idx & 511;
            const int r = sub >> 3;
            const int c = (sub & 7) * 8;
            const u16* src;
            if (plane == 0)      src = Kb + (size_t)(kt + r) * D.ldk + c;
            else if (plane == 1) src = Vb + (size_t)(kt + r) * D.ldv + c;
            else                 src = Vb + D.vplane + (size_t)(kt + r) * D.ldv + c;
            cp_async16(smaddr(swp(sb, plane * 64 + r, c)), src);
        }
    };

    // prologue: Q hi -> stage0 rows 0..127, Q lo -> stage1 rows 0..127
    #pragma unroll
    for (int i = 0; i < 4; i++) {
        const int idx = tid + i * 256;              // 0..1023
        const int r = idx >> 3;
        const int c = (idx & 7) * 8;
        cp_async16(smaddr(swp(smu, r, c)), Qb + (size_t)r * D.ldq + c);
        cp_async16(smaddr(swp(smu + STAGE_U16, r, c)),
                   Qb + D.qplane + (size_t)r * D.ldq + c);
    }
    CP_COMMIT();
    CP_WAIT(0);
    __syncthreads();

    u32 qh[4][4], ql[4][4];
    #pragma unroll
    for (int kc = 0; kc < 4; kc++) {
        ldsm4(qh[kc], smaddr(swp(smu, mrow + l15, kc * 16 + qc8)));
        ldsm4(ql[kc], smaddr(swp(smu + STAGE_U16, mrow + l15, kc * 16 + qc8)));
    }
    __syncthreads();    // all warps done reading Q before stages are refilled

    fill(0, 0);
    CP_COMMIT();

    float acc[8][4];
    #pragma unroll
    for (int nt = 0; nt < 8; nt++)
        #pragma unroll
        for (int r = 0; r < 4; r++) acc[nt][r] = 0.f;
    float mx0 = -1e30f, mx1 = -1e30f, lsum0 = 0.f, lsum1 = 0.f;

    const int ntile = D.Tk >> 6;
    for (int it = 0; it < ntile; it++) {
        const int st = it & 1;
        __syncthreads();
        if (it + 1 < ntile) fill((it + 1) * 64, 1 - st);
        CP_COMMIT();
        CP_WAIT(1);
        __syncthreads();

        const u16* sb = smu + st * STAGE_U16;

        // ---- S = Q K^T : (Q_hi + Q_lo) x K_hi ----
        float s[8][4];
        #pragma unroll
        for (int nt = 0; nt < 8; nt++)
            #pragma unroll
            for (int r = 0; r < 4; r++) s[nt][r] = 0.f;

        #pragma unroll
        for (int kc = 0; kc < 4; kc++) {
            #pragma unroll
            for (int ntp = 0; ntp < 4; ntp++) {
                u32 kh[4];
                ldsm4(kh, smaddr(swp(sb, ntp * 16 + l7 + kk8, kc * 16 + kd8)));
                mma_f16(s[2 * ntp],     qh[kc][0], qh[kc][1], qh[kc][2], qh[kc][3], kh[0], kh[1]);
                mma_f16(s[2 * ntp],     ql[kc][0], ql[kc][1], ql[kc][2], ql[kc][3], kh[0], kh[1]);
                mma_f16(s[2 * ntp + 1], qh[kc][0], qh[kc][1], qh[kc][2], qh[kc][3], kh[2], kh[3]);
                mma_f16(s[2 * ntp + 1], ql[kc][0], ql[kc][1], ql[kc][2], ql[kc][3], kh[2], kh[3]);
            }
        }

        // ---- online softmax (exp2 domain) ----
        float rm0 = -1e30f, rm1 = -1e30f;
        #pragma unroll
        for (int nt = 0; nt < 8; nt++) {
            rm0 = fmaxf(rm0, fmaxf(s[nt][0], s[nt][1]));
            rm1 = fmaxf(rm1, fmaxf(s[nt][2], s[nt][3]));
        }
        rm0 = fmaxf(rm0, __shfl_xor_sync(0xffffffffu, rm0, 1));
        rm0 = fmaxf(rm0, __shfl_xor_sync(0xffffffffu, rm0, 2));
        rm1 = fmaxf(rm1, __shfl_xor_sync(0xffffffffu, rm1, 1));
        rm1 = fmaxf(rm1, __shfl_xor_sync(0xffffffffu, rm1, 2));

        const float mn0 = fmaxf(mx0, rm0);
        const float mn1 = fmaxf(mx1, rm1);
        const float corr0 = exp2a(mx0 - mn0);
        const float corr1 = exp2a(mx1 - mn1);
        float rs0 = 0.f, rs1 = 0.f;
        #pragma unroll
        for (int nt = 0; nt < 8; nt++) {
            s[nt][0] = exp2a(s[nt][0] - mn0); rs0 += s[nt][0];
            s[nt][1] = exp2a(s[nt][1] - mn0); rs0 += s[nt][1];
            s[nt][2] = exp2a(s[nt][2] - mn1); rs1 += s[nt][2];
            s[nt][3] = exp2a(s[nt][3] - mn1); rs1 += s[nt][3];
        }
        rs0 += __shfl_xor_sync(0xffffffffu, rs0, 1);
        rs0 += __shfl_xor_sync(0xffffffffu, rs0, 2);
        rs1 += __shfl_xor_sync(0xffffffffu, rs1, 1);
        rs1 += __shfl_xor_sync(0xffffffffu, rs1, 2);
        lsum0 = lsum0 * corr0 + rs0; mx0 = mn0;
        lsum1 = lsum1 * corr1 + rs1; mx1 = mn1;
        #pragma unroll
        for (int nt = 0; nt < 8; nt++) {
            acc[nt][0] *= corr0; acc[nt][1] *= corr0;
            acc[nt][2] *= corr1; acc[nt][3] *= corr1;
        }

        // ---- O += P V : P single fp16, V = V_hi + V_lo ----
        #pragma unroll
        for (int kc = 0; kc < 4; kc++) {
            const int j0 = 2 * kc, j1 = 2 * kc + 1;
            u32 pa[4];
            pa[0] = pack_f16(s[j0][0], s[j0][1]);
            pa[1] = pack_f16(s[j0][2], s[j0][3]);
            pa[2] = pack_f16(s[j1][0], s[j1][1]);
            pa[3] = pack_f16(s[j1][2], s[j1][3]);

            #pragma unroll
            for (int ntp = 0; ntp < 4; ntp++) {
                u32 vh[4], vl[4];
                ldsm4t(vh, smaddr(swp(sb, 64 + kc * 16 + l7 + vk8, ntp * 16 + vd8)));
                ldsm4t(vl, smaddr(swp(sb, 128 + kc * 16 + l7 + vk8, ntp * 16 + vd8)));
                mma_f16(acc[2 * ntp],     pa[0], pa[1], pa[2], pa[3], vh[0], vh[1]);
                mma_f16(acc[2 * ntp],     pa[0], pa[1], pa[2], pa[3], vl[0], vl[1]);
                mma_f16(acc[2 * ntp + 1], pa[0], pa[1], pa[2], pa[3], vh[2], vh[3]);
                mma_f16(acc[2 * ntp + 1], pa[0], pa[1], pa[2], pa[3], vl[2], vl[3]);
            }
        }
    }

    const float inv0 = 1.0f / lsum0;
    const float inv1 = 1.0f / lsum1;
    u16* Ob = D.O + (size_t)(b * D.Tq + qt * 128 + mrow) * D.ldo + h * HD_;
    #pragma unroll
    for (int nt = 0; nt < 8; nt++) {
        const int col = nt * 8 + 2 * tg;
        float h0, l0, h1, l1;
        split_f16(acc[nt][0] * inv0, h0, l0);
        split_f16(acc[nt][1] * inv0, h1, l1);
        const size_t o0 = (size_t)g * D.ldo + col;
        *(u32*)&Ob[o0]            = pack_f16(h0, h1);
        *(u32*)&Ob[o0 + D.oplane] = pack_f16(l0, l1);
        split_f16(acc[nt][2] * inv1, h0, l0);
        split_f16(acc[nt][3] * inv1, h1, l1);
        const size_t o1 = (size_t)(g + 8) * D.ldo + col;
        *(u32*)&Ob[o1]            = pack_f16(h0, h1);
        *(u32*)&Ob[o1 + D.oplane] = pack_f16(l0, l1);
    }
}

// ---------------------------------------------------------------------------
// Host orchestration: split pass + 5 launches
// ---------------------------------------------------------------------------
static inline GemmDesc mk_gemm(const u16* A, int lda, int aoff, int aplane,
                               const u16* W, int ldw, int woff, int wplane,
                               const float* bias, void* C, int ldc, int coff,
                               int M, int N, int K, int ashift,
                               int outmode, int qcols, int oplane,
                               int& blk_cursor)
{
    GemmDesc d;
    d.A = A; d.W = W; d.bias = bias; d.C = C;
    d.lda = lda; d.aoff = aoff; d.aplane = aplane;
    d.ldw = ldw; d.woff = woff; d.wplane = wplane;
    d.ldc = ldc; d.coff = coff; d.K = K; d.ashift = ashift;
    d.outmode = outmode; d.qcols = qcols; d.oplane = oplane;
    d.nbx = N / 128; d.blk0 = blk_cursor;
    blk_cursor += (N / 128) * (M / 128);
    return d;
}

static inline AttnDesc mk_attn(const u16* Q, int ldq, int qoff, int qplane,
                               const u16* K, int ldk, int koff, int kplane,
                               const u16* V, int ldv, int voff, int vplane,
                               u16* O, int ldo, int oplane,
                               int Tq, int Tk, int& blk_cursor)
{
    AttnDesc d;
    d.Q = Q; d.K = K; d.V = V; d.O = O;
    d.ldq = ldq; d.qoff = qoff; d.qplane = qplane;
    d.ldk = ldk; d.koff = koff; d.kplane = kplane;
    d.ldv = ldv; d.voff = voff; d.vplane = vplane;
    d.ldo = ldo; d.oplane = oplane;
    d.Tq = Tq; d.Tk = Tk; d.nbx = Tq / 128; d.blk0 = blk_cursor;
    blk_cursor += (Tq / 128) * H_ * B_;
    return d;
}

static inline SplitDesc mk_split(const float* src, u16* dst, int nelem, int& blk_cursor)
{
    SplitDesc d;
    d.src = src; d.dst = dst; d.nelem = nelem; d.blk0 = blk_cursor;
    blk_cursor += nelem / 1024;
    return d;
}

extern "C" void kernel_launch(void* const* d_in, const int* in_sizes, int n_in,
                              void* d_out, int out_size)
{
    (void)in_sizes; (void)n_in; (void)out_size;

    const float* x_fast      = (const float*)d_in[0];
    const float* x_slow      = (const float*)d_in[1];
    const float* fself_wqkv  = (const float*)d_in[2];
    const float* fself_bqkv  = (const float*)d_in[3];
    const float* fself_wo    = (const float*)d_in[4];
    const float* fself_bo    = (const float*)d_in[5];
    const float* fcross_wqkv = (const float*)d_in[6];
    const float* fcross_bqkv = (const float*)d_in[7];
    const float* fcross_wo   = (const float*)d_in[8];
    const float* fcross_bo   = (const float*)d_in[9];
    const float* sself_wqkv  = (const float*)d_in[10];
    const float* sself_bqkv  = (const float*)d_in[11];
    const float* sself_wo    = (const float*)d_in[12];
    const float* sself_bo    = (const float*)d_in[13];
    const float* scross_wqkv = (const float*)d_in[14];
    const float* scross_bqkv = (const float*)d_in[15];
    const float* scross_wo   = (const float*)d_in[16];
    const float* scross_bo   = (const float*)d_in[17];
    const float* lift_w      = (const float*)d_in[18];
    const float* lift_b      = (const float*)d_in[19];
    const float* pool_w1     = (const float*)d_in[20];
    const float* pool_b1     = (const float*)d_in[21];
    const float* pool_w2     = (const float*)d_in[22];
    const float* pool_b2     = (const float*)d_in[23];

    float* out = (float*)d_out;
    float* zf = out;
    float* zs = out + (size_t)B_ * LF_ * 1024;

    float* S0 = nullptr;
    cudaGetSymbolAddress((void**)&S0, g_scratch);
    u16* xf    = (u16*)(S0 + O_XF);
    u16* xs    = (u16*)(S0 + O_XS);
    u16* wfs   = (u16*)(S0 + O_WFS);
    u16* wfc   = (u16*)(S0 + O_WFC);
    u16* wss   = (u16*)(S0 + O_WSS);
    u16* wsc   = (u16*)(S0 + O_WSC);
    u16* wof   = (u16*)(S0 + O_WOF);
    u16* woc   = (u16*)(S0 + O_WOC);
    u16* wos   = (u16*)(S0 + O_WOS);
    u16* wosc  = (u16*)(S0 + O_WOSC);
    u16* wl    = (u16*)(S0 + O_WL);
    u16* wp1   = (u16*)(S0 + O_WP1);
    u16* wp2   = (u16*)(S0 + O_WP2);
    u16* y     = (u16*)(S0 + O_Y);
    u16* qkv_f = (u16*)(S0 + O_QKV_F);
    u16* q_fc  = (u16*)(S0 + O_Q_FC);
    u16* kv_fc = (u16*)(S0 + O_KV_FC);
    u16* o1    = (u16*)(S0 + O_O1);
    u16* o2    = (u16*)(S0 + O_O2);
    u16* h1    = (u16*)(S0 + O_H1);
    u16* s     = (u16*)(S0 + O_S);
    u16* qkv_s = (u16*)(S0 + O_QKV_S);
    u16* q_sc  = (u16*)(S0 + O_Q_SC);
    u16* kv_sc = (u16*)(S0 + O_KV_SC);
    u16* o3    = (u16*)(S0 + O_O3);
    u16* o4    = (u16*)(S0 + O_O4);

    const int P_XF   = 4194304, P_XS  = 1048576;
    const int P_WQKV = 786432,  P_WO  = 262144, P_WL = 524288;
    const int P_WP1  = 8388608, P_WP2 = 1048576;
    const int P_QKVF = 6291456, P_QFC = 2097152, P_KVFC = 1048576;
    const int P_QKVS = 1572864, P_QSC = 524288,  P_KVSC = 1048576;
    const int P_O12  = 2097152, P_O34 = 524288;
    const int P_Y    = 524288,  P_H1  = 2097152, P_S = 524288;

    cudaFuncSetAttribute(gemm_batch_kernel,
                         cudaFuncAttributeMaxDynamicSharedMemorySize, SMEM_GEMM);
    cudaFuncSetAttribute(attn_batch_kernel,
                         cudaFuncAttributeMaxDynamicSharedMemorySize, SMEM_ATTN);

    // ---- L0: split inputs + weights into fp16 hi/lo planes ----
    {
        SplitBatch sb; int cur = 0;
        sb.d[0]  = mk_split(x_fast,      xf,   P_XF,   cur);
        sb.d[1]  = mk_split(x_slow,      xs,   P_XS,   cur);
        sb.d[2]  = mk_split(fself_wqkv,  wfs,  P_WQKV, cur);
        sb.d[3]  = mk_split(fcross_wqkv, wfc,  P_WQKV, cur);
        sb.d[4]  = mk_split(sself_wqkv,  wss,  P_WQKV, cur);
        sb.d[5]  = mk_split(scross_wqkv, wsc,  P_WQKV, cur);
        sb.d[6]  = mk_split(fself_wo,    wof,  P_WO,   cur);
        sb.d[7]  = mk_split(fcross_wo,   woc,  P_WO,   cur);
        sb.d[8]  = mk_split(sself_wo,    wos,  P_WO,   cur);
        sb.d[9]  = mk_split(scross_wo,   wosc, P_WO,   cur);
        sb.d[10] = mk_split(lift_w,      wl,   P_WL,   cur);
        sb.d[11] = mk_split(pool_w1,     wp1,  P_WP1,  cur);
        sb.d[12] = mk_split(pool_w2,     wp2,  P_WP2,  cur);
        sb.n = 13;
        split_kernel<<<cur, 256>>>(sb);
    }
    // ---- L1: input-only GEMMs ----
    {
        GemmBatch gb; int cur = 0;
        gb.d[0] = mk_gemm(xf, 1024, 0,   P_XF, wfs, 1536, 0, P_WQKV, fself_bqkv,  qkv_f, 1536, 0, 4096, 1536, 512,  0, 2, 512, P_QKVF, cur);
        gb.d[1] = mk_gemm(xf, 4096, 0,   P_XF, wp1, 2048, 0, P_WP1,  pool_b1,     h1,    2048, 0, 1024, POOLH, 4096, 0, 3, 0,   P_H1,   cur);
        gb.d[2] = mk_gemm(xf, 1024, 512, P_XF, wfc, 1536, 0, P_WQKV, fcross_bqkv, q_fc,  512,  0, 4096, 512,  512,  0, 2, 512, P_QFC,  cur);
        gb.d[3] = mk_gemm(xs, 1024, 0,   P_XS, wl,  512,  0, P_WL,   lift_b,      y,     512,  0, 1024, 512,  1024, 0, 2, 0,   P_Y,    cur);
        gb.d[4] = mk_gemm(xs, 1024, 0,   P_XS, wss, 1536, 0, P_WQKV, sself_bqkv,  qkv_s, 1536, 0, 1024, 1536, 512,  0, 2, 512, P_QKVS, cur);
        gb.d[5] = mk_gemm(xs, 1024, 512, P_XS, wsc, 1536, 0, P_WQKV, scross_bqkv, q_sc,  512,  0, 1024, 512,  512,  0, 2, 512, P_QSC,  cur);
        gb.n = 6;
        gemm_batch_kernel<<<cur, 256, SMEM_GEMM>>>(gb);
    }
    // ---- L2: kv_fc (needs y) + pool2 (needs h1) ----
    {
        GemmBatch gb; int cur = 0;
        gb.d[0] = mk_gemm(y,  512,  0, P_Y,  wfc, 1536, 512, P_WQKV, fcross_bqkv + 512, kv_fc, 1024, 0, 1024, 1024, 512,  0, 2, 0, P_KVFC, cur);
        gb.d[1] = mk_gemm(h1, 2048, 0, P_H1, wp2, 512,  0,   P_WP2,  pool_b2,           s,     512,  0, 1024, 512,  2048, 0, 2, 0, P_S,    cur);
        gb.n = 2;
        gemm_batch_kernel<<<cur, 256, SMEM_GEMM>>>(gb);
    }
    // ---- L3: kv_sc on shifted s ----
    {
        GemmBatch gb; int cur = 0;
        gb.d[0] = mk_gemm(s, 512, 0, P_S, wsc, 1536, 512, P_WQKV, scross_bqkv + 512, kv_sc, 1024, 0, 1024, 1024, 512, 1, 2, 0, P_KVSC, cur);
        gb.n = 1;
        gemm_batch_kernel<<<cur, 256, SMEM_GEMM>>>(gb);
    }
    // ---- L4: all four attentions ----
    {
        AttnBatch ab; int cur = 0;
        ab.d[0] = mk_attn(qkv_f, 1536, 0, P_QKVF, qkv_f, 1536, 512, P_QKVF, qkv_f, 1536, 1024, P_QKVF, o1, 512, P_O12, LF_, LF_, cur);
        ab.d[1] = mk_attn(q_fc,  512,  0, P_QFC,  kv_fc, 1024, 0,   P_KVFC, kv_fc, 1024, 512,  P_KVFC, o2, 512, P_O12, LF_, TS_, cur);
        ab.d[2] = mk_attn(qkv_s, 1536, 0, P_QKVS, qkv_s, 1536, 512, P_QKVS, qkv_s, 1536, 1024, P_QKVS, o3, 512, P_O34, TS_, TS_, cur);
        ab.d[3] = mk_attn(q_sc,  512,  0, P_QSC,  kv_sc, 1024, 0,   P_KVSC, kv_sc, 1024, 512,  P_KVSC, o4, 512, P_O34, TS_, TS_, cur);
        ab.n = 4;
        attn_batch_kernel<<<cur, 256, SMEM_ATTN>>>(ab);
    }
    // ---- L5: all four out-projections ----
    {
        GemmBatch gb; int cur = 0;
        gb.d[0] = mk_gemm(o1, 512, 0, P_O12, wof,  512, 0, P_WO, fself_bo,  zf, 1024, 0,   4096, 512, 512, 0, 0, 0, 0, cur);
        gb.d[1] = mk_gemm(o2, 512, 0, P_O12, woc,  512, 0, P_WO, fcross_bo, zf, 1024, 512, 4096, 512, 512, 0, 0, 0, 0, cur);
        gb.d[2] = mk_gemm(o3, 512, 0, P_O34, wos,  512, 0, P_WO, sself_bo,  zs, 1024, 0,   1024, 512, 512, 0, 0, 0, 0, cur);
        gb.d[3] = mk_gemm(o4, 512, 0, P_O34, wosc, 512, 0, P_WO, scross_bo, zs, 1024, 512, 1024, 512, 512, 0, 0, 0, 0, cur);
        gb.n = 4;
        gemm_batch_kernel<<<cur, 256, SMEM_GEMM>>>(gb);
    }
}

// round 13
// speedup vs baseline: 1.1103x; 1.1103x over previous
#include <cuda_runtime.h>
#include <cuda_fp16.h>
#include <math.h>

#define B_    2
#define LF_   2048
#define TS_   512
#define D2_   512
#define H_    8
#define HD_   64
#define POOLH 2048

typedef unsigned long long u64;
typedef unsigned int u32;
typedef unsigned short u16;

// ---------------------------------------------------------------------------
// fp16 split/pack + MMA + ldmatrix + cp.async helpers
// ---------------------------------------------------------------------------
__device__ __forceinline__ void split_f16(float x, float &hi, float &lo) {
    hi = __half2float(__float2half_rn(x));
    lo = x - hi;
}
__device__ __forceinline__ u32 pack_f16(float a, float b) {
    __half2 t = __floats2half2_rn(a, b);
    return *(u32*)&t;
}
__device__ __forceinline__ u64 pack4_f16(float a, float b, float c, float d) {
    return (u64)pack_f16(a, b) | ((u64)pack_f16(c, d) << 32);
}
__device__ __forceinline__ float exp2a(float x) {
    float r;
    asm("ex2.approx.f32 %0, %1;" : "=f"(r) : "f"(x));
    return r;
}
__device__ __forceinline__ void mma_f16(float c[4], u32 a0, u32 a1, u32 a2, u32 a3,
                                        u32 b0, u32 b1) {
    asm volatile(
        "mma.sync.aligned.m16n8k16.row.col.f32.f16.f16.f32 "
        "{%0,%1,%2,%3}, {%4,%5,%6,%7}, {%8,%9}, {%0,%1,%2,%3};\n"
        : "+f"(c[0]), "+f"(c[1]), "+f"(c[2]), "+f"(c[3])
        : "r"(a0), "r"(a1), "r"(a2), "r"(a3), "r"(b0), "r"(b1));
}
__device__ __forceinline__ u32 smaddr(const void* p) {
    return (u32)__cvta_generic_to_shared(p);
}
__device__ __forceinline__ void ldsm4(u32 r[4], u32 addr) {
    asm volatile("ldmatrix.sync.aligned.m8n8.x4.shared.b16 {%0,%1,%2,%3}, [%4];"
                 : "=r"(r[0]), "=r"(r[1]), "=r"(r[2]), "=r"(r[3]) : "r"(addr));
}
__device__ __forceinline__ void ldsm4t(u32 r[4], u32 addr) {
    asm volatile("ldmatrix.sync.aligned.m8n8.x4.trans.shared.b16 {%0,%1,%2,%3}, [%4];"
                 : "=r"(r[0]), "=r"(r[1]), "=r"(r[2]), "=r"(r[3]) : "r"(addr));
}
__device__ __forceinline__ void cp_async16(u32 dst, const void* src) {
    asm volatile("cp.async.cg.shared.global [%0], [%1], 16;" :: "r"(dst), "l"(src));
}
__device__ __forceinline__ void cp_async16z(u32 dst, const void* src, u32 sz) {
    asm volatile("cp.async.cg.shared.global [%0], [%1], 16, %2;"
                 :: "r"(dst), "l"(src), "r"(sz));
}
#define CP_COMMIT() asm volatile("cp.async.commit_group;")
#define CP_WAIT(n)  asm volatile("cp.async.wait_group %0;" :: "n"(n))

// XOR-swizzled smem addressing: 64 u16 per row (128B), chunk ^= row&7.
__device__ __forceinline__ u16* swp(u16* base, int row, int col) {
    return base + row * 64 + ((((col >> 3) ^ (row & 7)) << 3) | (col & 7));
}
__device__ __forceinline__ const u16* swp(const u16* base, int row, int col) {
    return base + row * 64 + ((((col >> 3) ^ (row & 7)) << 3) | (col & 7));
}

// combined softmax scale: 1/sqrt(64) * log2(e)
#define QSCALE 0.18033688011112042f

// ---------------------------------------------------------------------------
// Scratch layout (float units).
// ---------------------------------------------------------------------------
static const size_t O_XF    = 0;
static const size_t O_XS    = 4194304;
static const size_t O_WFS   = 5242880;
static const size_t O_WFC   = 6029312;
static const size_t O_WSS   = 6815744;
static const size_t O_WSC   = 7602176;
static const size_t O_WOF   = 8388608;
static const size_t O_WOC   = 8650752;
static const size_t O_WOS   = 8912896;
static const size_t O_WOSC  = 9175040;
static const size_t O_WL    = 9437184;
static const size_t O_WP1   = 9961472;
static const size_t O_WP2   = 18350080;
static const size_t O_Y     = 19398656;
static const size_t O_QKV_F = 19922944;
static const size_t O_Q_FC  = 26214400;
static const size_t O_KV_FC = 28311552;
static const size_t O_O1    = 29360128;
static const size_t O_O2    = 31457280;
static const size_t O_H1    = 33554432;
static const size_t O_S     = 35651584;
static const size_t O_QKV_S = 36175872;
static const size_t O_Q_SC  = 37748736;
static const size_t O_KV_SC = 38273024;
static const size_t O_O3    = 39321600;
static const size_t O_O4    = 39845888;
static const size_t SCRATCH_FLOATS = 40370176;

__device__ float g_scratch[SCRATCH_FLOATS];

// ---------------------------------------------------------------------------
// Batched split pass: fp32 -> fp16 hi/lo planes. lo==0: hi plane only
// (weights: the W operand never reads its lo plane).
// ---------------------------------------------------------------------------
#define SD_MAX 14
struct SplitDesc { const float* src; u16* dst; int nelem; int blk0; int lo; };
struct SplitBatch { SplitDesc d[SD_MAX]; int n; };

__global__ __launch_bounds__(256) void split_kernel(SplitBatch b)
{
    int pi = 0;
    #pragma unroll
    for (int i = 1; i < SD_MAX; i++)
        if (i < b.n && (int)blockIdx.x >= b.d[i].blk0) pi = i;
    const SplitDesc D = b.d[pi];
    const int idx = ((blockIdx.x - D.blk0) * 256 + threadIdx.x) * 4;
    float4 v = *(const float4*)(D.src + idx);
    float h0, l0, h1, l1, h2, l2, h3, l3;
    split_f16(v.x, h0, l0); split_f16(v.y, h1, l1);
    split_f16(v.z, h2, l2); split_f16(v.w, h3, l3);
    *(u64*)&D.dst[idx] = pack4_f16(h0, h1, h2, h3);
    if (D.lo)
        *(u64*)&D.dst[idx + D.nelem] = pack4_f16(l0, l1, l2, l3);
}

// ---------------------------------------------------------------------------
// Batched GEMM (R10 config): A = fp16 hi/lo (2 terms), W = fp16 hi only.
// Block tile 128x64, K-chunk 32, 256 threads (8 warps 4x2, warp tile 32x32).
// 4-stage cp.async pipeline, wait_group(2): each tile has two MMA phases
// to land. One sync per K-chunk.
// outmode 0: fp32 out. 2: split planes (cols < qcols scaled QSCALE).
// 3: GELU then split planes.
// ---------------------------------------------------------------------------
#define GD_MAX 6
struct GemmDesc {
    const u16 *A, *W;
    const float *bias;
    void *C;
    int lda, aoff, aplane, ldw, woff, wplane, ldc, coff, K;
    int ashift, nbx, blk0, outmode, qcols, oplane;
};
struct GemmBatch { GemmDesc d[GD_MAX]; int n; };

#define GT_A (128 * 64)               // 128 rows x [hi k0..31 | lo k0..31]
#define GT_W (32 * 64)                // 32 k-rows x 64 n (hi plane only)
#define GT_STAGE (GT_A + GT_W)        // 10240 u16 = 20480 B
#define SMEM_GEMM (4 * GT_STAGE * 2)  // 81920 B (4 stages)

__global__ __launch_bounds__(256) void gemm_batch_kernel(GemmBatch batch)
{
    extern __shared__ __align__(16) u16 smg[];

    int pi = 0;
    #pragma unroll
    for (int i = 1; i < GD_MAX; i++)
        if (i < batch.n && (int)blockIdx.x >= batch.d[i].blk0) pi = i;
    const GemmDesc D = batch.d[pi];
    const int lb = blockIdx.x - D.blk0;
    const int m0 = (lb / D.nbx) * 128;
    const int n0 = (lb % D.nbx) * 64;

    const int tid  = threadIdx.x;
    const int lane = tid & 31;
    const int warp = tid >> 5;
    const int warp_m = warp >> 1;
    const int warp_n = warp & 1;
    const int g  = lane >> 2;
    const int tg = lane & 3;

    const int l15 = lane & 15;
    const int l7  = lane & 7;
    const int ka8 = (lane >> 4) * 8;
    const int wk8 = ((lane >> 3) & 1) * 8;
    const int wn8 = (lane >> 4) * 8;

    float acc[2][4][4];
    #pragma unroll
    for (int mt = 0; mt < 2; mt++)
        #pragma unroll
        for (int nt = 0; nt < 4; nt++)
            #pragma unroll
            for (int r = 0; r < 4; r++) acc[mt][nt][r] = 0.f;

    auto fill = [&](int k0, int st) {
        u16* sb = smg + st * GT_STAGE;
        // A tile: 128 rows x 8 chunks (0-3 hi, 4-7 lo)
        #pragma unroll
        for (int i = 0; i < 4; i++) {
            const int idx = tid + i * 256;
            const int row = idx >> 3, ch = idx & 7;
            const int kc = (ch & 3) * 8;
            const int pl = (ch >> 2) ? D.aplane : 0;
            int mg = m0 + row;
            u32 sz = 16;
            if (D.ashift) {
                if ((mg & 511) == 0) { sz = 0; }
                else mg -= 1;
            }
            const u16* src = D.A + pl + (size_t)(sz ? mg : 0) * D.lda + D.aoff + k0 + kc;
            cp_async16z(smaddr(swp(sb, row, ch * 8)), src, sz);
        }
        // W tile: 32 k-rows x 8 chunks, hi plane only
        u16* wb = sb + GT_A;
        {
            const int row = tid >> 3, ch = tid & 7;
            const u16* src = D.W + (size_t)(k0 + row) * D.ldw + D.woff + n0 + ch * 8;
            cp_async16(smaddr(swp(wb, row, ch * 8)), src);
        }
    };

    auto do_mma = [&](int st) {
        const u16* As = smg + st * GT_STAGE;
        const u16* Ws = As + GT_A;
        #pragma unroll
        for (int kk = 0; kk < 2; kk++) {
            u32 afr[2][2][4];
            #pragma unroll
            for (int s = 0; s < 2; s++)
                #pragma unroll
                for (int mt = 0; mt < 2; mt++)
                    ldsm4(afr[s][mt],
                          smaddr(swp(As, warp_m * 32 + mt * 16 + l15, s * 32 + kk * 16 + ka8)));
            u32 bfr[4][2];
            #pragma unroll
            for (int ntp = 0; ntp < 2; ntp++) {
                u32 t[4];
                ldsm4t(t, smaddr(swp(Ws, kk * 16 + l7 + wk8,
                                     warp_n * 32 + ntp * 16 + wn8)));
                bfr[2 * ntp][0]     = t[0]; bfr[2 * ntp][1]     = t[1];
                bfr[2 * ntp + 1][0] = t[2]; bfr[2 * ntp + 1][1] = t[3];
            }
            #pragma unroll
            for (int mt = 0; mt < 2; mt++)
                #pragma unroll
                for (int nt = 0; nt < 4; nt++) {
                    mma_f16(acc[mt][nt], afr[0][mt][0], afr[0][mt][1], afr[0][mt][2], afr[0][mt][3],
                            bfr[nt][0], bfr[nt][1]);
                    mma_f16(acc[mt][nt], afr[1][mt][0], afr[1][mt][1], afr[1][mt][2], afr[1][mt][3],
                            bfr[nt][0], bfr[nt][1]);
                }
        }
    };

    const int nk = D.K >> 5;   // all problems have nk >= 16
    // 4-stage prologue: fill 0,1,2
    fill(0, 0);
    CP_COMMIT();
    fill(32, 1);
    CP_COMMIT();
    fill(64, 2);
    CP_COMMIT();

    for (int ki = 0; ki < nk; ki++) {
        CP_WAIT(2);            // tile ki resident (ki+1, ki+2 may be in flight)
        __syncthreads();       // all warps done with stage (ki+3)%4 == (ki-1)%4
        if (ki + 3 < nk) fill((ki + 3) * 32, (ki + 3) & 3);
        CP_COMMIT();
        do_mma(ki & 3);
    }

    if (D.outmode == 0) {
        float* C = (float*)D.C;
        #pragma unroll
        for (int mt = 0; mt < 2; mt++) {
            #pragma unroll
            for (int nt = 0; nt < 4; nt++) {
                const int m = m0 + warp_m * 32 + mt * 16 + g;
                const int n = n0 + warp_n * 32 + nt * 8 + tg * 2;
                const float bb0 = D.bias[n], bb1 = D.bias[n + 1];
                *(float2*)(C + (size_t)m * D.ldc + D.coff + n) =
                    make_float2(acc[mt][nt][0] + bb0, acc[mt][nt][1] + bb1);
                *(float2*)(C + (size_t)(m + 8) * D.ldc + D.coff + n) =
                    make_float2(acc[mt][nt][2] + bb0, acc[mt][nt][3] + bb1);
            }
        }
    } else {
        u16* Ch = (u16*)D.C;
        const float sc = (D.outmode == 2 && n0 < D.qcols) ? QSCALE : 1.0f;
        #pragma unroll
        for (int mt = 0; mt < 2; mt++) {
            #pragma unroll
            for (int nt = 0; nt < 4; nt++) {
                const int m = m0 + warp_m * 32 + mt * 16 + g;
                const int n = n0 + warp_n * 32 + nt * 8 + tg * 2;
                const float bb0 = D.bias[n], bb1 = D.bias[n + 1];
                float v[4] = {(acc[mt][nt][0] + bb0) * sc, (acc[mt][nt][1] + bb1) * sc,
                              (acc[mt][nt][2] + bb0) * sc, (acc[mt][nt][3] + bb1) * sc};
                if (D.outmode == 3) {
                    #pragma unroll
                    for (int r = 0; r < 4; r++) {
                        float x = v[r];
                        float u = 0.7978845608028654f * (x + 0.044715f * x * x * x);
                        v[r] = 0.5f * x * (1.0f + tanhf(u));
                    }
                }
                float h0, l0, h1, l1, h2, l2, h3, l3;
                split_f16(v[0], h0, l0); split_f16(v[1], h1, l1);
                split_f16(v[2], h2, l2); split_f16(v[3], h3, l3);
                const size_t o0 = (size_t)m * D.ldc + D.coff + n;
                const size_t o1 = (size_t)(m + 8) * D.ldc + D.coff + n;
                *(u32*)&Ch[o0]            = pack_f16(h0, h1);
                *(u32*)&Ch[o0 + D.oplane] = pack_f16(l0, l1);
                *(u32*)&Ch[o1]            = pack_f16(h2, h3);
                *(u32*)&Ch[o1 + D.oplane] = pack_f16(l2, l3);
            }
        }
    }
}

// ---------------------------------------------------------------------------
// Batched flash attention (R10 config, verbatim): Q = hi/lo, K = hi only,
// V = hi/lo with single-fp16 P. cp.async double buffer, XOR swizzle, exp2
// softmax. 64 q-rows/CTA, 4 warps, 64-key tiles, 128 threads.
// ---------------------------------------------------------------------------
#define AD_MAX 4
struct AttnDesc {
    const u16 *Q, *K, *V;
    u16 *O;
    int ldq, qoff, qplane, ldk, koff, kplane, ldv, voff, vplane;
    int ldo, oplane, Tq, Tk, nbx, blk0;
};
struct AttnBatch { AttnDesc d[AD_MAX]; int n; };

#define STAGE_U16 (192 * 64)            // K hi (64 rows) + V hi/lo (128 rows)
#define SMEM_ATTN (2 * STAGE_U16 * 2)   // 49152 bytes

__global__ __launch_bounds__(128) void attn_batch_kernel(AttnBatch batch)
{
    extern __shared__ __align__(16) u16 smu[];

    int pi = 0;
    #pragma unroll
    for (int i = 1; i < AD_MAX; i++)
        if (i < batch.n && (int)blockIdx.x >= batch.d[i].blk0) pi = i;
    const AttnDesc D = batch.d[pi];
    const int lb = blockIdx.x - D.blk0;
    const int qt = lb % D.nbx;
    const int h  = (lb / D.nbx) % H_;
    const int b  = lb / (D.nbx * H_);

    const int tid  = threadIdx.x;
    const int lane = tid & 31;
    const int warp = tid >> 5;
    const int g  = lane >> 2;
    const int tg = lane & 3;
    const int mrow = warp * 16;

    const int l15 = lane & 15;
    const int l7  = lane & 7;
    const int qc8 = (lane >> 4) * 8;
    const int kk8 = (lane >> 4) * 8;
    const int kd8 = ((lane >> 3) & 1) * 8;
    const int vk8 = ((lane >> 3) & 1) * 8;
    const int vd8 = (lane >> 4) * 8;

    const u16* Qb = D.Q + (size_t)(b * D.Tq + qt * 64) * D.ldq + D.qoff + h * HD_;
    const u16* Kb = D.K + (size_t)(b * D.Tk) * D.ldk + D.koff + h * HD_;
    const u16* Vb = D.V + (size_t)(b * D.Tk) * D.ldv + D.voff + h * HD_;

    auto fill = [&](int kt, int st) {
        u16* sb = smu + st * STAGE_U16;
        #pragma unroll
        for (int i = 0; i < 12; i++) {
            const int plane = i >> 2;
            const int idx = tid + (i & 3) * 128;
            const int r = idx >> 3;
            const int c = (idx & 7) * 8;
            const u16* src;
            int drow;
            if (plane == 0)      { src = Kb + (size_t)(kt + r) * D.ldk + c;             drow = r; }
            else if (plane == 1) { src = Vb + (size_t)(kt + r) * D.ldv + c;             drow = 64 + r; }
            else                 { src = Vb + D.vplane + (size_t)(kt + r) * D.ldv + c;  drow = 128 + r; }
            cp_async16(smaddr(swp(sb, drow, c)), src);
        }
    };

    {
        u16* qs = smu + STAGE_U16;
        #pragma unroll
        for (int i = 0; i < 8; i++) {
            const int plane = i >> 2;
            const int idx = tid + (i & 3) * 128;
            const int r = idx >> 3;
            const int c = (idx & 7) * 8;
            const u16* src = Qb + (plane ? D.qplane : 0) + (size_t)r * D.ldq + c;
            cp_async16(smaddr(swp(qs, plane * 64 + r, c)), src);
        }
        CP_COMMIT();
    }
    fill(0, 0);
    CP_COMMIT();
    CP_WAIT(1);
    __syncthreads();

    u32 qh[4][4], ql[4][4];
    {
        const u16* qs = smu + STAGE_U16;
        #pragma unroll
        for (int kc = 0; kc < 4; kc++) {
            ldsm4(qh[kc], smaddr(swp(qs, mrow + l15, kc * 16 + qc8)));
            ldsm4(ql[kc], smaddr(swp(qs, 64 + mrow + l15, kc * 16 + qc8)));
        }
    }

    float acc[8][4];
    #pragma unroll
    for (int nt = 0; nt < 8; nt++)
        #pragma unroll
        for (int r = 0; r < 4; r++) acc[nt][r] = 0.f;
    float mx0 = -1e30f, mx1 = -1e30f, lsum0 = 0.f, lsum1 = 0.f;

    const int ntile = D.Tk >> 6;
    for (int it = 0; it < ntile; it++) {
        const int st = it & 1;
        __syncthreads();
        if (it + 1 < ntile) fill((it + 1) * 64, 1 - st);
        CP_COMMIT();
        CP_WAIT(1);
        __syncthreads();

        const u16* sb = smu + st * STAGE_U16;

        // ---- S = Q K^T : (Q_hi + Q_lo) x K_hi ----
        float s[8][4];
        #pragma unroll
        for (int nt = 0; nt < 8; nt++)
            #pragma unroll
            for (int r = 0; r < 4; r++) s[nt][r] = 0.f;

        #pragma unroll
        for (int kc = 0; kc < 4; kc++) {
            #pragma unroll
            for (int ntp = 0; ntp < 4; ntp++) {
                u32 kh[4];
                ldsm4(kh, smaddr(swp(sb, ntp * 16 + l7 + kk8, kc * 16 + kd8)));
                mma_f16(s[2 * ntp],     qh[kc][0], qh[kc][1], qh[kc][2], qh[kc][3], kh[0], kh[1]);
                mma_f16(s[2 * ntp],     ql[kc][0], ql[kc][1], ql[kc][2], ql[kc][3], kh[0], kh[1]);
                mma_f16(s[2 * ntp + 1], qh[kc][0], qh[kc][1], qh[kc][2], qh[kc][3], kh[2], kh[3]);
                mma_f16(s[2 * ntp + 1], ql[kc][0], ql[kc][1], ql[kc][2], ql[kc][3], kh[2], kh[3]);
            }
        }

        // ---- online softmax (exp2 domain) ----
        float rm0 = -1e30f, rm1 = -1e30f;
        #pragma unroll
        for (int nt = 0; nt < 8; nt++) {
            rm0 = fmaxf(rm0, fmaxf(s[nt][0], s[nt][1]));
            rm1 = fmaxf(rm1, fmaxf(s[nt][2], s[nt][3]));
        }
        rm0 = fmaxf(rm0, __shfl_xor_sync(0xffffffffu, rm0, 1));
        rm0 = fmaxf(rm0, __shfl_xor_sync(0xffffffffu, rm0, 2));
        rm1 = fmaxf(rm1, __shfl_xor_sync(0xffffffffu, rm1, 1));
        rm1 = fmaxf(rm1, __shfl_xor_sync(0xffffffffu, rm1, 2));

        const float mn0 = fmaxf(mx0, rm0);
        const float mn1 = fmaxf(mx1, rm1);
        const float corr0 = exp2a(mx0 - mn0);
        const float corr1 = exp2a(mx1 - mn1);
        float rs0 = 0.f, rs1 = 0.f;
        #pragma unroll
        for (int nt = 0; nt < 8; nt++) {
            s[nt][0] = exp2a(s[nt][0] - mn0); rs0 += s[nt][0];
            s[nt][1] = exp2a(s[nt][1] - mn0); rs0 += s[nt][1];
            s[nt][2] = exp2a(s[nt][2] - mn1); rs1 += s[nt][2];
            s[nt][3] = exp2a(s[nt][3] - mn1); rs1 += s[nt][3];
        }
        rs0 += __shfl_xor_sync(0xffffffffu, rs0, 1);
        rs0 += __shfl_xor_sync(0xffffffffu, rs0, 2);
        rs1 += __shfl_xor_sync(0xffffffffu, rs1, 1);
        rs1 += __shfl_xor_sync(0xffffffffu, rs1, 2);
        lsum0 = lsum0 * corr0 + rs0; mx0 = mn0;
        lsum1 = lsum1 * corr1 + rs1; mx1 = mn1;
        #pragma unroll
        for (int nt = 0; nt < 8; nt++) {
            acc[nt][0] *= corr0; acc[nt][1] *= corr0;
            acc[nt][2] *= corr1; acc[nt][3] *= corr1;
        }

        // ---- O += P V : P single fp16, V = V_hi + V_lo ----
        #pragma unroll
        for (int kc = 0; kc < 4; kc++) {
            const int j0 = 2 * kc, j1 = 2 * kc + 1;
            u32 pa[4];
            pa[0] = pack_f16(s[j0][0], s[j0][1]);
            pa[1] = pack_f16(s[j0][2], s[j0][3]);
            pa[2] = pack_f16(s[j1][0], s[j1][1]);
            pa[3] = pack_f16(s[j1][2], s[j1][3]);

            #pragma unroll
            for (int ntp = 0; ntp < 4; ntp++) {
                u32 vh[4], vl[4];
                ldsm4t(vh, smaddr(swp(sb, 64 + kc * 16 + l7 + vk8, ntp * 16 + vd8)));
                ldsm4t(vl, smaddr(swp(sb, 128 + kc * 16 + l7 + vk8, ntp * 16 + vd8)));
                mma_f16(acc[2 * ntp],     pa[0], pa[1], pa[2], pa[3], vh[0], vh[1]);
                mma_f16(acc[2 * ntp],     pa[0], pa[1], pa[2], pa[3], vl[0], vl[1]);
                mma_f16(acc[2 * ntp + 1], pa[0], pa[1], pa[2], pa[3], vh[2], vh[3]);
                mma_f16(acc[2 * ntp + 1], pa[0], pa[1], pa[2], pa[3], vl[2], vl[3]);
            }
        }
    }

    const float inv0 = 1.0f / lsum0;
    const float inv1 = 1.0f / lsum1;
    u16* Ob = D.O + (size_t)(b * D.Tq + qt * 64 + mrow) * D.ldo + h * HD_;
    #pragma unroll
    for (int nt = 0; nt < 8; nt++) {
        const int col = nt * 8 + 2 * tg;
        float h0, l0, h1, l1;
        split_f16(acc[nt][0] * inv0, h0, l0);
        split_f16(acc[nt][1] * inv0, h1, l1);
        const size_t o0 = (size_t)g * D.ldo + col;
        *(u32*)&Ob[o0]            = pack_f16(h0, h1);
        *(u32*)&Ob[o0 + D.oplane] = pack_f16(l0, l1);
        split_f16(acc[nt][2] * inv1, h0, l0);
        split_f16(acc[nt][3] * inv1, h1, l1);
        const size_t o1 = (size_t)(g + 8) * D.ldo + col;
        *(u32*)&Ob[o1]            = pack_f16(h0, h1);
        *(u32*)&Ob[o1 + D.oplane] = pack_f16(l0, l1);
    }
}

// ---------------------------------------------------------------------------
// Host orchestration: split pass + 5 launches
// ---------------------------------------------------------------------------
static inline GemmDesc mk_gemm(const u16* A, int lda, int aoff, int aplane,
                               const u16* W, int ldw, int woff, int wplane,
                               const float* bias, void* C, int ldc, int coff,
                               int M, int N, int K, int ashift,
                               int outmode, int qcols, int oplane,
                               int& blk_cursor)
{
    GemmDesc d;
    d.A = A; d.W = W; d.bias = bias; d.C = C;
    d.lda = lda; d.aoff = aoff; d.aplane = aplane;
    d.ldw = ldw; d.woff = woff; d.wplane = wplane;
    d.ldc = ldc; d.coff = coff; d.K = K; d.ashift = ashift;
    d.outmode = outmode; d.qcols = qcols; d.oplane = oplane;
    d.nbx = N / 64; d.blk0 = blk_cursor;
    blk_cursor += (N / 64) * (M / 128);
    return d;
}

static inline AttnDesc mk_attn(const u16* Q, int ldq, int qoff, int qplane,
                               const u16* K, int ldk, int koff, int kplane,
                               const u16* V, int ldv, int voff, int vplane,
                               u16* O, int ldo, int oplane,
                               int Tq, int Tk, int& blk_cursor)
{
    AttnDesc d;
    d.Q = Q; d.K = K; d.V = V; d.O = O;
    d.ldq = ldq; d.qoff = qoff; d.qplane = qplane;
    d.ldk = ldk; d.koff = koff; d.kplane = kplane;
    d.ldv = ldv; d.voff = voff; d.vplane = vplane;
    d.ldo = ldo; d.oplane = oplane;
    d.Tq = Tq; d.Tk = Tk; d.nbx = Tq / 64; d.blk0 = blk_cursor;
    blk_cursor += (Tq / 64) * H_ * B_;
    return d;
}

static inline SplitDesc mk_split(const float* src, u16* dst, int nelem, int lo,
                                 int& blk_cursor)
{
    SplitDesc d;
    d.src = src; d.dst = dst; d.nelem = nelem; d.lo = lo; d.blk0 = blk_cursor;
    blk_cursor += nelem / 1024;
    return d;
}

extern "C" void kernel_launch(void* const* d_in, const int* in_sizes, int n_in,
                              void* d_out, int out_size)
{
    (void)in_sizes; (void)n_in; (void)out_size;

    const float* x_fast      = (const float*)d_in[0];
    const float* x_slow      = (const float*)d_in[1];
    const float* fself_wqkv  = (const float*)d_in[2];
    const float* fself_bqkv  = (const float*)d_in[3];
    const float* fself_wo    = (const float*)d_in[4];
    const float* fself_bo    = (const float*)d_in[5];
    const float* fcross_wqkv = (const float*)d_in[6];
    const float* fcross_bqkv = (const float*)d_in[7];
    const float* fcross_wo   = (const float*)d_in[8];
    const float* fcross_bo   = (const float*)d_in[9];
    const float* sself_wqkv  = (const float*)d_in[10];
    const float* sself_bqkv  = (const float*)d_in[11];
    const float* sself_wo    = (const float*)d_in[12];
    const float* sself_bo    = (const float*)d_in[13];
    const float* scross_wqkv = (const float*)d_in[14];
    const float* scross_bqkv = (const float*)d_in[15];
    const float* scross_wo   = (const float*)d_in[16];
    const float* scross_bo   = (const float*)d_in[17];
    const float* lift_w      = (const float*)d_in[18];
    const float* lift_b      = (const float*)d_in[19];
    const float* pool_w1     = (const float*)d_in[20];
    const float* pool_b1     = (const float*)d_in[21];
    const float* pool_w2     = (const float*)d_in[22];
    const float* pool_b2     = (const float*)d_in[23];

    float* out = (float*)d_out;
    float* zf = out;
    float* zs = out + (size_t)B_ * LF_ * 1024;

    float* S0 = nullptr;
    cudaGetSymbolAddress((void**)&S0, g_scratch);
    u16* xf    = (u16*)(S0 + O_XF);
    u16* xs    = (u16*)(S0 + O_XS);
    u16* wfs   = (u16*)(S0 + O_WFS);
    u16* wfc   = (u16*)(S0 + O_WFC);
    u16* wss   = (u16*)(S0 + O_WSS);
    u16* wsc   = (u16*)(S0 + O_WSC);
    u16* wof   = (u16*)(S0 + O_WOF);
    u16* woc   = (u16*)(S0 + O_WOC);
    u16* wos   = (u16*)(S0 + O_WOS);
    u16* wosc  = (u16*)(S0 + O_WOSC);
    u16* wl    = (u16*)(S0 + O_WL);
    u16* wp1   = (u16*)(S0 + O_WP1);
    u16* wp2   = (u16*)(S0 + O_WP2);
    u16* y     = (u16*)(S0 + O_Y);
    u16* qkv_f = (u16*)(S0 + O_QKV_F);
    u16* q_fc  = (u16*)(S0 + O_Q_FC);
    u16* kv_fc = (u16*)(S0 + O_KV_FC);
    u16* o1    = (u16*)(S0 + O_O1);
    u16* o2    = (u16*)(S0 + O_O2);
    u16* h1    = (u16*)(S0 + O_H1);
    u16* s     = (u16*)(S0 + O_S);
    u16* qkv_s = (u16*)(S0 + O_QKV_S);
    u16* q_sc  = (u16*)(S0 + O_Q_SC);
    u16* kv_sc = (u16*)(S0 + O_KV_SC);
    u16* o3    = (u16*)(S0 + O_O3);
    u16* o4    = (u16*)(S0 + O_O4);

    const int P_XF   = 4194304, P_XS  = 1048576;
    const int P_WQKV = 786432,  P_WO  = 262144, P_WL = 524288;
    const int P_WP1  = 8388608, P_WP2 = 1048576;
    const int P_QKVF = 6291456, P_QFC = 2097152, P_KVFC = 1048576;
    const int P_QKVS = 1572864, P_QSC = 524288,  P_KVSC = 1048576;
    const int P_O12  = 2097152, P_O34 = 524288;
    const int P_Y    = 524288,  P_H1  = 2097152, P_S = 524288;

    cudaFuncSetAttribute(gemm_batch_kernel,
                         cudaFuncAttributeMaxDynamicSharedMemorySize, SMEM_GEMM);
    cudaFuncSetAttribute(attn_batch_kernel,
                         cudaFuncAttributeMaxDynamicSharedMemorySize, SMEM_ATTN);

    // ---- L0: split inputs (hi+lo) + weights (hi only) ----
    {
        SplitBatch sb; int cur = 0;
        sb.d[0]  = mk_split(x_fast,      xf,   P_XF,   1, cur);
        sb.d[1]  = mk_split(x_slow,      xs,   P_XS,   1, cur);
        sb.d[2]  = mk_split(fself_wqkv,  wfs,  P_WQKV, 0, cur);
        sb.d[3]  = mk_split(fcross_wqkv, wfc,  P_WQKV, 0, cur);
        sb.d[4]  = mk_split(sself_wqkv,  wss,  P_WQKV, 0, cur);
        sb.d[5]  = mk_split(scross_wqkv, wsc,  P_WQKV, 0, cur);
        sb.d[6]  = mk_split(fself_wo,    wof,  P_WO,   0, cur);
        sb.d[7]  = mk_split(fcross_wo,   woc,  P_WO,   0, cur);
        sb.d[8]  = mk_split(sself_wo,    wos,  P_WO,   0, cur);
        sb.d[9]  = mk_split(scross_wo,   wosc, P_WO,   0, cur);
        sb.d[10] = mk_split(lift_w,      wl,   P_WL,   0, cur);
        sb.d[11] = mk_split(pool_w1,     wp1,  P_WP1,  0, cur);
        sb.d[12] = mk_split(pool_w2,     wp2,  P_WP2,  0, cur);
        sb.n = 13;
        split_kernel<<<cur, 256>>>(sb);
    }
    // ---- L1: input-only GEMMs ----
    {
        GemmBatch gb; int cur = 0;
        gb.d[0] = mk_gemm(xf, 1024, 0,   P_XF, wfs, 1536, 0, P_WQKV, fself_bqkv,  qkv_f, 1536, 0, 4096, 1536, 512,  0, 2, 512, P_QKVF, cur);
        gb.d[1] = mk_gemm(xf, 4096, 0,   P_XF, wp1, 2048, 0, P_WP1,  pool_b1,     h1,    2048, 0, 1024, POOLH, 4096, 0, 3, 0,   P_H1,   cur);
        gb.d[2] = mk_gemm(xf, 1024, 512, P_XF, wfc, 1536, 0, P_WQKV, fcross_bqkv, q_fc,  512,  0, 4096, 512,  512,  0, 2, 512, P_QFC,  cur);
        gb.d[3] = mk_gemm(xs, 1024, 0,   P_XS, wl,  512,  0, P_WL,   lift_b,      y,     512,  0, 1024, 512,  1024, 0, 2, 0,   P_Y,    cur);
        gb.d[4] = mk_gemm(xs, 1024, 0,   P_XS, wss, 1536, 0, P_WQKV, sself_bqkv,  qkv_s, 1536, 0, 1024, 1536, 512,  0, 2, 512, P_QKVS, cur);
        gb.d[5] = mk_gemm(xs, 1024, 512, P_XS, wsc, 1536, 0, P_WQKV, scross_bqkv, q_sc,  512,  0, 1024, 512,  512,  0, 2, 512, P_QSC,  cur);
        gb.n = 6;
        gemm_batch_kernel<<<cur, 256, SMEM_GEMM>>>(gb);
    }
    // ---- L2: kv_fc (needs y) + pool2 (needs h1) ----
    {
        GemmBatch gb; int cur = 0;
        gb.d[0] = mk_gemm(y,  512,  0, P_Y,  wfc, 1536, 512, P_WQKV, fcross_bqkv + 512, kv_fc, 1024, 0, 1024, 1024, 512,  0, 2, 0, P_KVFC, cur);
        gb.d[1] = mk_gemm(h1, 2048, 0, P_H1, wp2, 512,  0,   P_WP2,  pool_b2,           s,     512,  0, 1024, 512,  2048, 0, 2, 0, P_S,    cur);
        gb.n = 2;
        gemm_batch_kernel<<<cur, 256, SMEM_GEMM>>>(gb);
    }
    // ---- L3: kv_sc on shifted s ----
    {
        GemmBatch gb; int cur = 0;
        gb.d[0] = mk_gemm(s, 512, 0, P_S, wsc, 1536, 512, P_WQKV, scross_bqkv + 512, kv_sc, 1024, 0, 1024, 1024, 512, 1, 2, 0, P_KVSC, cur);
        gb.n = 1;
        gemm_batch_kernel<<<cur, 256, SMEM_GEMM>>>(gb);
    }
    // ---- L4: all four attentions ----
    {
        AttnBatch ab; int cur = 0;
        ab.d[0] = mk_attn(qkv_f, 1536, 0, P_QKVF, qkv_f, 1536, 512, P_QKVF, qkv_f, 1536, 1024, P_QKVF, o1, 512, P_O12, LF_, LF_, cur);
        ab.d[1] = mk_attn(q_fc,  512,  0, P_QFC,  kv_fc, 1024, 0,   P_KVFC, kv_fc, 1024, 512,  P_KVFC, o2, 512, P_O12, LF_, TS_, cur);
        ab.d[2] = mk_attn(qkv_s, 1536, 0, P_QKVS, qkv_s, 1536, 512, P_QKVS, qkv_s, 1536, 1024, P_QKVS, o3, 512, P_O34, TS_, TS_, cur);
        ab.d[3] = mk_attn(q_sc,  512,  0, P_QSC,  kv_sc, 1024, 0,   P_KVSC, kv_sc, 1024, 512,  P_KVSC, o4, 512, P_O34, TS_, TS_, cur);
        ab.n = 4;
        attn_batch_kernel<<<cur, 128, SMEM_ATTN>>>(ab);
    }
    // ---- L5: all four out-projections ----
    {
        GemmBatch gb; int cur = 0;
        gb.d[0] = mk_gemm(o1, 512, 0, P_O12, wof,  512, 0, P_WO, fself_bo,  zf, 1024, 0,   4096, 512, 512, 0, 0, 0, 0, cur);
        gb.d[1] = mk_gemm(o2, 512, 0, P_O12, woc,  512, 0, P_WO, fcross_bo, zf, 1024, 512, 4096, 512, 512, 0, 0, 0, 0, cur);
        gb.d[2] = mk_gemm(o3, 512, 0, P_O34, wos,  512, 0, P_WO, sself_bo,  zs, 1024, 0,   1024, 512, 512, 0, 0, 0, 0, cur);
        gb.d[3] = mk_gemm(o4, 512, 0, P_O34, wosc, 512, 0, P_WO, scross_bo, zs, 1024, 512, 1024, 512, 512, 0, 0, 0, 0, cur);
        gb.n = 4;
        gemm_batch_kernel<<<cur, 256, SMEM_GEMM>>>(gb);
    }
}

// round 14
// speedup vs baseline: 1.1685x; 1.0525x over previous
#include <cuda_runtime.h>
#include <cuda_fp16.h>
#include <math.h>

#define B_    2
#define LF_   2048
#define TS_   512
#define D2_   512
#define H_    8
#define HD_   64
#define POOLH 2048

typedef unsigned long long u64;
typedef unsigned int u32;
typedef unsigned short u16;

// ---------------------------------------------------------------------------
// fp16 split/pack + MMA + ldmatrix + cp.async helpers
// ---------------------------------------------------------------------------
__device__ __forceinline__ void split_f16(float x, float &hi, float &lo) {
    hi = __half2float(__float2half_rn(x));
    lo = x - hi;
}
__device__ __forceinline__ u32 pack_f16(float a, float b) {
    __half2 t = __floats2half2_rn(a, b);
    return *(u32*)&t;
}
__device__ __forceinline__ u64 pack4_f16(float a, float b, float c, float d) {
    return (u64)pack_f16(a, b) | ((u64)pack_f16(c, d) << 32);
}
__device__ __forceinline__ float exp2a(float x) {
    float r;
    asm("ex2.approx.f32 %0, %1;" : "=f"(r) : "f"(x));
    return r;
}
__device__ __forceinline__ void mma_f16(float c[4], u32 a0, u32 a1, u32 a2, u32 a3,
                                        u32 b0, u32 b1) {
    asm volatile(
        "mma.sync.aligned.m16n8k16.row.col.f32.f16.f16.f32 "
        "{%0,%1,%2,%3}, {%4,%5,%6,%7}, {%8,%9}, {%0,%1,%2,%3};\n"
        : "+f"(c[0]), "+f"(c[1]), "+f"(c[2]), "+f"(c[3])
        : "r"(a0), "r"(a1), "r"(a2), "r"(a3), "r"(b0), "r"(b1));
}
__device__ __forceinline__ u32 smaddr(const void* p) {
    return (u32)__cvta_generic_to_shared(p);
}
__device__ __forceinline__ void ldsm4(u32 r[4], u32 addr) {
    asm volatile("ldmatrix.sync.aligned.m8n8.x4.shared.b16 {%0,%1,%2,%3}, [%4];"
                 : "=r"(r[0]), "=r"(r[1]), "=r"(r[2]), "=r"(r[3]) : "r"(addr));
}
__device__ __forceinline__ void ldsm4t(u32 r[4], u32 addr) {
    asm volatile("ldmatrix.sync.aligned.m8n8.x4.trans.shared.b16 {%0,%1,%2,%3}, [%4];"
                 : "=r"(r[0]), "=r"(r[1]), "=r"(r[2]), "=r"(r[3]) : "r"(addr));
}
__device__ __forceinline__ void cp_async16(u32 dst, const void* src) {
    asm volatile("cp.async.cg.shared.global [%0], [%1], 16;" :: "r"(dst), "l"(src));
}
__device__ __forceinline__ void cp_async16z(u32 dst, const void* src, u32 sz) {
    asm volatile("cp.async.cg.shared.global [%0], [%1], 16, %2;"
                 :: "r"(dst), "l"(src), "r"(sz));
}
#define CP_COMMIT() asm volatile("cp.async.commit_group;")
#define CP_WAIT(n)  asm volatile("cp.async.wait_group %0;" :: "n"(n))

// XOR-swizzled smem addressing: 64 u16 per row (128B), chunk ^= row&7.
__device__ __forceinline__ u16* swp(u16* base, int row, int col) {
    return base + row * 64 + ((((col >> 3) ^ (row & 7)) << 3) | (col & 7));
}
__device__ __forceinline__ const u16* swp(const u16* base, int row, int col) {
    return base + row * 64 + ((((col >> 3) ^ (row & 7)) << 3) | (col & 7));
}

// combined softmax scale: 1/sqrt(64) * log2(e)
#define QSCALE 0.18033688011112042f

// ---------------------------------------------------------------------------
// Scratch layout (float units).
// ---------------------------------------------------------------------------
static const size_t O_XF    = 0;
static const size_t O_XS    = 4194304;
static const size_t O_WFS   = 5242880;
static const size_t O_WFC   = 6029312;
static const size_t O_WSS   = 6815744;
static const size_t O_WSC   = 7602176;
static const size_t O_WOF   = 8388608;
static const size_t O_WOC   = 8650752;
static const size_t O_WOS   = 8912896;
static const size_t O_WOSC  = 9175040;
static const size_t O_WL    = 9437184;
static const size_t O_WP1   = 9961472;
static const size_t O_WP2   = 18350080;
static const size_t O_Y     = 19398656;
static const size_t O_QKV_F = 19922944;
static const size_t O_Q_FC  = 26214400;
static const size_t O_KV_FC = 28311552;
static const size_t O_O1    = 29360128;
static const size_t O_O2    = 31457280;
static const size_t O_H1    = 33554432;
static const size_t O_S     = 35651584;
static const size_t O_QKV_S = 36175872;
static const size_t O_Q_SC  = 37748736;
static const size_t O_KV_SC = 38273024;
static const size_t O_O3    = 39321600;
static const size_t O_O4    = 39845888;
static const size_t SCRATCH_FLOATS = 40370176;

__device__ float g_scratch[SCRATCH_FLOATS];

// ---------------------------------------------------------------------------
// Batched split pass: fp32 -> fp16 hi/lo planes. lo==0: hi plane only.
// ---------------------------------------------------------------------------
#define SD_MAX 14
struct SplitDesc { const float* src; u16* dst; int nelem; int blk0; int lo; };
struct SplitBatch { SplitDesc d[SD_MAX]; int n; };

__global__ __launch_bounds__(256) void split_kernel(SplitBatch b)
{
    int pi = 0;
    #pragma unroll
    for (int i = 1; i < SD_MAX; i++)
        if (i < b.n && (int)blockIdx.x >= b.d[i].blk0) pi = i;
    const SplitDesc D = b.d[pi];
    const int idx = ((blockIdx.x - D.blk0) * 256 + threadIdx.x) * 4;
    float4 v = *(const float4*)(D.src + idx);
    float h0, l0, h1, l1, h2, l2, h3, l3;
    split_f16(v.x, h0, l0); split_f16(v.y, h1, l1);
    split_f16(v.z, h2, l2); split_f16(v.w, h3, l3);
    *(u64*)&D.dst[idx] = pack4_f16(h0, h1, h2, h3);
    if (D.lo)
        *(u64*)&D.dst[idx + D.nelem] = pack4_f16(l0, l1, l2, l3);
}

// ---------------------------------------------------------------------------
// Batched GEMM (R10 config, verbatim): A = fp16 hi/lo (2 terms), W = hi only.
// Block 128x64, K-chunk 32, 256 threads (8 warps 4x2). 3-stage cp.async
// pipeline, wait(1), one sync per K-chunk.
// outmode 0: fp32. 2: split planes (cols < qcols scaled QSCALE). 3: GELU+split.
// ---------------------------------------------------------------------------
#define GD_MAX 6
struct GemmDesc {
    const u16 *A, *W;
    const float *bias;
    void *C;
    int lda, aoff, aplane, ldw, woff, wplane, ldc, coff, K;
    int ashift, nbx, blk0, outmode, qcols, oplane;
};
struct GemmBatch { GemmDesc d[GD_MAX]; int n; };

#define GT_A (128 * 64)
#define GT_W (32 * 64)
#define GT_STAGE (GT_A + GT_W)        // 10240 u16 = 20480 B
#define SMEM_GEMM (3 * GT_STAGE * 2)  // 61440 B

__global__ __launch_bounds__(256) void gemm_batch_kernel(GemmBatch batch)
{
    extern __shared__ __align__(16) u16 smg[];

    int pi = 0;
    #pragma unroll
    for (int i = 1; i < GD_MAX; i++)
        if (i < batch.n && (int)blockIdx.x >= batch.d[i].blk0) pi = i;
    const GemmDesc D = batch.d[pi];
    const int lb = blockIdx.x - D.blk0;
    const int m0 = (lb / D.nbx) * 128;
    const int n0 = (lb % D.nbx) * 64;

    const int tid  = threadIdx.x;
    const int lane = tid & 31;
    const int warp = tid >> 5;
    const int warp_m = warp >> 1;
    const int warp_n = warp & 1;
    const int g  = lane >> 2;
    const int tg = lane & 3;

    const int l15 = lane & 15;
    const int l7  = lane & 7;
    const int ka8 = (lane >> 4) * 8;
    const int wk8 = ((lane >> 3) & 1) * 8;
    const int wn8 = (lane >> 4) * 8;

    float acc[2][4][4];
    #pragma unroll
    for (int mt = 0; mt < 2; mt++)
        #pragma unroll
        for (int nt = 0; nt < 4; nt++)
            #pragma unroll
            for (int r = 0; r < 4; r++) acc[mt][nt][r] = 0.f;

    auto fill = [&](int k0, int st) {
        u16* sb = smg + st * GT_STAGE;
        #pragma unroll
        for (int i = 0; i < 4; i++) {
            const int idx = tid + i * 256;
            const int row = idx >> 3, ch = idx & 7;
            const int kc = (ch & 3) * 8;
            const int pl = (ch >> 2) ? D.aplane : 0;
            int mg = m0 + row;
            u32 sz = 16;
            if (D.ashift) {
                if ((mg & 511) == 0) { sz = 0; }
                else mg -= 1;
            }
            const u16* src = D.A + pl + (size_t)(sz ? mg : 0) * D.lda + D.aoff + k0 + kc;
            cp_async16z(smaddr(swp(sb, row, ch * 8)), src, sz);
        }
        u16* wb = sb + GT_A;
        {
            const int row = tid >> 3, ch = tid & 7;
            const u16* src = D.W + (size_t)(k0 + row) * D.ldw + D.woff + n0 + ch * 8;
            cp_async16(smaddr(swp(wb, row, ch * 8)), src);
        }
    };

    auto do_mma = [&](int st) {
        const u16* As = smg + st * GT_STAGE;
        const u16* Ws = As + GT_A;
        #pragma unroll
        for (int kk = 0; kk < 2; kk++) {
            u32 afr[2][2][4];
            #pragma unroll
            for (int s = 0; s < 2; s++)
                #pragma unroll
                for (int mt = 0; mt < 2; mt++)
                    ldsm4(afr[s][mt],
                          smaddr(swp(As, warp_m * 32 + mt * 16 + l15, s * 32 + kk * 16 + ka8)));
            u32 bfr[4][2];
            #pragma unroll
            for (int ntp = 0; ntp < 2; ntp++) {
                u32 t[4];
                ldsm4t(t, smaddr(swp(Ws, kk * 16 + l7 + wk8,
                                     warp_n * 32 + ntp * 16 + wn8)));
                bfr[2 * ntp][0]     = t[0]; bfr[2 * ntp][1]     = t[1];
                bfr[2 * ntp + 1][0] = t[2]; bfr[2 * ntp + 1][1] = t[3];
            }
            #pragma unroll
            for (int mt = 0; mt < 2; mt++)
                #pragma unroll
                for (int nt = 0; nt < 4; nt++) {
                    mma_f16(acc[mt][nt], afr[0][mt][0], afr[0][mt][1], afr[0][mt][2], afr[0][mt][3],
                            bfr[nt][0], bfr[nt][1]);
                    mma_f16(acc[mt][nt], afr[1][mt][0], afr[1][mt][1], afr[1][mt][2], afr[1][mt][3],
                            bfr[nt][0], bfr[nt][1]);
                }
        }
    };

    const int nk = D.K >> 5;
    fill(0, 0);
    CP_COMMIT();
    if (nk > 1) fill(32, 1);
    CP_COMMIT();

    for (int ki = 0; ki < nk; ki++) {
        CP_WAIT(1);
        __syncthreads();
        if (ki + 2 < nk) fill((ki + 2) * 32, (ki + 2) % 3);
        CP_COMMIT();
        do_mma(ki % 3);
    }

    if (D.outmode == 0) {
        float* C = (float*)D.C;
        #pragma unroll
        for (int mt = 0; mt < 2; mt++) {
            #pragma unroll
            for (int nt = 0; nt < 4; nt++) {
                const int m = m0 + warp_m * 32 + mt * 16 + g;
                const int n = n0 + warp_n * 32 + nt * 8 + tg * 2;
                const float bb0 = D.bias[n], bb1 = D.bias[n + 1];
                *(float2*)(C + (size_t)m * D.ldc + D.coff + n) =
                    make_float2(acc[mt][nt][0] + bb0, acc[mt][nt][1] + bb1);
                *(float2*)(C + (size_t)(m + 8) * D.ldc + D.coff + n) =
                    make_float2(acc[mt][nt][2] + bb0, acc[mt][nt][3] + bb1);
            }
        }
    } else {
        u16* Ch = (u16*)D.C;
        const float sc = (D.outmode == 2 && n0 < D.qcols) ? QSCALE : 1.0f;
        #pragma unroll
        for (int mt = 0; mt < 2; mt++) {
            #pragma unroll
            for (int nt = 0; nt < 4; nt++) {
                const int m = m0 + warp_m * 32 + mt * 16 + g;
                const int n = n0 + warp_n * 32 + nt * 8 + tg * 2;
                const float bb0 = D.bias[n], bb1 = D.bias[n + 1];
                float v[4] = {(acc[mt][nt][0] + bb0) * sc, (acc[mt][nt][1] + bb1) * sc,
                              (acc[mt][nt][2] + bb0) * sc, (acc[mt][nt][3] + bb1) * sc};
                if (D.outmode == 3) {
                    #pragma unroll
                    for (int r = 0; r < 4; r++) {
                        float x = v[r];
                        float u = 0.7978845608028654f * (x + 0.044715f * x * x * x);
                        v[r] = 0.5f * x * (1.0f + tanhf(u));
                    }
                }
                float h0, l0, h1, l1, h2, l2, h3, l3;
                split_f16(v[0], h0, l0); split_f16(v[1], h1, l1);
                split_f16(v[2], h2, l2); split_f16(v[3], h3, l3);
                const size_t o0 = (size_t)m * D.ldc + D.coff + n;
                const size_t o1 = (size_t)(m + 8) * D.ldc + D.coff + n;
                *(u32*)&Ch[o0]            = pack_f16(h0, h1);
                *(u32*)&Ch[o0 + D.oplane] = pack_f16(l0, l1);
                *(u32*)&Ch[o1]            = pack_f16(h2, h3);
                *(u32*)&Ch[o1 + D.oplane] = pack_f16(l2, l3);
            }
        }
    }
}

// ---------------------------------------------------------------------------
// Batched flash attention: 3-stage cp.async pipeline, ONE sync per KV tile
// (GEMM-validated structure). Q = hi/lo, K = hi only, V = hi/lo + single-
// fp16 P. XOR swizzle, exp2 softmax. 64 q-rows/CTA, 4 warps, 128 threads.
// ---------------------------------------------------------------------------
#define AD_MAX 4
struct AttnDesc {
    const u16 *Q, *K, *V;
    u16 *O;
    int ldq, qoff, qplane, ldk, koff, kplane, ldv, voff, vplane;
    int ldo, oplane, Tq, Tk, nbx, blk0;
};
struct AttnBatch { AttnDesc d[AD_MAX]; int n; };

#define STAGE_U16 (192 * 64)            // K hi (64 rows) + V hi/lo (128 rows)
#define SMEM_ATTN (3 * STAGE_U16 * 2)   // 73728 bytes (3 stages)

__global__ __launch_bounds__(128) void attn_batch_kernel(AttnBatch batch)
{
    extern __shared__ __align__(16) u16 smu[];

    int pi = 0;
    #pragma unroll
    for (int i = 1; i < AD_MAX; i++)
        if (i < batch.n && (int)blockIdx.x >= batch.d[i].blk0) pi = i;
    const AttnDesc D = batch.d[pi];
    const int lb = blockIdx.x - D.blk0;
    const int qt = lb % D.nbx;
    const int h  = (lb / D.nbx) % H_;
    const int b  = lb / (D.nbx * H_);

    const int tid  = threadIdx.x;
    const int lane = tid & 31;
    const int warp = tid >> 5;
    const int g  = lane >> 2;
    const int tg = lane & 3;
    const int mrow = warp * 16;

    const int l15 = lane & 15;
    const int l7  = lane & 7;
    const int qc8 = (lane >> 4) * 8;
    const int kk8 = (lane >> 4) * 8;
    const int kd8 = ((lane >> 3) & 1) * 8;
    const int vk8 = ((lane >> 3) & 1) * 8;
    const int vd8 = (lane >> 4) * 8;

    const u16* Qb = D.Q + (size_t)(b * D.Tq + qt * 64) * D.ldq + D.qoff + h * HD_;
    const u16* Kb = D.K + (size_t)(b * D.Tk) * D.ldk + D.koff + h * HD_;
    const u16* Vb = D.V + (size_t)(b * D.Tk) * D.ldv + D.voff + h * HD_;

    auto fill = [&](int kt, int st) {
        u16* sb = smu + st * STAGE_U16;
        #pragma unroll
        for (int i = 0; i < 12; i++) {
            const int plane = i >> 2;
            const int idx = tid + (i & 3) * 128;
            const int r = idx >> 3;
            const int c = (idx & 7) * 8;
            const u16* src;
            int drow;
            if (plane == 0)      { src = Kb + (size_t)(kt + r) * D.ldk + c;             drow = r; }
            else if (plane == 1) { src = Vb + (size_t)(kt + r) * D.ldv + c;             drow = 64 + r; }
            else                 { src = Vb + D.vplane + (size_t)(kt + r) * D.ldv + c;  drow = 128 + r; }
            cp_async16(smaddr(swp(sb, drow, c)), src);
        }
    };

    const int ntile = D.Tk >> 6;   // >= 8 for all problems

    // prologue: Q -> stage 2 (consumed into regs before iter-0 fill hits it)
    {
        u16* qs = smu + 2 * STAGE_U16;
        #pragma unroll
        for (int i = 0; i < 8; i++) {
            const int plane = i >> 2;
            const int idx = tid + (i & 3) * 128;
            const int r = idx >> 3;
            const int c = (idx & 7) * 8;
            const u16* src = Qb + (plane ? D.qplane : 0) + (size_t)r * D.ldq + c;
            cp_async16(smaddr(swp(qs, plane * 64 + r, c)), src);
        }
        CP_COMMIT();
    }
    fill(0, 0);
    CP_COMMIT();
    fill(64, 1);
    CP_COMMIT();
    CP_WAIT(2);            // Q group resident (T0, T1 may be in flight)
    __syncthreads();

    u32 qh[4][4], ql[4][4];
    {
        const u16* qs = smu + 2 * STAGE_U16;
        #pragma unroll
        for (int kc = 0; kc < 4; kc++) {
            ldsm4(qh[kc], smaddr(swp(qs, mrow + l15, kc * 16 + qc8)));
            ldsm4(ql[kc], smaddr(swp(qs, 64 + mrow + l15, kc * 16 + qc8)));
        }
    }

    float acc[8][4];
    #pragma unroll
    for (int nt = 0; nt < 8; nt++)
        #pragma unroll
        for (int r = 0; r < 4; r++) acc[nt][r] = 0.f;
    float mx0 = -1e30f, mx1 = -1e30f, lsum0 = 0.f, lsum1 = 0.f;

    for (int it = 0; it < ntile; it++) {
        CP_WAIT(1);          // tile it resident (it+1 may be in flight)
        __syncthreads();     // all warps past compute(it-1); Q ldsm done (it=0)
        if (it + 2 < ntile) fill((it + 2) * 64, (it + 2) % 3);
        CP_COMMIT();

        const u16* sb = smu + (it % 3) * STAGE_U16;

        // ---- S = Q K^T : (Q_hi + Q_lo) x K_hi ----
        float s[8][4];
        #pragma unroll
        for (int nt = 0; nt < 8; nt++)
            #pragma unroll
            for (int r = 0; r < 4; r++) s[nt][r] = 0.f;

        #pragma unroll
        for (int kc = 0; kc < 4; kc++) {
            #pragma unroll
            for (int ntp = 0; ntp < 4; ntp++) {
                u32 kh[4];
                ldsm4(kh, smaddr(swp(sb, ntp * 16 + l7 + kk8, kc * 16 + kd8)));
                mma_f16(s[2 * ntp],     qh[kc][0], qh[kc][1], qh[kc][2], qh[kc][3], kh[0], kh[1]);
                mma_f16(s[2 * ntp],     ql[kc][0], ql[kc][1], ql[kc][2], ql[kc][3], kh[0], kh[1]);
                mma_f16(s[2 * ntp + 1], qh[kc][0], qh[kc][1], qh[kc][2], qh[kc][3], kh[2], kh[3]);
                mma_f16(s[2 * ntp + 1], ql[kc][0], ql[kc][1], ql[kc][2], ql[kc][3], kh[2], kh[3]);
            }
        }

        // ---- online softmax (exp2 domain) ----
        float rm0 = -1e30f, rm1 = -1e30f;
        #pragma unroll
        for (int nt = 0; nt < 8; nt++) {
            rm0 = fmaxf(rm0, fmaxf(s[nt][0], s[nt][1]));
            rm1 = fmaxf(rm1, fmaxf(s[nt][2], s[nt][3]));
        }
        rm0 = fmaxf(rm0, __shfl_xor_sync(0xffffffffu, rm0, 1));
        rm0 = fmaxf(rm0, __shfl_xor_sync(0xffffffffu, rm0, 2));
        rm1 = fmaxf(rm1, __shfl_xor_sync(0xffffffffu, rm1, 1));
        rm1 = fmaxf(rm1, __shfl_xor_sync(0xffffffffu, rm1, 2));

        const float mn0 = fmaxf(mx0, rm0);
        const float mn1 = fmaxf(mx1, rm1);
        const float corr0 = exp2a(mx0 - mn0);
        const float corr1 = exp2a(mx1 - mn1);
        float rs0 = 0.f, rs1 = 0.f;
        #pragma unroll
        for (int nt = 0; nt < 8; nt++) {
            s[nt][0] = exp2a(s[nt][0] - mn0); rs0 += s[nt][0];
            s[nt][1] = exp2a(s[nt][1] - mn0); rs0 += s[nt][1];
            s[nt][2] = exp2a(s[nt][2] - mn1); rs1 += s[nt][2];
            s[nt][3] = exp2a(s[nt][3] - mn1); rs1 += s[nt][3];
        }
        rs0 += __shfl_xor_sync(0xffffffffu, rs0, 1);
        rs0 += __shfl_xor_sync(0xffffffffu, rs0, 2);
        rs1 += __shfl_xor_sync(0xffffffffu, rs1, 1);
        rs1 += __shfl_xor_sync(0xffffffffu, rs1, 2);
        lsum0 = lsum0 * corr0 + rs0; mx0 = mn0;
        lsum1 = lsum1 * corr1 + rs1; mx1 = mn1;
        #pragma unroll
        for (int nt = 0; nt < 8; nt++) {
            acc[nt][0] *= corr0; acc[nt][1] *= corr0;
            acc[nt][2] *= corr1; acc[nt][3] *= corr1;
        }

        // ---- O += P V : P single fp16, V = V_hi + V_lo ----
        #pragma unroll
        for (int kc = 0; kc < 4; kc++) {
            const int j0 = 2 * kc, j1 = 2 * kc + 1;
            u32 pa[4];
            pa[0] = pack_f16(s[j0][0], s[j0][1]);
            pa[1] = pack_f16(s[j0][2], s[j0][3]);
            pa[2] = pack_f16(s[j1][0], s[j1][1]);
            pa[3] = pack_f16(s[j1][2], s[j1][3]);

            #pragma unroll
            for (int ntp = 0; ntp < 4; ntp++) {
                u32 vh[4], vl[4];
                ldsm4t(vh, smaddr(swp(sb, 64 + kc * 16 + l7 + vk8, ntp * 16 + vd8)));
                ldsm4t(vl, smaddr(swp(sb, 128 + kc * 16 + l7 + vk8, ntp * 16 + vd8)));
                mma_f16(acc[2 * ntp],     pa[0], pa[1], pa[2], pa[3], vh[0], vh[1]);
                mma_f16(acc[2 * ntp],     pa[0], pa[1], pa[2], pa[3], vl[0], vl[1]);
                mma_f16(acc[2 * ntp + 1], pa[0], pa[1], pa[2], pa[3], vh[2], vh[3]);
                mma_f16(acc[2 * ntp + 1], pa[0], pa[1], pa[2], pa[3], vl[2], vl[3]);
            }
        }
    }

    const float inv0 = 1.0f / lsum0;
    const float inv1 = 1.0f / lsum1;
    u16* Ob = D.O + (size_t)(b * D.Tq + qt * 64 + mrow) * D.ldo + h * HD_;
    #pragma unroll
    for (int nt = 0; nt < 8; nt++) {
        const int col = nt * 8 + 2 * tg;
        float h0, l0, h1, l1;
        split_f16(acc[nt][0] * inv0, h0, l0);
        split_f16(acc[nt][1] * inv0, h1, l1);
        const size_t o0 = (size_t)g * D.ldo + col;
        *(u32*)&Ob[o0]            = pack_f16(h0, h1);
        *(u32*)&Ob[o0 + D.oplane] = pack_f16(l0, l1);
        split_f16(acc[nt][2] * inv1, h0, l0);
        split_f16(acc[nt][3] * inv1, h1, l1);
        const size_t o1 = (size_t)(g + 8) * D.ldo + col;
        *(u32*)&Ob[o1]            = pack_f16(h0, h1);
        *(u32*)&Ob[o1 + D.oplane] = pack_f16(l0, l1);
    }
}

// ---------------------------------------------------------------------------
// Host orchestration: split pass + 5 launches
// ---------------------------------------------------------------------------
static inline GemmDesc mk_gemm(const u16* A, int lda, int aoff, int aplane,
                               const u16* W, int ldw, int woff, int wplane,
                               const float* bias, void* C, int ldc, int coff,
                               int M, int N, int K, int ashift,
                               int outmode, int qcols, int oplane,
                               int& blk_cursor)
{
    GemmDesc d;
    d.A = A; d.W = W; d.bias = bias; d.C = C;
    d.lda = lda; d.aoff = aoff; d.aplane = aplane;
    d.ldw = ldw; d.woff = woff; d.wplane = wplane;
    d.ldc = ldc; d.coff = coff; d.K = K; d.ashift = ashift;
    d.outmode = outmode; d.qcols = qcols; d.oplane = oplane;
    d.nbx = N / 64; d.blk0 = blk_cursor;
    blk_cursor += (N / 64) * (M / 128);
    return d;
}

static inline AttnDesc mk_attn(const u16* Q, int ldq, int qoff, int qplane,
                               const u16* K, int ldk, int koff, int kplane,
                               const u16* V, int ldv, int voff, int vplane,
                               u16* O, int ldo, int oplane,
                               int Tq, int Tk, int& blk_cursor)
{
    AttnDesc d;
    d.Q = Q; d.K = K; d.V = V; d.O = O;
    d.ldq = ldq; d.qoff = qoff; d.qplane = qplane;
    d.ldk = ldk; d.koff = koff; d.kplane = kplane;
    d.ldv = ldv; d.voff = voff; d.vplane = vplane;
    d.ldo = ldo; d.oplane = oplane;
    d.Tq = Tq; d.Tk = Tk; d.nbx = Tq / 64; d.blk0 = blk_cursor;
    blk_cursor += (Tq / 64) * H_ * B_;
    return d;
}

static inline SplitDesc mk_split(const float* src, u16* dst, int nelem, int lo,
                                 int& blk_cursor)
{
    SplitDesc d;
    d.src = src; d.dst = dst; d.nelem = nelem; d.lo = lo; d.blk0 = blk_cursor;
    blk_cursor += nelem / 1024;
    return d;
}

extern "C" void kernel_launch(void* const* d_in, const int* in_sizes, int n_in,
                              void* d_out, int out_size)
{
    (void)in_sizes; (void)n_in; (void)out_size;

    const float* x_fast      = (const float*)d_in[0];
    const float* x_slow      = (const float*)d_in[1];
    const float* fself_wqkv  = (const float*)d_in[2];
    const float* fself_bqkv  = (const float*)d_in[3];
    const float* fself_wo    = (const float*)d_in[4];
    const float* fself_bo    = (const float*)d_in[5];
    const float* fcross_wqkv = (const float*)d_in[6];
    const float* fcross_bqkv = (const float*)d_in[7];
    const float* fcross_wo   = (const float*)d_in[8];
    const float* fcross_bo   = (const float*)d_in[9];
    const float* sself_wqkv  = (const float*)d_in[10];
    const float* sself_bqkv  = (const float*)d_in[11];
    const float* sself_wo    = (const float*)d_in[12];
    const float* sself_bo    = (const float*)d_in[13];
    const float* scross_wqkv = (const float*)d_in[14];
    const float* scross_bqkv = (const float*)d_in[15];
    const float* scross_wo   = (const float*)d_in[16];
    const float* scross_bo   = (const float*)d_in[17];
    const float* lift_w      = (const float*)d_in[18];
    const float* lift_b      = (const float*)d_in[19];
    const float* pool_w1     = (const float*)d_in[20];
    const float* pool_b1     = (const float*)d_in[21];
    const float* pool_w2     = (const float*)d_in[22];
    const float* pool_b2     = (const float*)d_in[23];

    float* out = (float*)d_out;
    float* zf = out;
    float* zs = out + (size_t)B_ * LF_ * 1024;

    float* S0 = nullptr;
    cudaGetSymbolAddress((void**)&S0, g_scratch);
    u16* xf    = (u16*)(S0 + O_XF);
    u16* xs    = (u16*)(S0 + O_XS);
    u16* wfs   = (u16*)(S0 + O_WFS);
    u16* wfc   = (u16*)(S0 + O_WFC);
    u16* wss   = (u16*)(S0 + O_WSS);
    u16* wsc   = (u16*)(S0 + O_WSC);
    u16* wof   = (u16*)(S0 + O_WOF);
    u16* woc   = (u16*)(S0 + O_WOC);
    u16* wos   = (u16*)(S0 + O_WOS);
    u16* wosc  = (u16*)(S0 + O_WOSC);
    u16* wl    = (u16*)(S0 + O_WL);
    u16* wp1   = (u16*)(S0 + O_WP1);
    u16* wp2   = (u16*)(S0 + O_WP2);
    u16* y     = (u16*)(S0 + O_Y);
    u16* qkv_f = (u16*)(S0 + O_QKV_F);
    u16* q_fc  = (u16*)(S0 + O_Q_FC);
    u16* kv_fc = (u16*)(S0 + O_KV_FC);
    u16* o1    = (u16*)(S0 + O_O1);
    u16* o2    = (u16*)(S0 + O_O2);
    u16* h1    = (u16*)(S0 + O_H1);
    u16* s     = (u16*)(S0 + O_S);
    u16* qkv_s = (u16*)(S0 + O_QKV_S);
    u16* q_sc  = (u16*)(S0 + O_Q_SC);
    u16* kv_sc = (u16*)(S0 + O_KV_SC);
    u16* o3    = (u16*)(S0 + O_O3);
    u16* o4    = (u16*)(S0 + O_O4);

    const int P_XF   = 4194304, P_XS  = 1048576;
    const int P_WQKV = 786432,  P_WO  = 262144, P_WL = 524288;
    const int P_WP1  = 8388608, P_WP2 = 1048576;
    const int P_QKVF = 6291456, P_QFC = 2097152, P_KVFC = 1048576;
    const int P_QKVS = 1572864, P_QSC = 524288,  P_KVSC = 1048576;
    const int P_O12  = 2097152, P_O34 = 524288;
    const int P_Y    = 524288,  P_H1  = 2097152, P_S = 524288;

    cudaFuncSetAttribute(gemm_batch_kernel,
                         cudaFuncAttributeMaxDynamicSharedMemorySize, SMEM_GEMM);
    cudaFuncSetAttribute(attn_batch_kernel,
                         cudaFuncAttributeMaxDynamicSharedMemorySize, SMEM_ATTN);

    // ---- L0: split inputs (hi+lo) + weights (hi only) ----
    {
        SplitBatch sb; int cur = 0;
        sb.d[0]  = mk_split(x_fast,      xf,   P_XF,   1, cur);
        sb.d[1]  = mk_split(x_slow,      xs,   P_XS,   1, cur);
        sb.d[2]  = mk_split(fself_wqkv,  wfs,  P_WQKV, 0, cur);
        sb.d[3]  = mk_split(fcross_wqkv, wfc,  P_WQKV, 0, cur);
        sb.d[4]  = mk_split(sself_wqkv,  wss,  P_WQKV, 0, cur);
        sb.d[5]  = mk_split(scross_wqkv, wsc,  P_WQKV, 0, cur);
        sb.d[6]  = mk_split(fself_wo,    wof,  P_WO,   0, cur);
        sb.d[7]  = mk_split(fcross_wo,   woc,  P_WO,   0, cur);
        sb.d[8]  = mk_split(sself_wo,    wos,  P_WO,   0, cur);
        sb.d[9]  = mk_split(scross_wo,   wosc, P_WO,   0, cur);
        sb.d[10] = mk_split(lift_w,      wl,   P_WL,   0, cur);
        sb.d[11] = mk_split(pool_w1,     wp1,  P_WP1,  0, cur);
        sb.d[12] = mk_split(pool_w2,     wp2,  P_WP2,  0, cur);
        sb.n = 13;
        split_kernel<<<cur, 256>>>(sb);
    }
    // ---- L1: input-only GEMMs ----
    {
        GemmBatch gb; int cur = 0;
        gb.d[0] = mk_gemm(xf, 1024, 0,   P_XF, wfs, 1536, 0, P_WQKV, fself_bqkv,  qkv_f, 1536, 0, 4096, 1536, 512,  0, 2, 512, P_QKVF, cur);
        gb.d[1] = mk_gemm(xf, 4096, 0,   P_XF, wp1, 2048, 0, P_WP1,  pool_b1,     h1,    2048, 0, 1024, POOLH, 4096, 0, 3, 0,   P_H1,   cur);
        gb.d[2] = mk_gemm(xf, 1024, 512, P_XF, wfc, 1536, 0, P_WQKV, fcross_bqkv, q_fc,  512,  0, 4096, 512,  512,  0, 2, 512, P_QFC,  cur);
        gb.d[3] = mk_gemm(xs, 1024, 0,   P_XS, wl,  512,  0, P_WL,   lift_b,      y,     512,  0, 1024, 512,  1024, 0, 2, 0,   P_Y,    cur);
        gb.d[4] = mk_gemm(xs, 1024, 0,   P_XS, wss, 1536, 0, P_WQKV, sself_bqkv,  qkv_s, 1536, 0, 1024, 1536, 512,  0, 2, 512, P_QKVS, cur);
        gb.d[5] = mk_gemm(xs, 1024, 512, P_XS, wsc, 1536, 0, P_WQKV, scross_bqkv, q_sc,  512,  0, 1024, 512,  512,  0, 2, 512, P_QSC,  cur);
        gb.n = 6;
        gemm_batch_kernel<<<cur, 256, SMEM_GEMM>>>(gb);
    }
    // ---- L2: kv_fc (needs y) + pool2 (needs h1) ----
    {
        GemmBatch gb; int cur = 0;
        gb.d[0] = mk_gemm(y,  512,  0, P_Y,  wfc, 1536, 512, P_WQKV, fcross_bqkv + 512, kv_fc, 1024, 0, 1024, 1024, 512,  0, 2, 0, P_KVFC, cur);
        gb.d[1] = mk_gemm(h1, 2048, 0, P_H1, wp2, 512,  0,   P_WP2,  pool_b2,           s,     512,  0, 1024, 512,  2048, 0, 2, 0, P_S,    cur);
        gb.n = 2;
        gemm_batch_kernel<<<cur, 256, SMEM_GEMM>>>(gb);
    }
    // ---- L3: kv_sc on shifted s ----
    {
        GemmBatch gb; int cur = 0;
        gb.d[0] = mk_gemm(s, 512, 0, P_S, wsc, 1536, 512, P_WQKV, scross_bqkv + 512, kv_sc, 1024, 0, 1024, 1024, 512, 1, 2, 0, P_KVSC, cur);
        gb.n = 1;
        gemm_batch_kernel<<<cur, 256, SMEM_GEMM>>>(gb);
    }
    // ---- L4: all four attentions ----
    {
        AttnBatch ab; int cur = 0;
        ab.d[0] = mk_attn(qkv_f, 1536, 0, P_QKVF, qkv_f, 1536, 512, P_QKVF, qkv_f, 1536, 1024, P_QKVF, o1, 512, P_O12, LF_, LF_, cur);
        ab.d[1] = mk_attn(q_fc,  512,  0, P_QFC,  kv_fc, 1024, 0,   P_KVFC, kv_fc, 1024, 512,  P_KVFC, o2, 512, P_O12, LF_, TS_, cur);
        ab.d[2] = mk_attn(qkv_s, 1536, 0, P_QKVS, qkv_s, 1536, 512, P_QKVS, qkv_s, 1536, 1024, P_QKVS, o3, 512, P_O34, TS_, TS_, cur);
        ab.d[3] = mk_attn(q_sc,  512,  0, P_QSC,  kv_sc, 1024, 0,   P_KVSC, kv_sc, 1024, 512,  P_KVSC, o4, 512, P_O34, TS_, TS_, cur);
        ab.n = 4;
        attn_batch_kernel<<<cur, 128, SMEM_ATTN>>>(ab);
    }
    // ---- L5: all four out-projections ----
    {
        GemmBatch gb; int cur = 0;
        gb.d[0] = mk_gemm(o1, 512, 0, P_O12, wof,  512, 0, P_WO, fself_bo,  zf, 1024, 0,   4096, 512, 512, 0, 0, 0, 0, cur);
        gb.d[1] = mk_gemm(o2, 512, 0, P_O12, woc,  512, 0, P_WO, fcross_bo, zf, 1024, 512, 4096, 512, 512, 0, 0, 0, 0, cur);
        gb.d[2] = mk_gemm(o3, 512, 0, P_O34, wos,  512, 0, P_WO, sself_bo,  zs, 1024, 0,   1024, 512, 512, 0, 0, 0, 0, cur);
        gb.d[3] = mk_gemm(o4, 512, 0, P_O34, wosc, 512, 0, P_WO, scross_bo, zs, 1024, 512, 1024, 512, 512, 0, 0, 0, 0, cur);
        gb.n = 4;
        gemm_batch_kernel<<<cur, 256, SMEM_GEMM>>>(gb);
    }
}

// round 15
// speedup vs baseline: 1.5836x; 1.3552x over previous
#include <cuda_runtime.h>
#include <cuda_fp16.h>
#include <math.h>

#define B_    2
#define LF_   2048
#define TS_   512
#define D2_   512
#define H_    8
#define HD_   64
#define POOLH 2048

typedef unsigned long long u64;
typedef unsigned int u32;
typedef unsigned short u16;

// ---------------------------------------------------------------------------
// fp16 split/pack + MMA + ldmatrix + cp.async helpers
// ---------------------------------------------------------------------------
__device__ __forceinline__ void split_f16(float x, float &hi, float &lo) {
    hi = __half2float(__float2half_rn(x));
    lo = x - hi;
}
__device__ __forceinline__ u32 pack_f16(float a, float b) {
    __half2 t = __floats2half2_rn(a, b);
    return *(u32*)&t;
}
__device__ __forceinline__ u64 pack4_f16(float a, float b, float c, float d) {
    return (u64)pack_f16(a, b) | ((u64)pack_f16(c, d) << 32);
}
__device__ __forceinline__ float exp2a(float x) {
    float r;
    asm("ex2.approx.f32 %0, %1;" : "=f"(r) : "f"(x));
    return r;
}
__device__ __forceinline__ void mma_f16(float c[4], u32 a0, u32 a1, u32 a2, u32 a3,
                                        u32 b0, u32 b1) {
    asm volatile(
        "mma.sync.aligned.m16n8k16.row.col.f32.f16.f16.f32 "
        "{%0,%1,%2,%3}, {%4,%5,%6,%7}, {%8,%9}, {%0,%1,%2,%3};\n"
        : "+f"(c[0]), "+f"(c[1]), "+f"(c[2]), "+f"(c[3])
        : "r"(a0), "r"(a1), "r"(a2), "r"(a3), "r"(b0), "r"(b1));
}
__device__ __forceinline__ u32 smaddr(const void* p) {
    return (u32)__cvta_generic_to_shared(p);
}
__device__ __forceinline__ void ldsm4(u32 r[4], u32 addr) {
    asm volatile("ldmatrix.sync.aligned.m8n8.x4.shared.b16 {%0,%1,%2,%3}, [%4];"
                 : "=r"(r[0]), "=r"(r[1]), "=r"(r[2]), "=r"(r[3]) : "r"(addr));
}
__device__ __forceinline__ void ldsm4t(u32 r[4], u32 addr) {
    asm volatile("ldmatrix.sync.aligned.m8n8.x4.trans.shared.b16 {%0,%1,%2,%3}, [%4];"
                 : "=r"(r[0]), "=r"(r[1]), "=r"(r[2]), "=r"(r[3]) : "r"(addr));
}
__device__ __forceinline__ void cp_async16(u32 dst, const void* src) {
    asm volatile("cp.async.cg.shared.global [%0], [%1], 16;" :: "r"(dst), "l"(src));
}
__device__ __forceinline__ void cp_async16z(u32 dst, const void* src, u32 sz) {
    asm volatile("cp.async.cg.shared.global [%0], [%1], 16, %2;"
                 :: "r"(dst), "l"(src), "r"(sz));
}
#define CP_COMMIT() asm volatile("cp.async.commit_group;")
#define CP_WAIT(n)  asm volatile("cp.async.wait_group %0;" :: "n"(n))

// XOR-swizzled smem addressing: 64 u16 per row (128B), chunk ^= row&7.
__device__ __forceinline__ u16* swp(u16* base, int row, int col) {
    return base + row * 64 + ((((col >> 3) ^ (row & 7)) << 3) | (col & 7));
}
__device__ __forceinline__ const u16* swp(const u16* base, int row, int col) {
    return base + row * 64 + ((((col >> 3) ^ (row & 7)) << 3) | (col & 7));
}

// combined softmax scale: 1/sqrt(64) * log2(e)
#define QSCALE 0.18033688011112042f

// ---------------------------------------------------------------------------
// Scratch layout (float units).
// ---------------------------------------------------------------------------
static const size_t O_XF    = 0;
static const size_t O_XS    = 4194304;
static const size_t O_WFS   = 5242880;
static const size_t O_WFC   = 6029312;
static const size_t O_WSS   = 6815744;
static const size_t O_WSC   = 7602176;
static const size_t O_WOF   = 8388608;
static const size_t O_WOC   = 8650752;
static const size_t O_WOS   = 8912896;
static const size_t O_WOSC  = 9175040;
static const size_t O_WL    = 9437184;
static const size_t O_WP1   = 9961472;
static const size_t O_WP2   = 18350080;
static const size_t O_Y     = 19398656;
static const size_t O_QKV_F = 19922944;
static const size_t O_Q_FC  = 26214400;
static const size_t O_KV_FC = 28311552;
static const size_t O_O1    = 29360128;
static const size_t O_O2    = 31457280;
static const size_t O_H1    = 33554432;
static const size_t O_S     = 35651584;
static const size_t O_QKV_S = 36175872;
static const size_t O_Q_SC  = 37748736;
static const size_t O_KV_SC = 38273024;
static const size_t O_O3    = 39321600;
static const size_t O_O4    = 39845888;
static const size_t SCRATCH_FLOATS = 40370176;

__device__ float g_scratch[SCRATCH_FLOATS];

// ---------------------------------------------------------------------------
// Batched split pass: fp32 -> fp16 hi plane (lo plane optional, unused now)
// ---------------------------------------------------------------------------
#define SD_MAX 14
struct SplitDesc { const float* src; u16* dst; int nelem; int blk0; int lo; };
struct SplitBatch { SplitDesc d[SD_MAX]; int n; };

__global__ __launch_bounds__(256) void split_kernel(SplitBatch b)
{
    int pi = 0;
    #pragma unroll
    for (int i = 1; i < SD_MAX; i++)
        if (i < b.n && (int)blockIdx.x >= b.d[i].blk0) pi = i;
    const SplitDesc D = b.d[pi];
    const int idx = ((blockIdx.x - D.blk0) * 256 + threadIdx.x) * 4;
    float4 v = *(const float4*)(D.src + idx);
    float h0, l0, h1, l1, h2, l2, h3, l3;
    split_f16(v.x, h0, l0); split_f16(v.y, h1, l1);
    split_f16(v.z, h2, l2); split_f16(v.w, h3, l3);
    *(u64*)&D.dst[idx] = pack4_f16(h0, h1, h2, h3);
    if (D.lo)
        *(u64*)&D.dst[idx + D.nelem] = pack4_f16(l0, l1, l2, l3);
}

// ---------------------------------------------------------------------------
// Batched GEMM: A = fp16 hi ONLY (1 term), W = fp16 hi only. 16 MMAs/chunk/warp.
// Block 128x64, K-chunk 32, 256 threads (8 warps 4x2). 3-stage cp.async
// pipeline, wait(1), one sync per K-chunk.
// outmode 0: fp32. 2: fp16 hi (+lo if olo; cols < qcols scaled QSCALE).
// 3: GELU then fp16 hi (+lo if olo).
// ---------------------------------------------------------------------------
#define GD_MAX 6
struct GemmDesc {
    const u16 *A, *W;
    const float *bias;
    void *C;
    int lda, aoff, ldw, woff, ldc, coff, K;
    int ashift, nbx, blk0, outmode, qcols, oplane, olo;
};
struct GemmBatch { GemmDesc d[GD_MAX]; int n; };

#define GT_A (128 * 64)               // container rows 64 u16; hi in chunks 0-3
#define GT_W (32 * 64)
#define GT_STAGE (GT_A + GT_W)        // 10240 u16 = 20480 B
#define SMEM_GEMM (3 * GT_STAGE * 2)  // 61440 B

__global__ __launch_bounds__(256) void gemm_batch_kernel(GemmBatch batch)
{
    extern __shared__ __align__(16) u16 smg[];

    int pi = 0;
    #pragma unroll
    for (int i = 1; i < GD_MAX; i++)
        if (i < batch.n && (int)blockIdx.x >= batch.d[i].blk0) pi = i;
    const GemmDesc D = batch.d[pi];
    const int lb = blockIdx.x - D.blk0;
    const int m0 = (lb / D.nbx) * 128;
    const int n0 = (lb % D.nbx) * 64;

    const int tid  = threadIdx.x;
    const int lane = tid & 31;
    const int warp = tid >> 5;
    const int warp_m = warp >> 1;
    const int warp_n = warp & 1;
    const int g  = lane >> 2;
    const int tg = lane & 3;

    const int l15 = lane & 15;
    const int l7  = lane & 7;
    const int ka8 = (lane >> 4) * 8;
    const int wk8 = ((lane >> 3) & 1) * 8;
    const int wn8 = (lane >> 4) * 8;

    float acc[2][4][4];
    #pragma unroll
    for (int mt = 0; mt < 2; mt++)
        #pragma unroll
        for (int nt = 0; nt < 4; nt++)
            #pragma unroll
            for (int r = 0; r < 4; r++) acc[mt][nt][r] = 0.f;

    auto fill = [&](int k0, int st) {
        u16* sb = smg + st * GT_STAGE;
        // A tile: 128 rows x 4 chunks (hi only)
        #pragma unroll
        for (int i = 0; i < 2; i++) {
            const int idx = tid + i * 256;      // 0..511
            const int row = idx >> 2, ch = idx & 3;
            const int kc = ch * 8;
            int mg = m0 + row;
            u32 sz = 16;
            if (D.ashift) {
                if ((mg & 511) == 0) { sz = 0; }
                else mg -= 1;
            }
            const u16* src = D.A + (size_t)(sz ? mg : 0) * D.lda + D.aoff + k0 + kc;
            cp_async16z(smaddr(swp(sb, row, kc)), src, sz);
        }
        // W tile: 32 k-rows x 8 chunks, hi plane only
        u16* wb = sb + GT_A;
        {
            const int row = tid >> 3, ch = tid & 7;
            const u16* src = D.W + (size_t)(k0 + row) * D.ldw + D.woff + n0 + ch * 8;
            cp_async16(smaddr(swp(wb, row, ch * 8)), src);
        }
    };

    auto do_mma = [&](int st) {
        const u16* As = smg + st * GT_STAGE;
        const u16* Ws = As + GT_A;
        #pragma unroll
        for (int kk = 0; kk < 2; kk++) {
            u32 afr[2][4];
            #pragma unroll
            for (int mt = 0; mt < 2; mt++)
                ldsm4(afr[mt],
                      smaddr(swp(As, warp_m * 32 + mt * 16 + l15, kk * 16 + ka8)));
            u32 bfr[4][2];
            #pragma unroll
            for (int ntp = 0; ntp < 2; ntp++) {
                u32 t[4];
                ldsm4t(t, smaddr(swp(Ws, kk * 16 + l7 + wk8,
                                     warp_n * 32 + ntp * 16 + wn8)));
                bfr[2 * ntp][0]     = t[0]; bfr[2 * ntp][1]     = t[1];
                bfr[2 * ntp + 1][0] = t[2]; bfr[2 * ntp + 1][1] = t[3];
            }
            #pragma unroll
            for (int mt = 0; mt < 2; mt++)
                #pragma unroll
                for (int nt = 0; nt < 4; nt++)
                    mma_f16(acc[mt][nt], afr[mt][0], afr[mt][1], afr[mt][2], afr[mt][3],
                            bfr[nt][0], bfr[nt][1]);
        }
    };

    const int nk = D.K >> 5;
    fill(0, 0);
    CP_COMMIT();
    if (nk > 1) fill(32, 1);
    CP_COMMIT();

    for (int ki = 0; ki < nk; ki++) {
        CP_WAIT(1);
        __syncthreads();
        if (ki + 2 < nk) fill((ki + 2) * 32, (ki + 2) % 3);
        CP_COMMIT();
        do_mma(ki % 3);
    }

    if (D.outmode == 0) {
        float* C = (float*)D.C;
        #pragma unroll
        for (int mt = 0; mt < 2; mt++) {
            #pragma unroll
            for (int nt = 0; nt < 4; nt++) {
                const int m = m0 + warp_m * 32 + mt * 16 + g;
                const int n = n0 + warp_n * 32 + nt * 8 + tg * 2;
                const float bb0 = D.bias[n], bb1 = D.bias[n + 1];
                *(float2*)(C + (size_t)m * D.ldc + D.coff + n) =
                    make_float2(acc[mt][nt][0] + bb0, acc[mt][nt][1] + bb1);
                *(float2*)(C + (size_t)(m + 8) * D.ldc + D.coff + n) =
                    make_float2(acc[mt][nt][2] + bb0, acc[mt][nt][3] + bb1);
            }
        }
    } else {
        u16* Ch = (u16*)D.C;
        const float sc = (D.outmode == 2 && n0 < D.qcols) ? QSCALE : 1.0f;
        #pragma unroll
        for (int mt = 0; mt < 2; mt++) {
            #pragma unroll
            for (int nt = 0; nt < 4; nt++) {
                const int m = m0 + warp_m * 32 + mt * 16 + g;
                const int n = n0 + warp_n * 32 + nt * 8 + tg * 2;
                const float bb0 = D.bias[n], bb1 = D.bias[n + 1];
                float v[4] = {(acc[mt][nt][0] + bb0) * sc, (acc[mt][nt][1] + bb1) * sc,
                              (acc[mt][nt][2] + bb0) * sc, (acc[mt][nt][3] + bb1) * sc};
                if (D.outmode == 3) {
                    #pragma unroll
                    for (int r = 0; r < 4; r++) {
                        float x = v[r];
                        float u = 0.7978845608028654f * (x + 0.044715f * x * x * x);
                        v[r] = 0.5f * x * (1.0f + tanhf(u));
                    }
                }
                float h0, l0, h1, l1, h2, l2, h3, l3;
                split_f16(v[0], h0, l0); split_f16(v[1], h1, l1);
                split_f16(v[2], h2, l2); split_f16(v[3], h3, l3);
                const size_t o0 = (size_t)m * D.ldc + D.coff + n;
                const size_t o1 = (size_t)(m + 8) * D.ldc + D.coff + n;
                *(u32*)&Ch[o0] = pack_f16(h0, h1);
                *(u32*)&Ch[o1] = pack_f16(h2, h3);
                if (D.olo) {
                    *(u32*)&Ch[o0 + D.oplane] = pack_f16(l0, l1);
                    *(u32*)&Ch[o1 + D.oplane] = pack_f16(l2, l3);
                }
            }
        }
    }
}

// ---------------------------------------------------------------------------
// Batched flash attention (R13 body): 3-stage pipeline, one sync/tile.
// Q = hi/lo, K = hi only, V = hi/lo, P single fp16. Output hi plane only.
// 64 q-rows/CTA, 4 warps, 128 threads.
// ---------------------------------------------------------------------------
#define AD_MAX 4
struct AttnDesc {
    const u16 *Q, *K, *V;
    u16 *O;
    int ldq, qoff, qplane, ldk, koff, kplane, ldv, voff, vplane;
    int ldo, oplane, Tq, Tk, nbx, blk0;
};
struct AttnBatch { AttnDesc d[AD_MAX]; int n; };

#define STAGE_U16 (192 * 64)
#define SMEM_ATTN (3 * STAGE_U16 * 2)   // 73728 bytes

__global__ __launch_bounds__(128) void attn_batch_kernel(AttnBatch batch)
{
    extern __shared__ __align__(16) u16 smu[];

    int pi = 0;
    #pragma unroll
    for (int i = 1; i < AD_MAX; i++)
        if (i < batch.n && (int)blockIdx.x >= batch.d[i].blk0) pi = i;
    const AttnDesc D = batch.d[pi];
    const int lb = blockIdx.x - D.blk0;
    const int qt = lb % D.nbx;
    const int h  = (lb / D.nbx) % H_;
    const int b  = lb / (D.nbx * H_);

    const int tid  = threadIdx.x;
    const int lane = tid & 31;
    const int warp = tid >> 5;
    const int g  = lane >> 2;
    const int tg = lane & 3;
    const int mrow = warp * 16;

    const int l15 = lane & 15;
    const int l7  = lane & 7;
    const int qc8 = (lane >> 4) * 8;
    const int kk8 = (lane >> 4) * 8;
    const int kd8 = ((lane >> 3) & 1) * 8;
    const int vk8 = ((lane >> 3) & 1) * 8;
    const int vd8 = (lane >> 4) * 8;

    const u16* Qb = D.Q + (size_t)(b * D.Tq + qt * 64) * D.ldq + D.qoff + h * HD_;
    const u16* Kb = D.K + (size_t)(b * D.Tk) * D.ldk + D.koff + h * HD_;
    const u16* Vb = D.V + (size_t)(b * D.Tk) * D.ldv + D.voff + h * HD_;

    auto fill = [&](int kt, int st) {
        u16* sb = smu + st * STAGE_U16;
        #pragma unroll
        for (int i = 0; i < 12; i++) {
            const int plane = i >> 2;
            const int idx = tid + (i & 3) * 128;
            const int r = idx >> 3;
            const int c = (idx & 7) * 8;
            const u16* src;
            int drow;
            if (plane == 0)      { src = Kb + (size_t)(kt + r) * D.ldk + c;             drow = r; }
            else if (plane == 1) { src = Vb + (size_t)(kt + r) * D.ldv + c;             drow = 64 + r; }
            else                 { src = Vb + D.vplane + (size_t)(kt + r) * D.ldv + c;  drow = 128 + r; }
            cp_async16(smaddr(swp(sb, drow, c)), src);
        }
    };

    const int ntile = D.Tk >> 6;

    {
        u16* qs = smu + 2 * STAGE_U16;
        #pragma unroll
        for (int i = 0; i < 8; i++) {
            const int plane = i >> 2;
            const int idx = tid + (i & 3) * 128;
            const int r = idx >> 3;
            const int c = (idx & 7) * 8;
            const u16* src = Qb + (plane ? D.qplane : 0) + (size_t)r * D.ldq + c;
            cp_async16(smaddr(swp(qs, plane * 64 + r, c)), src);
        }
        CP_COMMIT();
    }
    fill(0, 0);
    CP_COMMIT();
    fill(64, 1);
    CP_COMMIT();
    CP_WAIT(2);
    __syncthreads();

    u32 qh[4][4], ql[4][4];
    {
        const u16* qs = smu + 2 * STAGE_U16;
        #pragma unroll
        for (int kc = 0; kc < 4; kc++) {
            ldsm4(qh[kc], smaddr(swp(qs, mrow + l15, kc * 16 + qc8)));
            ldsm4(ql[kc], smaddr(swp(qs, 64 + mrow + l15, kc * 16 + qc8)));
        }
    }

    float acc[8][4];
    #pragma unroll
    for (int nt = 0; nt < 8; nt++)
        #pragma unroll
        for (int r = 0; r < 4; r++) acc[nt][r] = 0.f;
    float mx0 = -1e30f, mx1 = -1e30f, lsum0 = 0.f, lsum1 = 0.f;

    for (int it = 0; it < ntile; it++) {
        CP_WAIT(1);
        __syncthreads();
        if (it + 2 < ntile) fill((it + 2) * 64, (it + 2) % 3);
        CP_COMMIT();

        const u16* sb = smu + (it % 3) * STAGE_U16;

        float s[8][4];
        #pragma unroll
        for (int nt = 0; nt < 8; nt++)
            #pragma unroll
            for (int r = 0; r < 4; r++) s[nt][r] = 0.f;

        #pragma unroll
        for (int kc = 0; kc < 4; kc++) {
            #pragma unroll
            for (int ntp = 0; ntp < 4; ntp++) {
                u32 kh[4];
                ldsm4(kh, smaddr(swp(sb, ntp * 16 + l7 + kk8, kc * 16 + kd8)));
                mma_f16(s[2 * ntp],     qh[kc][0], qh[kc][1], qh[kc][2], qh[kc][3], kh[0], kh[1]);
                mma_f16(s[2 * ntp],     ql[kc][0], ql[kc][1], ql[kc][2], ql[kc][3], kh[0], kh[1]);
                mma_f16(s[2 * ntp + 1], qh[kc][0], qh[kc][1], qh[kc][2], qh[kc][3], kh[2], kh[3]);
                mma_f16(s[2 * ntp + 1], ql[kc][0], ql[kc][1], ql[kc][2], ql[kc][3], kh[2], kh[3]);
            }
        }

        float rm0 = -1e30f, rm1 = -1e30f;
        #pragma unroll
        for (int nt = 0; nt < 8; nt++) {
            rm0 = fmaxf(rm0, fmaxf(s[nt][0], s[nt][1]));
            rm1 = fmaxf(rm1, fmaxf(s[nt][2], s[nt][3]));
        }
        rm0 = fmaxf(rm0, __shfl_xor_sync(0xffffffffu, rm0, 1));
        rm0 = fmaxf(rm0, __shfl_xor_sync(0xffffffffu, rm0, 2));
        rm1 = fmaxf(rm1, __shfl_xor_sync(0xffffffffu, rm1, 1));
        rm1 = fmaxf(rm1, __shfl_xor_sync(0xffffffffu, rm1, 2));

        const float mn0 = fmaxf(mx0, rm0);
        const float mn1 = fmaxf(mx1, rm1);
        const float corr0 = exp2a(mx0 - mn0);
        const float corr1 = exp2a(mx1 - mn1);
        float rs0 = 0.f, rs1 = 0.f;
        #pragma unroll
        for (int nt = 0; nt < 8; nt++) {
            s[nt][0] = exp2a(s[nt][0] - mn0); rs0 += s[nt][0];
            s[nt][1] = exp2a(s[nt][1] - mn0); rs0 += s[nt][1];
            s[nt][2] = exp2a(s[nt][2] - mn1); rs1 += s[nt][2];
            s[nt][3] = exp2a(s[nt][3] - mn1); rs1 += s[nt][3];
        }
        rs0 += __shfl_xor_sync(0xffffffffu, rs0, 1);
        rs0 += __shfl_xor_sync(0xffffffffu, rs0, 2);
        rs1 += __shfl_xor_sync(0xffffffffu, rs1, 1);
        rs1 += __shfl_xor_sync(0xffffffffu, rs1, 2);
        lsum0 = lsum0 * corr0 + rs0; mx0 = mn0;
        lsum1 = lsum1 * corr1 + rs1; mx1 = mn1;
        #pragma unroll
        for (int nt = 0; nt < 8; nt++) {
            acc[nt][0] *= corr0; acc[nt][1] *= corr0;
            acc[nt][2] *= corr1; acc[nt][3] *= corr1;
        }

        #pragma unroll
        for (int kc = 0; kc < 4; kc++) {
            const int j0 = 2 * kc, j1 = 2 * kc + 1;
            u32 pa[4];
            pa[0] = pack_f16(s[j0][0], s[j0][1]);
            pa[1] = pack_f16(s[j0][2], s[j0][3]);
            pa[2] = pack_f16(s[j1][0], s[j1][1]);
            pa[3] = pack_f16(s[j1][2], s[j1][3]);

            #pragma unroll
            for (int ntp = 0; ntp < 4; ntp++) {
                u32 vh[4], vl[4];
                ldsm4t(vh, smaddr(swp(sb, 64 + kc * 16 + l7 + vk8, ntp * 16 + vd8)));
                ldsm4t(vl, smaddr(swp(sb, 128 + kc * 16 + l7 + vk8, ntp * 16 + vd8)));
                mma_f16(acc[2 * ntp],     pa[0], pa[1], pa[2], pa[3], vh[0], vh[1]);
                mma_f16(acc[2 * ntp],     pa[0], pa[1], pa[2], pa[3], vl[0], vl[1]);
                mma_f16(acc[2 * ntp + 1], pa[0], pa[1], pa[2], pa[3], vh[2], vh[3]);
                mma_f16(acc[2 * ntp + 1], pa[0], pa[1], pa[2], pa[3], vl[2], vl[3]);
            }
        }
    }

    const float inv0 = 1.0f / lsum0;
    const float inv1 = 1.0f / lsum1;
    u16* Ob = D.O + (size_t)(b * D.Tq + qt * 64 + mrow) * D.ldo + h * HD_;
    #pragma unroll
    for (int nt = 0; nt < 8; nt++) {
        const int col = nt * 8 + 2 * tg;
        *(u32*)&Ob[(size_t)g * D.ldo + col] =
            pack_f16(acc[nt][0] * inv0, acc[nt][1] * inv0);
        *(u32*)&Ob[(size_t)(g + 8) * D.ldo + col] =
            pack_f16(acc[nt][2] * inv1, acc[nt][3] * inv1);
    }
}

// ---------------------------------------------------------------------------
// Host orchestration: split pass + 5 launches
// ---------------------------------------------------------------------------
static inline GemmDesc mk_gemm(const u16* A, int lda, int aoff,
                               const u16* W, int ldw, int woff,
                               const float* bias, void* C, int ldc, int coff,
                               int M, int N, int K, int ashift,
                               int outmode, int qcols, int oplane, int olo,
                               int& blk_cursor)
{
    GemmDesc d;
    d.A = A; d.W = W; d.bias = bias; d.C = C;
    d.lda = lda; d.aoff = aoff;
    d.ldw = ldw; d.woff = woff;
    d.ldc = ldc; d.coff = coff; d.K = K; d.ashift = ashift;
    d.outmode = outmode; d.qcols = qcols; d.oplane = oplane; d.olo = olo;
    d.nbx = N / 64; d.blk0 = blk_cursor;
    blk_cursor += (N / 64) * (M / 128);
    return d;
}

static inline AttnDesc mk_attn(const u16* Q, int ldq, int qoff, int qplane,
                               const u16* K, int ldk, int koff, int kplane,
                               const u16* V, int ldv, int voff, int vplane,
                               u16* O, int ldo, int oplane,
                               int Tq, int Tk, int& blk_cursor)
{
    AttnDesc d;
    d.Q = Q; d.K = K; d.V = V; d.O = O;
    d.ldq = ldq; d.qoff = qoff; d.qplane = qplane;
    d.ldk = ldk; d.koff = koff; d.kplane = kplane;
    d.ldv = ldv; d.voff = voff; d.vplane = vplane;
    d.ldo = ldo; d.oplane = oplane;
    d.Tq = Tq; d.Tk = Tk; d.nbx = Tq / 64; d.blk0 = blk_cursor;
    blk_cursor += (Tq / 64) * H_ * B_;
    return d;
}

static inline SplitDesc mk_split(const float* src, u16* dst, int nelem, int lo,
                                 int& blk_cursor)
{
    SplitDesc d;
    d.src = src; d.dst = dst; d.nelem = nelem; d.lo = lo; d.blk0 = blk_cursor;
    blk_cursor += nelem / 1024;
    return d;
}

extern "C" void kernel_launch(void* const* d_in, const int* in_sizes, int n_in,
                              void* d_out, int out_size)
{
    (void)in_sizes; (void)n_in; (void)out_size;

    const float* x_fast      = (const float*)d_in[0];
    const float* x_slow      = (const float*)d_in[1];
    const float* fself_wqkv  = (const float*)d_in[2];
    const float* fself_bqkv  = (const float*)d_in[3];
    const float* fself_wo    = (const float*)d_in[4];
    const float* fself_bo    = (const float*)d_in[5];
    const float* fcross_wqkv = (const float*)d_in[6];
    const float* fcross_bqkv = (const float*)d_in[7];
    const float* fcross_wo   = (const float*)d_in[8];
    const float* fcross_bo   = (const float*)d_in[9];
    const float* sself_wqkv  = (const float*)d_in[10];
    const float* sself_bqkv  = (const float*)d_in[11];
    const float* sself_wo    = (const float*)d_in[12];
    const float* sself_bo    = (const float*)d_in[13];
    const float* scross_wqkv = (const float*)d_in[14];
    const float* scross_bqkv = (const float*)d_in[15];
    const float* scross_wo   = (const float*)d_in[16];
    const float* scross_bo   = (const float*)d_in[17];
    const float* lift_w      = (const float*)d_in[18];
    const float* lift_b      = (const float*)d_in[19];
    const float* pool_w1     = (const float*)d_in[20];
    const float* pool_b1     = (const float*)d_in[21];
    const float* pool_w2     = (const float*)d_in[22];
    const float* pool_b2     = (const float*)d_in[23];

    float* out = (float*)d_out;
    float* zf = out;
    float* zs = out + (size_t)B_ * LF_ * 1024;

    float* S0 = nullptr;
    cudaGetSymbolAddress((void**)&S0, g_scratch);
    u16* xf    = (u16*)(S0 + O_XF);
    u16* xs    = (u16*)(S0 + O_XS);
    u16* wfs   = (u16*)(S0 + O_WFS);
    u16* wfc   = (u16*)(S0 + O_WFC);
    u16* wss   = (u16*)(S0 + O_WSS);
    u16* wsc   = (u16*)(S0 + O_WSC);
    u16* wof   = (u16*)(S0 + O_WOF);
    u16* woc   = (u16*)(S0 + O_WOC);
    u16* wos   = (u16*)(S0 + O_WOS);
    u16* wosc  = (u16*)(S0 + O_WOSC);
    u16* wl    = (u16*)(S0 + O_WL);
    u16* wp1   = (u16*)(S0 + O_WP1);
    u16* wp2   = (u16*)(S0 + O_WP2);
    u16* y     = (u16*)(S0 + O_Y);
    u16* qkv_f = (u16*)(S0 + O_QKV_F);
    u16* q_fc  = (u16*)(S0 + O_Q_FC);
    u16* kv_fc = (u16*)(S0 + O_KV_FC);
    u16* o1    = (u16*)(S0 + O_O1);
    u16* o2    = (u16*)(S0 + O_O2);
    u16* h1    = (u16*)(S0 + O_H1);
    u16* s     = (u16*)(S0 + O_S);
    u16* qkv_s = (u16*)(S0 + O_QKV_S);
    u16* q_sc  = (u16*)(S0 + O_Q_SC);
    u16* kv_sc = (u16*)(S0 + O_KV_SC);
    u16* o3    = (u16*)(S0 + O_O3);
    u16* o4    = (u16*)(S0 + O_O4);

    const int P_XF   = 4194304, P_XS  = 1048576;
    const int P_WQKV = 786432,  P_WO  = 262144, P_WL = 524288;
    const int P_WP1  = 8388608, P_WP2 = 1048576;
    const int P_QKVF = 6291456, P_QFC = 2097152, P_KVFC = 1048576;
    const int P_QKVS = 1572864, P_QSC = 524288,  P_KVSC = 1048576;

    cudaFuncSetAttribute(gemm_batch_kernel,
                         cudaFuncAttributeMaxDynamicSharedMemorySize, SMEM_GEMM);
    cudaFuncSetAttribute(attn_batch_kernel,
                         cudaFuncAttributeMaxDynamicSharedMemorySize, SMEM_ATTN);

    // ---- L0: convert inputs + weights to fp16 hi planes ----
    {
        SplitBatch sb; int cur = 0;
        sb.d[0]  = mk_split(x_fast,      xf,   P_XF,   0, cur);
        sb.d[1]  = mk_split(x_slow,      xs,   P_XS,   0, cur);
        sb.d[2]  = mk_split(fself_wqkv,  wfs,  P_WQKV, 0, cur);
        sb.d[3]  = mk_split(fcross_wqkv, wfc,  P_WQKV, 0, cur);
        sb.d[4]  = mk_split(sself_wqkv,  wss,  P_WQKV, 0, cur);
        sb.d[5]  = mk_split(scross_wqkv, wsc,  P_WQKV, 0, cur);
        sb.d[6]  = mk_split(fself_wo,    wof,  P_WO,   0, cur);
        sb.d[7]  = mk_split(fcross_wo,   woc,  P_WO,   0, cur);
        sb.d[8]  = mk_split(sself_wo,    wos,  P_WO,   0, cur);
        sb.d[9]  = mk_split(scross_wo,   wosc, P_WO,   0, cur);
        sb.d[10] = mk_split(lift_w,      wl,   P_WL,   0, cur);
        sb.d[11] = mk_split(pool_w1,     wp1,  P_WP1,  0, cur);
        sb.d[12] = mk_split(pool_w2,     wp2,  P_WP2,  0, cur);
        sb.n = 13;
        split_kernel<<<cur, 256>>>(sb);
    }
    // ---- L1: input-only GEMMs ----
    {
        GemmBatch gb; int cur = 0;
        gb.d[0] = mk_gemm(xf, 1024, 0,   wfs, 1536, 0, fself_bqkv,  qkv_f, 1536, 0, 4096, 1536, 512,  0, 2, 512, P_QKVF, 1, cur);
        gb.d[1] = mk_gemm(xf, 4096, 0,   wp1, 2048, 0, pool_b1,     h1,    2048, 0, 1024, POOLH, 4096, 0, 3, 0,   0,      0, cur);
        gb.d[2] = mk_gemm(xf, 1024, 512, wfc, 1536, 0, fcross_bqkv, q_fc,  512,  0, 4096, 512,  512,  0, 2, 512, P_QFC,  1, cur);
        gb.d[3] = mk_gemm(xs, 1024, 0,   wl,  512,  0, lift_b,      y,     512,  0, 1024, 512,  1024, 0, 2, 0,   0,      0, cur);
        gb.d[4] = mk_gemm(xs, 1024, 0,   wss, 1536, 0, sself_bqkv,  qkv_s, 1536, 0, 1024, 1536, 512,  0, 2, 512, P_QKVS, 1, cur);
        gb.d[5] = mk_gemm(xs, 1024, 512, wsc, 1536, 0, scross_bqkv, q_sc,  512,  0, 1024, 512,  512,  0, 2, 512, P_QSC,  1, cur);
        gb.n = 6;
        gemm_batch_kernel<<<cur, 256, SMEM_GEMM>>>(gb);
    }
    // ---- L2: kv_fc (needs y) + pool2 (needs h1) ----
    {
        GemmBatch gb; int cur = 0;
        gb.d[0] = mk_gemm(y,  512,  0, wfc, 1536, 512, fcross_bqkv + 512, kv_fc, 1024, 0, 1024, 1024, 512,  0, 2, 0, P_KVFC, 1, cur);
        gb.d[1] = mk_gemm(h1, 2048, 0, wp2, 512,  0,   pool_b2,           s,     512,  0, 1024, 512,  2048, 0, 2, 0, 0,      0, cur);
        gb.n = 2;
        gemm_batch_kernel<<<cur, 256, SMEM_GEMM>>>(gb);
    }
    // ---- L3: kv_sc on shifted s ----
    {
        GemmBatch gb; int cur = 0;
        gb.d[0] = mk_gemm(s, 512, 0, wsc, 1536, 512, scross_bqkv + 512, kv_sc, 1024, 0, 1024, 1024, 512, 1, 2, 0, P_KVSC, 1, cur);
        gb.n = 1;
        gemm_batch_kernel<<<cur, 256, SMEM_GEMM>>>(gb);
    }
    // ---- L4: all four attentions ----
    {
        AttnBatch ab; int cur = 0;
        ab.d[0] = mk_attn(qkv_f, 1536, 0, P_QKVF, qkv_f, 1536, 512, P_QKVF, qkv_f, 1536, 1024, P_QKVF, o1, 512, 0, LF_, LF_, cur);
        ab.d[1] = mk_attn(q_fc,  512,  0, P_QFC,  kv_fc, 1024, 0,   P_KVFC, kv_fc, 1024, 512,  P_KVFC, o2, 512, 0, LF_, TS_, cur);
        ab.d[2] = mk_attn(qkv_s, 1536, 0, P_QKVS, qkv_s, 1536, 512, P_QKVS, qkv_s, 1536, 1024, P_QKVS, o3, 512, 0, TS_, TS_, cur);
        ab.d[3] = mk_attn(q_sc,  512,  0, P_QSC,  kv_sc, 1024, 0,   P_KVSC, kv_sc, 1024, 512,  P_KVSC, o4, 512, 0, TS_, TS_, cur);
        ab.n = 4;
        attn_batch_kernel<<<cur, 128, SMEM_ATTN>>>(ab);
    }
    // ---- L5: all four out-projections ----
    {
        GemmBatch gb; int cur = 0;
        gb.d[0] = mk_gemm(o1, 512, 0, wof,  512, 0, fself_bo,  zf, 1024, 0,   4096, 512, 512, 0, 0, 0, 0, 0, cur);
        gb.d[1] = mk_gemm(o2, 512, 0, woc,  512, 0, fcross_bo, zf, 1024, 512, 4096, 512, 512, 0, 0, 0, 0, 0, cur);
        gb.d[2] = mk_gemm(o3, 512, 0, wos,  512, 0, sself_bo,  zs, 1024, 0,   1024, 512, 512, 0, 0, 0, 0, 0, cur);
        gb.d[3] = mk_gemm(o4, 512, 0, wosc, 512, 0, scross_bo, zs, 1024, 512, 1024, 512, 512, 0, 0, 0, 0, 0, cur);
        gb.n = 4;
        gemm_batch_kernel<<<cur, 256, SMEM_GEMM>>>(gb);
    }
}

// round 16
// speedup vs baseline: 1.8051x; 1.1399x over previous
#include <cuda_runtime.h>
#include <cuda_fp16.h>
#include <math.h>

#define B_    2
#define LF_   2048
#define TS_   512
#define D2_   512
#define H_    8
#define HD_   64
#define POOLH 2048

typedef unsigned long long u64;
typedef unsigned int u32;
typedef unsigned short u16;

// ---------------------------------------------------------------------------
// fp16 helpers
// ---------------------------------------------------------------------------
__device__ __forceinline__ void split_f16(float x, float &hi, float &lo) {
    hi = __half2float(__float2half_rn(x));
    lo = x - hi;
}
__device__ __forceinline__ u32 pack_f16(float a, float b) {
    __half2 t = __floats2half2_rn(a, b);
    return *(u32*)&t;
}
__device__ __forceinline__ u64 pack4_f16(float a, float b, float c, float d) {
    return (u64)pack_f16(a, b) | ((u64)pack_f16(c, d) << 32);
}
__device__ __forceinline__ float exp2a(float x) {
    float r;
    asm("ex2.approx.f32 %0, %1;" : "=f"(r) : "f"(x));
    return r;
}
__device__ __forceinline__ void mma_f16(float c[4], u32 a0, u32 a1, u32 a2, u32 a3,
                                        u32 b0, u32 b1) {
    asm volatile(
        "mma.sync.aligned.m16n8k16.row.col.f32.f16.f16.f32 "
        "{%0,%1,%2,%3}, {%4,%5,%6,%7}, {%8,%9}, {%0,%1,%2,%3};\n"
        : "+f"(c[0]), "+f"(c[1]), "+f"(c[2]), "+f"(c[3])
        : "r"(a0), "r"(a1), "r"(a2), "r"(a3), "r"(b0), "r"(b1));
}
__device__ __forceinline__ u32 smaddr(const void* p) {
    return (u32)__cvta_generic_to_shared(p);
}
__device__ __forceinline__ void ldsm4(u32 r[4], u32 addr) {
    asm volatile("ldmatrix.sync.aligned.m8n8.x4.shared.b16 {%0,%1,%2,%3}, [%4];"
                 : "=r"(r[0]), "=r"(r[1]), "=r"(r[2]), "=r"(r[3]) : "r"(addr));
}
__device__ __forceinline__ void ldsm4t(u32 r[4], u32 addr) {
    asm volatile("ldmatrix.sync.aligned.m8n8.x4.trans.shared.b16 {%0,%1,%2,%3}, [%4];"
                 : "=r"(r[0]), "=r"(r[1]), "=r"(r[2]), "=r"(r[3]) : "r"(addr));
}
__device__ __forceinline__ void cp_async16(u32 dst, const void* src) {
    asm volatile("cp.async.cg.shared.global [%0], [%1], 16;" :: "r"(dst), "l"(src));
}
__device__ __forceinline__ void cp_async16z(u32 dst, const void* src, u32 sz) {
    asm volatile("cp.async.cg.shared.global [%0], [%1], 16, %2;"
                 :: "r"(dst), "l"(src), "r"(sz));
}
#define CP_COMMIT() asm volatile("cp.async.commit_group;")
#define CP_WAIT(n)  asm volatile("cp.async.wait_group %0;" :: "n"(n))

// XOR-swizzled smem addressing: 64 u16 per row (128B), chunk ^= row&7.
__device__ __forceinline__ u16* swp(u16* base, int row, int col) {
    return base + row * 64 + ((((col >> 3) ^ (row & 7)) << 3) | (col & 7));
}
__device__ __forceinline__ const u16* swp(const u16* base, int row, int col) {
    return base + row * 64 + ((((col >> 3) ^ (row & 7)) << 3) | (col & 7));
}

// combined softmax scale: 1/sqrt(64) * log2(e)
#define QSCALE 0.18033688011112042f

// ---------------------------------------------------------------------------
// Scratch layout (float units).
// ---------------------------------------------------------------------------
static const size_t O_XF    = 0;
static const size_t O_XS    = 4194304;
static const size_t O_WFS   = 5242880;
static const size_t O_WFC   = 6029312;
static const size_t O_WSS   = 6815744;
static const size_t O_WSC   = 7602176;
static const size_t O_WOF   = 8388608;
static const size_t O_WOC   = 8650752;
static const size_t O_WOS   = 8912896;
static const size_t O_WOSC  = 9175040;
static const size_t O_WL    = 9437184;
static const size_t O_WP1   = 9961472;
static const size_t O_WP2   = 18350080;
static const size_t O_Y     = 19398656;
static const size_t O_QKV_F = 19922944;
static const size_t O_Q_FC  = 26214400;
static const size_t O_KV_FC = 28311552;
static const size_t O_O1    = 29360128;
static const size_t O_O2    = 31457280;
static const size_t O_H1    = 33554432;
static const size_t O_S     = 35651584;
static const size_t O_QKV_S = 36175872;
static const size_t O_Q_SC  = 37748736;
static const size_t O_KV_SC = 38273024;
static const size_t O_O3    = 39321600;
static const size_t O_O4    = 39845888;
static const size_t SCRATCH_FLOATS = 40370176;

__device__ float g_scratch[SCRATCH_FLOATS];

// ---------------------------------------------------------------------------
// Batched convert pass: fp32 -> fp16 plane
// ---------------------------------------------------------------------------
#define SD_MAX 14
struct SplitDesc { const float* src; u16* dst; int nelem; int blk0; int lo; };
struct SplitBatch { SplitDesc d[SD_MAX]; int n; };

__global__ __launch_bounds__(256) void split_kernel(SplitBatch b)
{
    int pi = 0;
    #pragma unroll
    for (int i = 1; i < SD_MAX; i++)
        if (i < b.n && (int)blockIdx.x >= b.d[i].blk0) pi = i;
    const SplitDesc D = b.d[pi];
    const int idx = ((blockIdx.x - D.blk0) * 256 + threadIdx.x) * 4;
    float4 v = *(const float4*)(D.src + idx);
    float h0, l0, h1, l1, h2, l2, h3, l3;
    split_f16(v.x, h0, l0); split_f16(v.y, h1, l1);
    split_f16(v.z, h2, l2); split_f16(v.w, h3, l3);
    *(u64*)&D.dst[idx] = pack4_f16(h0, h1, h2, h3);
    if (D.lo)
        *(u64*)&D.dst[idx + D.nelem] = pack4_f16(l0, l1, l2, l3);
}

// ---------------------------------------------------------------------------
// Batched GEMM (R14 config, verbatim): A fp16, W fp16, fp32 accumulate.
// Block 128x64, K-chunk 32, 256 threads (8 warps 4x2). 3-stage cp.async
// pipeline, wait(1), one sync per K-chunk.
// outmode 0: fp32. 2: fp16 (+lo plane if olo; cols < qcols scaled QSCALE).
// 3: GELU then fp16.
// ---------------------------------------------------------------------------
#define GD_MAX 6
struct GemmDesc {
    const u16 *A, *W;
    const float *bias;
    void *C;
    int lda, aoff, ldw, woff, ldc, coff, K;
    int ashift, nbx, blk0, outmode, qcols, oplane, olo;
};
struct GemmBatch { GemmDesc d[GD_MAX]; int n; };

#define GT_A (128 * 64)
#define GT_W (32 * 64)
#define GT_STAGE (GT_A + GT_W)        // 10240 u16 = 20480 B
#define SMEM_GEMM (3 * GT_STAGE * 2)  // 61440 B

__global__ __launch_bounds__(256) void gemm_batch_kernel(GemmBatch batch)
{
    extern __shared__ __align__(16) u16 smg[];

    int pi = 0;
    #pragma unroll
    for (int i = 1; i < GD_MAX; i++)
        if (i < batch.n && (int)blockIdx.x >= batch.d[i].blk0) pi = i;
    const GemmDesc D = batch.d[pi];
    const int lb = blockIdx.x - D.blk0;
    const int m0 = (lb / D.nbx) * 128;
    const int n0 = (lb % D.nbx) * 64;

    const int tid  = threadIdx.x;
    const int lane = tid & 31;
    const int warp = tid >> 5;
    const int warp_m = warp >> 1;
    const int warp_n = warp & 1;
    const int g  = lane >> 2;
    const int tg = lane & 3;

    const int l15 = lane & 15;
    const int l7  = lane & 7;
    const int ka8 = (lane >> 4) * 8;
    const int wk8 = ((lane >> 3) & 1) * 8;
    const int wn8 = (lane >> 4) * 8;

    float acc[2][4][4];
    #pragma unroll
    for (int mt = 0; mt < 2; mt++)
        #pragma unroll
        for (int nt = 0; nt < 4; nt++)
            #pragma unroll
            for (int r = 0; r < 4; r++) acc[mt][nt][r] = 0.f;

    auto fill = [&](int k0, int st) {
        u16* sb = smg + st * GT_STAGE;
        #pragma unroll
        for (int i = 0; i < 2; i++) {
            const int idx = tid + i * 256;
            const int row = idx >> 2, ch = idx & 3;
            const int kc = ch * 8;
            int mg = m0 + row;
            u32 sz = 16;
            if (D.ashift) {
                if ((mg & 511) == 0) { sz = 0; }
                else mg -= 1;
            }
            const u16* src = D.A + (size_t)(sz ? mg : 0) * D.lda + D.aoff + k0 + kc;
            cp_async16z(smaddr(swp(sb, row, kc)), src, sz);
        }
        u16* wb = sb + GT_A;
        {
            const int row = tid >> 3, ch = tid & 7;
            const u16* src = D.W + (size_t)(k0 + row) * D.ldw + D.woff + n0 + ch * 8;
            cp_async16(smaddr(swp(wb, row, ch * 8)), src);
        }
    };

    auto do_mma = [&](int st) {
        const u16* As = smg + st * GT_STAGE;
        const u16* Ws = As + GT_A;
        #pragma unroll
        for (int kk = 0; kk < 2; kk++) {
            u32 afr[2][4];
            #pragma unroll
            for (int mt = 0; mt < 2; mt++)
                ldsm4(afr[mt],
                      smaddr(swp(As, warp_m * 32 + mt * 16 + l15, kk * 16 + ka8)));
            u32 bfr[4][2];
            #pragma unroll
            for (int ntp = 0; ntp < 2; ntp++) {
                u32 t[4];
                ldsm4t(t, smaddr(swp(Ws, kk * 16 + l7 + wk8,
                                     warp_n * 32 + ntp * 16 + wn8)));
                bfr[2 * ntp][0]     = t[0]; bfr[2 * ntp][1]     = t[1];
                bfr[2 * ntp + 1][0] = t[2]; bfr[2 * ntp + 1][1] = t[3];
            }
            #pragma unroll
            for (int mt = 0; mt < 2; mt++)
                #pragma unroll
                for (int nt = 0; nt < 4; nt++)
                    mma_f16(acc[mt][nt], afr[mt][0], afr[mt][1], afr[mt][2], afr[mt][3],
                            bfr[nt][0], bfr[nt][1]);
        }
    };

    const int nk = D.K >> 5;
    fill(0, 0);
    CP_COMMIT();
    if (nk > 1) fill(32, 1);
    CP_COMMIT();

    for (int ki = 0; ki < nk; ki++) {
        CP_WAIT(1);
        __syncthreads();
        if (ki + 2 < nk) fill((ki + 2) * 32, (ki + 2) % 3);
        CP_COMMIT();
        do_mma(ki % 3);
    }

    if (D.outmode == 0) {
        float* C = (float*)D.C;
        #pragma unroll
        for (int mt = 0; mt < 2; mt++) {
            #pragma unroll
            for (int nt = 0; nt < 4; nt++) {
                const int m = m0 + warp_m * 32 + mt * 16 + g;
                const int n = n0 + warp_n * 32 + nt * 8 + tg * 2;
                const float bb0 = D.bias[n], bb1 = D.bias[n + 1];
                *(float2*)(C + (size_t)m * D.ldc + D.coff + n) =
                    make_float2(acc[mt][nt][0] + bb0, acc[mt][nt][1] + bb1);
                *(float2*)(C + (size_t)(m + 8) * D.ldc + D.coff + n) =
                    make_float2(acc[mt][nt][2] + bb0, acc[mt][nt][3] + bb1);
            }
        }
    } else {
        u16* Ch = (u16*)D.C;
        const float sc = (D.outmode == 2 && n0 < D.qcols) ? QSCALE : 1.0f;
        #pragma unroll
        for (int mt = 0; mt < 2; mt++) {
            #pragma unroll
            for (int nt = 0; nt < 4; nt++) {
                const int m = m0 + warp_m * 32 + mt * 16 + g;
                const int n = n0 + warp_n * 32 + nt * 8 + tg * 2;
                const float bb0 = D.bias[n], bb1 = D.bias[n + 1];
                float v[4] = {(acc[mt][nt][0] + bb0) * sc, (acc[mt][nt][1] + bb1) * sc,
                              (acc[mt][nt][2] + bb0) * sc, (acc[mt][nt][3] + bb1) * sc};
                if (D.outmode == 3) {
                    #pragma unroll
                    for (int r = 0; r < 4; r++) {
                        float x = v[r];
                        float u = 0.7978845608028654f * (x + 0.044715f * x * x * x);
                        v[r] = 0.5f * x * (1.0f + tanhf(u));
                    }
                }
                float h0, l0, h1, l1, h2, l2, h3, l3;
                split_f16(v[0], h0, l0); split_f16(v[1], h1, l1);
                split_f16(v[2], h2, l2); split_f16(v[3], h3, l3);
                const size_t o0 = (size_t)m * D.ldc + D.coff + n;
                const size_t o1 = (size_t)(m + 8) * D.ldc + D.coff + n;
                *(u32*)&Ch[o0] = pack_f16(h0, h1);
                *(u32*)&Ch[o1] = pack_f16(h2, h3);
                if (D.olo) {
                    *(u32*)&Ch[o0 + D.oplane] = pack_f16(l0, l1);
                    *(u32*)&Ch[o1 + D.oplane] = pack_f16(l2, l3);
                }
            }
        }
    }
}

// ---------------------------------------------------------------------------
// Batched flash attention: plain fp16 Q/K/V/P, fp32 softmax+accumulate.
// 3-stage cp.async pipeline, one sync per tile. 64 MMAs/tile (half of R13).
// 64 q-rows/CTA, 4 warps, 128 threads. Output fp16 plane.
// ---------------------------------------------------------------------------
#define AD_MAX 4
struct AttnDesc {
    const u16 *Q, *K, *V;
    u16 *O;
    int ldq, qoff, ldk, koff, ldv, voff;
    int ldo, Tq, Tk, nbx, blk0;
};
struct AttnBatch { AttnDesc d[AD_MAX]; int n; };

#define STAGE_U16 (128 * 64)            // K (64 rows) + V (64 rows)
#define SMEM_ATTN (3 * STAGE_U16 * 2)   // 49152 bytes (3 stages)

__global__ __launch_bounds__(128) void attn_batch_kernel(AttnBatch batch)
{
    extern __shared__ __align__(16) u16 smu[];

    int pi = 0;
    #pragma unroll
    for (int i = 1; i < AD_MAX; i++)
        if (i < batch.n && (int)blockIdx.x >= batch.d[i].blk0) pi = i;
    const AttnDesc D = batch.d[pi];
    const int lb = blockIdx.x - D.blk0;
    const int qt = lb % D.nbx;
    const int h  = (lb / D.nbx) % H_;
    const int b  = lb / (D.nbx * H_);

    const int tid  = threadIdx.x;
    const int lane = tid & 31;
    const int warp = tid >> 5;
    const int g  = lane >> 2;
    const int tg = lane & 3;
    const int mrow = warp * 16;

    const int l15 = lane & 15;
    const int l7  = lane & 7;
    const int qc8 = (lane >> 4) * 8;
    const int kk8 = (lane >> 4) * 8;
    const int kd8 = ((lane >> 3) & 1) * 8;
    const int vk8 = ((lane >> 3) & 1) * 8;
    const int vd8 = (lane >> 4) * 8;

    const u16* Qb = D.Q + (size_t)(b * D.Tq + qt * 64) * D.ldq + D.qoff + h * HD_;
    const u16* Kb = D.K + (size_t)(b * D.Tk) * D.ldk + D.koff + h * HD_;
    const u16* Vb = D.V + (size_t)(b * D.Tk) * D.ldv + D.voff + h * HD_;

    // fill one KV tile: K rows 0-63, V rows 64-127
    auto fill = [&](int kt, int st) {
        u16* sb = smu + st * STAGE_U16;
        #pragma unroll
        for (int i = 0; i < 8; i++) {
            const int plane = i >> 2;               // 0 K, 1 V
            const int idx = tid + (i & 3) * 128;    // 0..511
            const int r = idx >> 3;
            const int c = (idx & 7) * 8;
            const u16* src = (plane == 0)
                ? Kb + (size_t)(kt + r) * D.ldk + c
                : Vb + (size_t)(kt + r) * D.ldv + c;
            cp_async16(smaddr(swp(sb, plane * 64 + r, c)), src);
        }
    };

    const int ntile = D.Tk >> 6;

    // prologue: Q -> stage 2 (consumed into regs before iter-0 sync)
    {
        u16* qs = smu + 2 * STAGE_U16;
        #pragma unroll
        for (int i = 0; i < 4; i++) {
            const int idx = tid + i * 128;          // 0..511
            const int r = idx >> 3;
            const int c = (idx & 7) * 8;
            cp_async16(smaddr(swp(qs, r, c)), Qb + (size_t)r * D.ldq + c);
        }
        CP_COMMIT();
    }
    fill(0, 0);
    CP_COMMIT();
    fill(64, 1);
    CP_COMMIT();
    CP_WAIT(2);            // Q group resident
    __syncthreads();

    u32 qh[4][4];
    {
        const u16* qs = smu + 2 * STAGE_U16;
        #pragma unroll
        for (int kc = 0; kc < 4; kc++)
            ldsm4(qh[kc], smaddr(swp(qs, mrow + l15, kc * 16 + qc8)));
    }

    float acc[8][4];
    #pragma unroll
    for (int nt = 0; nt < 8; nt++)
        #pragma unroll
        for (int r = 0; r < 4; r++) acc[nt][r] = 0.f;
    float mx0 = -1e30f, mx1 = -1e30f, lsum0 = 0.f, lsum1 = 0.f;

    for (int it = 0; it < ntile; it++) {
        CP_WAIT(1);          // tile it resident (it+1 may be in flight)
        __syncthreads();     // all warps past compute(it-1); Q ldsm done (it=0)
        if (it + 2 < ntile) fill((it + 2) * 64, (it + 2) % 3);
        CP_COMMIT();

        const u16* sb = smu + (it % 3) * STAGE_U16;

        // ---- S = Q K^T ----
        float s[8][4];
        #pragma unroll
        for (int nt = 0; nt < 8; nt++)
            #pragma unroll
            for (int r = 0; r < 4; r++) s[nt][r] = 0.f;

        #pragma unroll
        for (int kc = 0; kc < 4; kc++) {
            #pragma unroll
            for (int ntp = 0; ntp < 4; ntp++) {
                u32 kh[4];
                ldsm4(kh, smaddr(swp(sb, ntp * 16 + l7 + kk8, kc * 16 + kd8)));
                mma_f16(s[2 * ntp],     qh[kc][0], qh[kc][1], qh[kc][2], qh[kc][3], kh[0], kh[1]);
                mma_f16(s[2 * ntp + 1], qh[kc][0], qh[kc][1], qh[kc][2], qh[kc][3], kh[2], kh[3]);
            }
        }

        // ---- online softmax (exp2 domain) ----
        float rm0 = -1e30f, rm1 = -1e30f;
        #pragma unroll
        for (int nt = 0; nt < 8; nt++) {
            rm0 = fmaxf(rm0, fmaxf(s[nt][0], s[nt][1]));
            rm1 = fmaxf(rm1, fmaxf(s[nt][2], s[nt][3]));
        }
        rm0 = fmaxf(rm0, __shfl_xor_sync(0xffffffffu, rm0, 1));
        rm0 = fmaxf(rm0, __shfl_xor_sync(0xffffffffu, rm0, 2));
        rm1 = fmaxf(rm1, __shfl_xor_sync(0xffffffffu, rm1, 1));
        rm1 = fmaxf(rm1, __shfl_xor_sync(0xffffffffu, rm1, 2));

        const float mn0 = fmaxf(mx0, rm0);
        const float mn1 = fmaxf(mx1, rm1);
        const float corr0 = exp2a(mx0 - mn0);
        const float corr1 = exp2a(mx1 - mn1);
        float rs0 = 0.f, rs1 = 0.f;
        #pragma unroll
        for (int nt = 0; nt < 8; nt++) {
            s[nt][0] = exp2a(s[nt][0] - mn0); rs0 += s[nt][0];
            s[nt][1] = exp2a(s[nt][1] - mn0); rs0 += s[nt][1];
            s[nt][2] = exp2a(s[nt][2] - mn1); rs1 += s[nt][2];
            s[nt][3] = exp2a(s[nt][3] - mn1); rs1 += s[nt][3];
        }
        rs0 += __shfl_xor_sync(0xffffffffu, rs0, 1);
        rs0 += __shfl_xor_sync(0xffffffffu, rs0, 2);
        rs1 += __shfl_xor_sync(0xffffffffu, rs1, 1);
        rs1 += __shfl_xor_sync(0xffffffffu, rs1, 2);
        lsum0 = lsum0 * corr0 + rs0; mx0 = mn0;
        lsum1 = lsum1 * corr1 + rs1; mx1 = mn1;
        #pragma unroll
        for (int nt = 0; nt < 8; nt++) {
            acc[nt][0] *= corr0; acc[nt][1] *= corr0;
            acc[nt][2] *= corr1; acc[nt][3] *= corr1;
        }

        // ---- O += P V ----
        #pragma unroll
        for (int kc = 0; kc < 4; kc++) {
            const int j0 = 2 * kc, j1 = 2 * kc + 1;
            u32 pa[4];
            pa[0] = pack_f16(s[j0][0], s[j0][1]);
            pa[1] = pack_f16(s[j0][2], s[j0][3]);
            pa[2] = pack_f16(s[j1][0], s[j1][1]);
            pa[3] = pack_f16(s[j1][2], s[j1][3]);

            #pragma unroll
            for (int ntp = 0; ntp < 4; ntp++) {
                u32 vh[4];
                ldsm4t(vh, smaddr(swp(sb, 64 + kc * 16 + l7 + vk8, ntp * 16 + vd8)));
                mma_f16(acc[2 * ntp],     pa[0], pa[1], pa[2], pa[3], vh[0], vh[1]);
                mma_f16(acc[2 * ntp + 1], pa[0], pa[1], pa[2], pa[3], vh[2], vh[3]);
            }
        }
    }

    const float inv0 = 1.0f / lsum0;
    const float inv1 = 1.0f / lsum1;
    u16* Ob = D.O + (size_t)(b * D.Tq + qt * 64 + mrow) * D.ldo + h * HD_;
    #pragma unroll
    for (int nt = 0; nt < 8; nt++) {
        const int col = nt * 8 + 2 * tg;
        *(u32*)&Ob[(size_t)g * D.ldo + col] =
            pack_f16(acc[nt][0] * inv0, acc[nt][1] * inv0);
        *(u32*)&Ob[(size_t)(g + 8) * D.ldo + col] =
            pack_f16(acc[nt][2] * inv1, acc[nt][3] * inv1);
    }
}

// ---------------------------------------------------------------------------
// Host orchestration: convert pass + 5 launches
// ---------------------------------------------------------------------------
static inline GemmDesc mk_gemm(const u16* A, int lda, int aoff,
                               const u16* W, int ldw, int woff,
                               const float* bias, void* C, int ldc, int coff,
                               int M, int N, int K, int ashift,
                               int outmode, int qcols, int oplane, int olo,
                               int& blk_cursor)
{
    GemmDesc d;
    d.A = A; d.W = W; d.bias = bias; d.C = C;
    d.lda = lda; d.aoff = aoff;
    d.ldw = ldw; d.woff = woff;
    d.ldc = ldc; d.coff = coff; d.K = K; d.ashift = ashift;
    d.outmode = outmode; d.qcols = qcols; d.oplane = oplane; d.olo = olo;
    d.nbx = N / 64; d.blk0 = blk_cursor;
    blk_cursor += (N / 64) * (M / 128);
    return d;
}

static inline AttnDesc mk_attn(const u16* Q, int ldq, int qoff,
                               const u16* K, int ldk, int koff,
                               const u16* V, int ldv, int voff,
                               u16* O, int ldo, int Tq, int Tk, int& blk_cursor)
{
    AttnDesc d;
    d.Q = Q; d.K = K; d.V = V; d.O = O;
    d.ldq = ldq; d.qoff = qoff;
    d.ldk = ldk; d.koff = koff;
    d.ldv = ldv; d.voff = voff;
    d.ldo = ldo;
    d.Tq = Tq; d.Tk = Tk; d.nbx = Tq / 64; d.blk0 = blk_cursor;
    blk_cursor += (Tq / 64) * H_ * B_;
    return d;
}

static inline SplitDesc mk_split(const float* src, u16* dst, int nelem, int lo,
                                 int& blk_cursor)
{
    SplitDesc d;
    d.src = src; d.dst = dst; d.nelem = nelem; d.lo = lo; d.blk0 = blk_cursor;
    blk_cursor += nelem / 1024;
    return d;
}

extern "C" void kernel_launch(void* const* d_in, const int* in_sizes, int n_in,
                              void* d_out, int out_size)
{
    (void)in_sizes; (void)n_in; (void)out_size;

    const float* x_fast      = (const float*)d_in[0];
    const float* x_slow      = (const float*)d_in[1];
    const float* fself_wqkv  = (const float*)d_in[2];
    const float* fself_bqkv  = (const float*)d_in[3];
    const float* fself_wo    = (const float*)d_in[4];
    const float* fself_bo    = (const float*)d_in[5];
    const float* fcross_wqkv = (const float*)d_in[6];
    const float* fcross_bqkv = (const float*)d_in[7];
    const float* fcross_wo   = (const float*)d_in[8];
    const float* fcross_bo   = (const float*)d_in[9];
    const float* sself_wqkv  = (const float*)d_in[10];
    const float* sself_bqkv  = (const float*)d_in[11];
    const float* sself_wo    = (const float*)d_in[12];
    const float* sself_bo    = (const float*)d_in[13];
    const float* scross_wqkv = (const float*)d_in[14];
    const float* scross_bqkv = (const float*)d_in[15];
    const float* scross_wo   = (const float*)d_in[16];
    const float* scross_bo   = (const float*)d_in[17];
    const float* lift_w      = (const float*)d_in[18];
    const float* lift_b      = (const float*)d_in[19];
    const float* pool_w1     = (const float*)d_in[20];
    const float* pool_b1     = (const float*)d_in[21];
    const float* pool_w2     = (const float*)d_in[22];
    const float* pool_b2     = (const float*)d_in[23];

    float* out = (float*)d_out;
    float* zf = out;
    float* zs = out + (size_t)B_ * LF_ * 1024;

    float* S0 = nullptr;
    cudaGetSymbolAddress((void**)&S0, g_scratch);
    u16* xf    = (u16*)(S0 + O_XF);
    u16* xs    = (u16*)(S0 + O_XS);
    u16* wfs   = (u16*)(S0 + O_WFS);
    u16* wfc   = (u16*)(S0 + O_WFC);
    u16* wss   = (u16*)(S0 + O_WSS);
    u16* wsc   = (u16*)(S0 + O_WSC);
    u16* wof   = (u16*)(S0 + O_WOF);
    u16* woc   = (u16*)(S0 + O_WOC);
    u16* wos   = (u16*)(S0 + O_WOS);
    u16* wosc  = (u16*)(S0 + O_WOSC);
    u16* wl    = (u16*)(S0 + O_WL);
    u16* wp1   = (u16*)(S0 + O_WP1);
    u16* wp2   = (u16*)(S0 + O_WP2);
    u16* y     = (u16*)(S0 + O_Y);
    u16* qkv_f = (u16*)(S0 + O_QKV_F);
    u16* q_fc  = (u16*)(S0 + O_Q_FC);
    u16* kv_fc = (u16*)(S0 + O_KV_FC);
    u16* o1    = (u16*)(S0 + O_O1);
    u16* o2    = (u16*)(S0 + O_O2);
    u16* h1    = (u16*)(S0 + O_H1);
    u16* s     = (u16*)(S0 + O_S);
    u16* qkv_s = (u16*)(S0 + O_QKV_S);
    u16* q_sc  = (u16*)(S0 + O_Q_SC);
    u16* kv_sc = (u16*)(S0 + O_KV_SC);
    u16* o3    = (u16*)(S0 + O_O3);
    u16* o4    = (u16*)(S0 + O_O4);

    const int P_XF   = 4194304, P_XS  = 1048576;
    const int P_WQKV = 786432,  P_WO  = 262144, P_WL = 524288;
    const int P_WP1  = 8388608, P_WP2 = 1048576;

    cudaFuncSetAttribute(gemm_batch_kernel,
                         cudaFuncAttributeMaxDynamicSharedMemorySize, SMEM_GEMM);
    cudaFuncSetAttribute(attn_batch_kernel,
                         cudaFuncAttributeMaxDynamicSharedMemorySize, SMEM_ATTN);

    // ---- L0: convert inputs + weights to fp16 ----
    {
        SplitBatch sb; int cur = 0;
        sb.d[0]  = mk_split(x_fast,      xf,   P_XF,   0, cur);
        sb.d[1]  = mk_split(x_slow,      xs,   P_XS,   0, cur);
        sb.d[2]  = mk_split(fself_wqkv,  wfs,  P_WQKV, 0, cur);
        sb.d[3]  = mk_split(fcross_wqkv, wfc,  P_WQKV, 0, cur);
        sb.d[4]  = mk_split(sself_wqkv,  wss,  P_WQKV, 0, cur);
        sb.d[5]  = mk_split(scross_wqkv, wsc,  P_WQKV, 0, cur);
        sb.d[6]  = mk_split(fself_wo,    wof,  P_WO,   0, cur);
        sb.d[7]  = mk_split(fcross_wo,   woc,  P_WO,   0, cur);
        sb.d[8]  = mk_split(sself_wo,    wos,  P_WO,   0, cur);
        sb.d[9]  = mk_split(scross_wo,   wosc, P_WO,   0, cur);
        sb.d[10] = mk_split(lift_w,      wl,   P_WL,   0, cur);
        sb.d[11] = mk_split(pool_w1,     wp1,  P_WP1,  0, cur);
        sb.d[12] = mk_split(pool_w2,     wp2,  P_WP2,  0, cur);
        sb.n = 13;
        split_kernel<<<cur, 256>>>(sb);
    }
    // ---- L1: input-only GEMMs ----
    {
        GemmBatch gb; int cur = 0;
        gb.d[0] = mk_gemm(xf, 1024, 0,   wfs, 1536, 0, fself_bqkv,  qkv_f, 1536, 0, 4096, 1536, 512,  0, 2, 512, 0, 0, cur);
        gb.d[1] = mk_gemm(xf, 4096, 0,   wp1, 2048, 0, pool_b1,     h1,    2048, 0, 1024, POOLH, 4096, 0, 3, 0,   0, 0, cur);
        gb.d[2] = mk_gemm(xf, 1024, 512, wfc, 1536, 0, fcross_bqkv, q_fc,  512,  0, 4096, 512,  512,  0, 2, 512, 0, 0, cur);
        gb.d[3] = mk_gemm(xs, 1024, 0,   wl,  512,  0, lift_b,      y,     512,  0, 1024, 512,  1024, 0, 2, 0,   0, 0, cur);
        gb.d[4] = mk_gemm(xs, 1024, 0,   wss, 1536, 0, sself_bqkv,  qkv_s, 1536, 0, 1024, 1536, 512,  0, 2, 512, 0, 0, cur);
        gb.d[5] = mk_gemm(xs, 1024, 512, wsc, 1536, 0, scross_bqkv, q_sc,  512,  0, 1024, 512,  512,  0, 2, 512, 0, 0, cur);
        gb.n = 6;
        gemm_batch_kernel<<<cur, 256, SMEM_GEMM>>>(gb);
    }
    // ---- L2: kv_fc (needs y) + pool2 (needs h1) ----
    {
        GemmBatch gb; int cur = 0;
        gb.d[0] = mk_gemm(y,  512,  0, wfc, 1536, 512, fcross_bqkv + 512, kv_fc, 1024, 0, 1024, 1024, 512,  0, 2, 0, 0, 0, cur);
        gb.d[1] = mk_gemm(h1, 2048, 0, wp2, 512,  0,   pool_b2,           s,     512,  0, 1024, 512,  2048, 0, 2, 0, 0, 0, cur);
        gb.n = 2;
        gemm_batch_kernel<<<cur, 256, SMEM_GEMM>>>(gb);
    }
    // ---- L3: kv_sc on shifted s ----
    {
        GemmBatch gb; int cur = 0;
        gb.d[0] = mk_gemm(s, 512, 0, wsc, 1536, 512, scross_bqkv + 512, kv_sc, 1024, 0, 1024, 1024, 512, 1, 2, 0, 0, 0, cur);
        gb.n = 1;
        gemm_batch_kernel<<<cur, 256, SMEM_GEMM>>>(gb);
    }
    // ---- L4: all four attentions ----
    {
        AttnBatch ab; int cur = 0;
        ab.d[0] = mk_attn(qkv_f, 1536, 0, qkv_f, 1536, 512, qkv_f, 1536, 1024, o1, 512, LF_, LF_, cur);
        ab.d[1] = mk_attn(q_fc,  512,  0, kv_fc, 1024, 0,   kv_fc, 1024, 512,  o2, 512, LF_, TS_, cur);
        ab.d[2] = mk_attn(qkv_s, 1536, 0, qkv_s, 1536, 512, qkv_s, 1536, 1024, o3, 512, TS_, TS_, cur);
        ab.d[3] = mk_attn(q_sc,  512,  0, kv_sc, 1024, 0,   kv_sc, 1024, 512,  o4, 512, TS_, TS_, cur);
        ab.n = 4;
        attn_batch_kernel<<<cur, 128, SMEM_ATTN>>>(ab);
    }
    // ---- L5: all four out-projections ----
    {
        GemmBatch gb; int cur = 0;
        gb.d[0] = mk_gemm(o1, 512, 0, wof,  512, 0, fself_bo,  zf, 1024, 0,   4096, 512, 512, 0, 0, 0, 0, 0, cur);
        gb.d[1] = mk_gemm(o2, 512, 0, woc,  512, 0, fcross_bo, zf, 1024, 512, 4096, 512, 512, 0, 0, 0, 0, 0, cur);
        gb.d[2] = mk_gemm(o3, 512, 0, wos,  512, 0, sself_bo,  zs, 1024, 0,   1024, 512, 512, 0, 0, 0, 0, 0, cur);
        gb.d[3] = mk_gemm(o4, 512, 0, wosc, 512, 0, scross_bo, zs, 1024, 512, 1024, 512, 512, 0, 0, 0, 0, 0, cur);
        gb.n = 4;
        gemm_batch_kernel<<<cur, 256, SMEM_GEMM>>>(gb);
    }
}

// round 17
// speedup vs baseline: 1.9309x; 1.0697x over previous
#include <cuda_runtime.h>
#include <cuda_fp16.h>
#include <math.h>

#define B_    2
#define LF_   2048
#define TS_   512
#define D2_   512
#define H_    8
#define HD_   64
#define POOLH 2048

typedef unsigned long long u64;
typedef unsigned int u32;
typedef unsigned short u16;

// ---------------------------------------------------------------------------
// fp16 helpers
// ---------------------------------------------------------------------------
__device__ __forceinline__ void split_f16(float x, float &hi, float &lo) {
    hi = __half2float(__float2half_rn(x));
    lo = x - hi;
}
__device__ __forceinline__ u32 pack_f16(float a, float b) {
    __half2 t = __floats2half2_rn(a, b);
    return *(u32*)&t;
}
__device__ __forceinline__ u64 pack4_f16(float a, float b, float c, float d) {
    return (u64)pack_f16(a, b) | ((u64)pack_f16(c, d) << 32);
}
__device__ __forceinline__ float exp2a(float x) {
    float r;
    asm("ex2.approx.f32 %0, %1;" : "=f"(r) : "f"(x));
    return r;
}
__device__ __forceinline__ void mma_f16(float c[4], u32 a0, u32 a1, u32 a2, u32 a3,
                                        u32 b0, u32 b1) {
    asm volatile(
        "mma.sync.aligned.m16n8k16.row.col.f32.f16.f16.f32 "
        "{%0,%1,%2,%3}, {%4,%5,%6,%7}, {%8,%9}, {%0,%1,%2,%3};\n"
        : "+f"(c[0]), "+f"(c[1]), "+f"(c[2]), "+f"(c[3])
        : "r"(a0), "r"(a1), "r"(a2), "r"(a3), "r"(b0), "r"(b1));
}
__device__ __forceinline__ u32 smaddr(const void* p) {
    return (u32)__cvta_generic_to_shared(p);
}
__device__ __forceinline__ void ldsm4(u32 r[4], u32 addr) {
    asm volatile("ldmatrix.sync.aligned.m8n8.x4.shared.b16 {%0,%1,%2,%3}, [%4];"
                 : "=r"(r[0]), "=r"(r[1]), "=r"(r[2]), "=r"(r[3]) : "r"(addr));
}
__device__ __forceinline__ void ldsm4t(u32 r[4], u32 addr) {
    asm volatile("ldmatrix.sync.aligned.m8n8.x4.trans.shared.b16 {%0,%1,%2,%3}, [%4];"
                 : "=r"(r[0]), "=r"(r[1]), "=r"(r[2]), "=r"(r[3]) : "r"(addr));
}
__device__ __forceinline__ void cp_async16(u32 dst, const void* src) {
    asm volatile("cp.async.cg.shared.global [%0], [%1], 16;" :: "r"(dst), "l"(src));
}
__device__ __forceinline__ void cp_async16z(u32 dst, const void* src, u32 sz) {
    asm volatile("cp.async.cg.shared.global [%0], [%1], 16, %2;"
                 :: "r"(dst), "l"(src), "r"(sz));
}
#define CP_COMMIT() asm volatile("cp.async.commit_group;")
#define CP_WAIT(n)  asm volatile("cp.async.wait_group %0;" :: "n"(n))

// XOR-swizzled smem addressing: 64 u16 per row (128B), chunk ^= row&7.
__device__ __forceinline__ u16* swp(u16* base, int row, int col) {
    return base + row * 64 + ((((col >> 3) ^ (row & 7)) << 3) | (col & 7));
}
__device__ __forceinline__ const u16* swp(const u16* base, int row, int col) {
    return base + row * 64 + ((((col >> 3) ^ (row & 7)) << 3) | (col & 7));
}

// combined softmax scale: 1/sqrt(64) * log2(e)
#define QSCALE 0.18033688011112042f

// ---------------------------------------------------------------------------
// Scratch layout (float units).
// ---------------------------------------------------------------------------
static const size_t O_XF    = 0;
static const size_t O_XS    = 4194304;
static const size_t O_WFS   = 5242880;
static const size_t O_WFC   = 6029312;
static const size_t O_WSS   = 6815744;
static const size_t O_WSC   = 7602176;
static const size_t O_WOF   = 8388608;
static const size_t O_WOC   = 8650752;
static const size_t O_WOS   = 8912896;
static const size_t O_WOSC  = 9175040;
static const size_t O_WL    = 9437184;
static const size_t O_WP1   = 9961472;
static const size_t O_WP2   = 18350080;
static const size_t O_Y     = 19398656;
static const size_t O_QKV_F = 19922944;
static const size_t O_Q_FC  = 26214400;
static const size_t O_KV_FC = 28311552;
static const size_t O_O1    = 29360128;
static const size_t O_O2    = 31457280;
static const size_t O_H1    = 33554432;
static const size_t O_S     = 35651584;
static const size_t O_QKV_S = 36175872;
static const size_t O_Q_SC  = 37748736;
static const size_t O_KV_SC = 38273024;
static const size_t O_O3    = 39321600;
static const size_t O_O4    = 39845888;
static const size_t SCRATCH_FLOATS = 40370176;

__device__ float g_scratch[SCRATCH_FLOATS];

// ---------------------------------------------------------------------------
// Batched convert pass: fp32 -> fp16 plane
// ---------------------------------------------------------------------------
#define SD_MAX 14
struct SplitDesc { const float* src; u16* dst; int nelem; int blk0; int lo; };
struct SplitBatch { SplitDesc d[SD_MAX]; int n; };

__global__ __launch_bounds__(256) void split_kernel(SplitBatch b)
{
    int pi = 0;
    #pragma unroll
    for (int i = 1; i < SD_MAX; i++)
        if (i < b.n && (int)blockIdx.x >= b.d[i].blk0) pi = i;
    const SplitDesc D = b.d[pi];
    const int idx = ((blockIdx.x - D.blk0) * 256 + threadIdx.x) * 4;
    float4 v = *(const float4*)(D.src + idx);
    float h0, l0, h1, l1, h2, l2, h3, l3;
    split_f16(v.x, h0, l0); split_f16(v.y, h1, l1);
    split_f16(v.z, h2, l2); split_f16(v.w, h3, l3);
    *(u64*)&D.dst[idx] = pack4_f16(h0, h1, h2, h3);
    if (D.lo)
        *(u64*)&D.dst[idx + D.nelem] = pack4_f16(l0, l1, l2, l3);
}

// ---------------------------------------------------------------------------
// Batched GEMM: A fp16, W fp16, fp32 accumulate. K-chunk 64 (A smem fully
// used; barriers per GEMM halved vs K-chunk 32). Block 128x64, 256 threads
// (8 warps 4x2). 3-stage cp.async pipeline, wait(1), one sync per chunk.
// outmode 0: fp32. 2: fp16 (cols < qcols scaled QSCALE). 3: GELU then fp16.
// ---------------------------------------------------------------------------
#define GD_MAX 6
struct GemmDesc {
    const u16 *A, *W;
    const float *bias;
    void *C;
    int lda, aoff, ldw, woff, ldc, coff, K;
    int ashift, nbx, blk0, outmode, qcols, oplane, olo;
};
struct GemmBatch { GemmDesc d[GD_MAX]; int n; };

#define GT_A (128 * 64)               // A: 128 rows x 64 u16 (k0..63)
#define GT_W (64 * 64)                // W: 64 k-rows x 64 n
#define GT_STAGE (GT_A + GT_W)        // 12288 u16 = 24576 B
#define SMEM_GEMM (3 * GT_STAGE * 2)  // 73728 B

__global__ __launch_bounds__(256) void gemm_batch_kernel(GemmBatch batch)
{
    extern __shared__ __align__(16) u16 smg[];

    int pi = 0;
    #pragma unroll
    for (int i = 1; i < GD_MAX; i++)
        if (i < batch.n && (int)blockIdx.x >= batch.d[i].blk0) pi = i;
    const GemmDesc D = batch.d[pi];
    const int lb = blockIdx.x - D.blk0;
    const int m0 = (lb / D.nbx) * 128;
    const int n0 = (lb % D.nbx) * 64;

    const int tid  = threadIdx.x;
    const int lane = tid & 31;
    const int warp = tid >> 5;
    const int warp_m = warp >> 1;
    const int warp_n = warp & 1;
    const int g  = lane >> 2;
    const int tg = lane & 3;

    const int l15 = lane & 15;
    const int l7  = lane & 7;
    const int ka8 = (lane >> 4) * 8;
    const int wk8 = ((lane >> 3) & 1) * 8;
    const int wn8 = (lane >> 4) * 8;

    float acc[2][4][4];
    #pragma unroll
    for (int mt = 0; mt < 2; mt++)
        #pragma unroll
        for (int nt = 0; nt < 4; nt++)
            #pragma unroll
            for (int r = 0; r < 4; r++) acc[mt][nt][r] = 0.f;

    auto fill = [&](int k0, int st) {
        u16* sb = smg + st * GT_STAGE;
        // A tile: 128 rows x 8 chunks (k0..k0+63)
        #pragma unroll
        for (int i = 0; i < 4; i++) {
            const int idx = tid + i * 256;      // 0..1023
            const int row = idx >> 3, ch = idx & 7;
            const int kc = ch * 8;
            int mg = m0 + row;
            u32 sz = 16;
            if (D.ashift) {
                if ((mg & 511) == 0) { sz = 0; }
                else mg -= 1;
            }
            const u16* src = D.A + (size_t)(sz ? mg : 0) * D.lda + D.aoff + k0 + kc;
            cp_async16z(smaddr(swp(sb, row, kc)), src, sz);
        }
        // W tile: 64 k-rows x 8 chunks
        u16* wb = sb + GT_A;
        #pragma unroll
        for (int i = 0; i < 2; i++) {
            const int idx = tid + i * 256;      // 0..511
            const int row = idx >> 3, ch = idx & 7;
            const u16* src = D.W + (size_t)(k0 + row) * D.ldw + D.woff + n0 + ch * 8;
            cp_async16(smaddr(swp(wb, row, ch * 8)), src);
        }
    };

    auto do_mma = [&](int st) {
        const u16* As = smg + st * GT_STAGE;
        const u16* Ws = As + GT_A;
        #pragma unroll
        for (int kk = 0; kk < 4; kk++) {
            u32 afr[2][4];
            #pragma unroll
            for (int mt = 0; mt < 2; mt++)
                ldsm4(afr[mt],
                      smaddr(swp(As, warp_m * 32 + mt * 16 + l15, kk * 16 + ka8)));
            u32 bfr[4][2];
            #pragma unroll
            for (int ntp = 0; ntp < 2; ntp++) {
                u32 t[4];
                ldsm4t(t, smaddr(swp(Ws, kk * 16 + l7 + wk8,
                                     warp_n * 32 + ntp * 16 + wn8)));
                bfr[2 * ntp][0]     = t[0]; bfr[2 * ntp][1]     = t[1];
                bfr[2 * ntp + 1][0] = t[2]; bfr[2 * ntp + 1][1] = t[3];
            }
            #pragma unroll
            for (int mt = 0; mt < 2; mt++)
                #pragma unroll
                for (int nt = 0; nt < 4; nt++)
                    mma_f16(acc[mt][nt], afr[mt][0], afr[mt][1], afr[mt][2], afr[mt][3],
                            bfr[nt][0], bfr[nt][1]);
        }
    };

    const int nk = D.K >> 6;   // all K divisible by 64
    fill(0, 0);
    CP_COMMIT();
    if (nk > 1) fill(64, 1);
    CP_COMMIT();

    for (int ki = 0; ki < nk; ki++) {
        CP_WAIT(1);
        __syncthreads();
        if (ki + 2 < nk) fill((ki + 2) * 64, (ki + 2) % 3);
        CP_COMMIT();
        do_mma(ki % 3);
    }

    if (D.outmode == 0) {
        float* C = (float*)D.C;
        #pragma unroll
        for (int mt = 0; mt < 2; mt++) {
            #pragma unroll
            for (int nt = 0; nt < 4; nt++) {
                const int m = m0 + warp_m * 32 + mt * 16 + g;
                const int n = n0 + warp_n * 32 + nt * 8 + tg * 2;
                const float bb0 = D.bias[n], bb1 = D.bias[n + 1];
                *(float2*)(C + (size_t)m * D.ldc + D.coff + n) =
                    make_float2(acc[mt][nt][0] + bb0, acc[mt][nt][1] + bb1);
                *(float2*)(C + (size_t)(m + 8) * D.ldc + D.coff + n) =
                    make_float2(acc[mt][nt][2] + bb0, acc[mt][nt][3] + bb1);
            }
        }
    } else {
        u16* Ch = (u16*)D.C;
        const float sc = (D.outmode == 2 && n0 < D.qcols) ? QSCALE : 1.0f;
        #pragma unroll
        for (int mt = 0; mt < 2; mt++) {
            #pragma unroll
            for (int nt = 0; nt < 4; nt++) {
                const int m = m0 + warp_m * 32 + mt * 16 + g;
                const int n = n0 + warp_n * 32 + nt * 8 + tg * 2;
                const float bb0 = D.bias[n], bb1 = D.bias[n + 1];
                float v[4] = {(acc[mt][nt][0] + bb0) * sc, (acc[mt][nt][1] + bb1) * sc,
                              (acc[mt][nt][2] + bb0) * sc, (acc[mt][nt][3] + bb1) * sc};
                if (D.outmode == 3) {
                    #pragma unroll
                    for (int r = 0; r < 4; r++) {
                        float x = v[r];
                        float u = 0.7978845608028654f * (x + 0.044715f * x * x * x);
                        v[r] = 0.5f * x * (1.0f + tanhf(u));
                    }
                }
                float h0, l0, h1, l1, h2, l2, h3, l3;
                split_f16(v[0], h0, l0); split_f16(v[1], h1, l1);
                split_f16(v[2], h2, l2); split_f16(v[3], h3, l3);
                const size_t o0 = (size_t)m * D.ldc + D.coff + n;
                const size_t o1 = (size_t)(m + 8) * D.ldc + D.coff + n;
                *(u32*)&Ch[o0] = pack_f16(h0, h1);
                *(u32*)&Ch[o1] = pack_f16(h2, h3);
                if (D.olo) {
                    *(u32*)&Ch[o0 + D.oplane] = pack_f16(l0, l1);
                    *(u32*)&Ch[o1 + D.oplane] = pack_f16(l2, l3);
                }
            }
        }
    }
}

// ---------------------------------------------------------------------------
// Batched flash attention (R15 body, verbatim): plain fp16 Q/K/V/P, fp32
// softmax+accumulate. 3-stage cp.async pipeline, one sync per tile.
// 64 q-rows/CTA, 4 warps, 128 threads.
// ---------------------------------------------------------------------------
#define AD_MAX 4
struct AttnDesc {
    const u16 *Q, *K, *V;
    u16 *O;
    int ldq, qoff, ldk, koff, ldv, voff;
    int ldo, Tq, Tk, nbx, blk0;
};
struct AttnBatch { AttnDesc d[AD_MAX]; int n; };

#define STAGE_U16 (128 * 64)            // K (64 rows) + V (64 rows)
#define SMEM_ATTN (3 * STAGE_U16 * 2)   // 49152 bytes

__global__ __launch_bounds__(128) void attn_batch_kernel(AttnBatch batch)
{
    extern __shared__ __align__(16) u16 smu[];

    int pi = 0;
    #pragma unroll
    for (int i = 1; i < AD_MAX; i++)
        if (i < batch.n && (int)blockIdx.x >= batch.d[i].blk0) pi = i;
    const AttnDesc D = batch.d[pi];
    const int lb = blockIdx.x - D.blk0;
    const int qt = lb % D.nbx;
    const int h  = (lb / D.nbx) % H_;
    const int b  = lb / (D.nbx * H_);

    const int tid  = threadIdx.x;
    const int lane = tid & 31;
    const int warp = tid >> 5;
    const int g  = lane >> 2;
    const int tg = lane & 3;
    const int mrow = warp * 16;

    const int l15 = lane & 15;
    const int l7  = lane & 7;
    const int qc8 = (lane >> 4) * 8;
    const int kk8 = (lane >> 4) * 8;
    const int kd8 = ((lane >> 3) & 1) * 8;
    const int vk8 = ((lane >> 3) & 1) * 8;
    const int vd8 = (lane >> 4) * 8;

    const u16* Qb = D.Q + (size_t)(b * D.Tq + qt * 64) * D.ldq + D.qoff + h * HD_;
    const u16* Kb = D.K + (size_t)(b * D.Tk) * D.ldk + D.koff + h * HD_;
    const u16* Vb = D.V + (size_t)(b * D.Tk) * D.ldv + D.voff + h * HD_;

    auto fill = [&](int kt, int st) {
        u16* sb = smu + st * STAGE_U16;
        #pragma unroll
        for (int i = 0; i < 8; i++) {
            const int plane = i >> 2;
            const int idx = tid + (i & 3) * 128;
            const int r = idx >> 3;
            const int c = (idx & 7) * 8;
            const u16* src = (plane == 0)
                ? Kb + (size_t)(kt + r) * D.ldk + c
                : Vb + (size_t)(kt + r) * D.ldv + c;
            cp_async16(smaddr(swp(sb, plane * 64 + r, c)), src);
        }
    };

    const int ntile = D.Tk >> 6;

    {
        u16* qs = smu + 2 * STAGE_U16;
        #pragma unroll
        for (int i = 0; i < 4; i++) {
            const int idx = tid + i * 128;
            const int r = idx >> 3;
            const int c = (idx & 7) * 8;
            cp_async16(smaddr(swp(qs, r, c)), Qb + (size_t)r * D.ldq + c);
        }
        CP_COMMIT();
    }
    fill(0, 0);
    CP_COMMIT();
    fill(64, 1);
    CP_COMMIT();
    CP_WAIT(2);
    __syncthreads();

    u32 qh[4][4];
    {
        const u16* qs = smu + 2 * STAGE_U16;
        #pragma unroll
        for (int kc = 0; kc < 4; kc++)
            ldsm4(qh[kc], smaddr(swp(qs, mrow + l15, kc * 16 + qc8)));
    }

    float acc[8][4];
    #pragma unroll
    for (int nt = 0; nt < 8; nt++)
        #pragma unroll
        for (int r = 0; r < 4; r++) acc[nt][r] = 0.f;
    float mx0 = -1e30f, mx1 = -1e30f, lsum0 = 0.f, lsum1 = 0.f;

    for (int it = 0; it < ntile; it++) {
        CP_WAIT(1);
        __syncthreads();
        if (it + 2 < ntile) fill((it + 2) * 64, (it + 2) % 3);
        CP_COMMIT();

        const u16* sb = smu + (it % 3) * STAGE_U16;

        float s[8][4];
        #pragma unroll
        for (int nt = 0; nt < 8; nt++)
            #pragma unroll
            for (int r = 0; r < 4; r++) s[nt][r] = 0.f;

        #pragma unroll
        for (int kc = 0; kc < 4; kc++) {
            #pragma unroll
            for (int ntp = 0; ntp < 4; ntp++) {
                u32 kh[4];
                ldsm4(kh, smaddr(swp(sb, ntp * 16 + l7 + kk8, kc * 16 + kd8)));
                mma_f16(s[2 * ntp],     qh[kc][0], qh[kc][1], qh[kc][2], qh[kc][3], kh[0], kh[1]);
                mma_f16(s[2 * ntp + 1], qh[kc][0], qh[kc][1], qh[kc][2], qh[kc][3], kh[2], kh[3]);
            }
        }

        float rm0 = -1e30f, rm1 = -1e30f;
        #pragma unroll
        for (int nt = 0; nt < 8; nt++) {
            rm0 = fmaxf(rm0, fmaxf(s[nt][0], s[nt][1]));
            rm1 = fmaxf(rm1, fmaxf(s[nt][2], s[nt][3]));
        }
        rm0 = fmaxf(rm0, __shfl_xor_sync(0xffffffffu, rm0, 1));
        rm0 = fmaxf(rm0, __shfl_xor_sync(0xffffffffu, rm0, 2));
        rm1 = fmaxf(rm1, __shfl_xor_sync(0xffffffffu, rm1, 1));
        rm1 = fmaxf(rm1, __shfl_xor_sync(0xffffffffu, rm1, 2));

        const float mn0 = fmaxf(mx0, rm0);
        const float mn1 = fmaxf(mx1, rm1);
        const float corr0 = exp2a(mx0 - mn0);
        const float corr1 = exp2a(mx1 - mn1);
        float rs0 = 0.f, rs1 = 0.f;
        #pragma unroll
        for (int nt = 0; nt < 8; nt++) {
            s[nt][0] = exp2a(s[nt][0] - mn0); rs0 += s[nt][0];
            s[nt][1] = exp2a(s[nt][1] - mn0); rs0 += s[nt][1];
            s[nt][2] = exp2a(s[nt][2] - mn1); rs1 += s[nt][2];
            s[nt][3] = exp2a(s[nt][3] - mn1); rs1 += s[nt][3];
        }
        rs0 += __shfl_xor_sync(0xffffffffu, rs0, 1);
        rs0 += __shfl_xor_sync(0xffffffffu, rs0, 2);
        rs1 += __shfl_xor_sync(0xffffffffu, rs1, 1);
        rs1 += __shfl_xor_sync(0xffffffffu, rs1, 2);
        lsum0 = lsum0 * corr0 + rs0; mx0 = mn0;
        lsum1 = lsum1 * corr1 + rs1; mx1 = mn1;
        #pragma unroll
        for (int nt = 0; nt < 8; nt++) {
            acc[nt][0] *= corr0; acc[nt][1] *= corr0;
            acc[nt][2] *= corr1; acc[nt][3] *= corr1;
        }

        #pragma unroll
        for (int kc = 0; kc < 4; kc++) {
            const int j0 = 2 * kc, j1 = 2 * kc + 1;
            u32 pa[4];
            pa[0] = pack_f16(s[j0][0], s[j0][1]);
            pa[1] = pack_f16(s[j0][2], s[j0][3]);
            pa[2] = pack_f16(s[j1][0], s[j1][1]);
            pa[3] = pack_f16(s[j1][2], s[j1][3]);

            #pragma unroll
            for (int ntp = 0; ntp < 4; ntp++) {
                u32 vh[4];
                ldsm4t(vh, smaddr(swp(sb, 64 + kc * 16 + l7 + vk8, ntp * 16 + vd8)));
                mma_f16(acc[2 * ntp],     pa[0], pa[1], pa[2], pa[3], vh[0], vh[1]);
                mma_f16(acc[2 * ntp + 1], pa[0], pa[1], pa[2], pa[3], vh[2], vh[3]);
            }
        }
    }

    const float inv0 = 1.0f / lsum0;
    const float inv1 = 1.0f / lsum1;
    u16* Ob = D.O + (size_t)(b * D.Tq + qt * 64 + mrow) * D.ldo + h * HD_;
    #pragma unroll
    for (int nt = 0; nt < 8; nt++) {
        const int col = nt * 8 + 2 * tg;
        *(u32*)&Ob[(size_t)g * D.ldo + col] =
            pack_f16(acc[nt][0] * inv0, acc[nt][1] * inv0);
        *(u32*)&Ob[(size_t)(g + 8) * D.ldo + col] =
            pack_f16(acc[nt][2] * inv1, acc[nt][3] * inv1);
    }
}

// ---------------------------------------------------------------------------
// Host orchestration: convert pass + 5 launches
// ---------------------------------------------------------------------------
static inline GemmDesc mk_gemm(const u16* A, int lda, int aoff,
                               const u16* W, int ldw, int woff,
                               const float* bias, void* C, int ldc, int coff,
                               int M, int N, int K, int ashift,
                               int outmode, int qcols, int oplane, int olo,
                               int& blk_cursor)
{
    GemmDesc d;
    d.A = A; d.W = W; d.bias = bias; d.C = C;
    d.lda = lda; d.aoff = aoff;
    d.ldw = ldw; d.woff = woff;
    d.ldc = ldc; d.coff = coff; d.K = K; d.ashift = ashift;
    d.outmode = outmode; d.qcols = qcols; d.oplane = oplane; d.olo = olo;
    d.nbx = N / 64; d.blk0 = blk_cursor;
    blk_cursor += (N / 64) * (M / 128);
    return d;
}

static inline AttnDesc mk_attn(const u16* Q, int ldq, int qoff,
                               const u16* K, int ldk, int koff,
                               const u16* V, int ldv, int voff,
                               u16* O, int ldo, int Tq, int Tk, int& blk_cursor)
{
    AttnDesc d;
    d.Q = Q; d.K = K; d.V = V; d.O = O;
    d.ldq = ldq; d.qoff = qoff;
    d.ldk = ldk; d.koff = koff;
    d.ldv = ldv; d.voff = voff;
    d.ldo = ldo;
    d.Tq = Tq; d.Tk = Tk; d.nbx = Tq / 64; d.blk0 = blk_cursor;
    blk_cursor += (Tq / 64) * H_ * B_;
    return d;
}

static inline SplitDesc mk_split(const float* src, u16* dst, int nelem, int lo,
                                 int& blk_cursor)
{
    SplitDesc d;
    d.src = src; d.dst = dst; d.nelem = nelem; d.lo = lo; d.blk0 = blk_cursor;
    blk_cursor += nelem / 1024;
    return d;
}

extern "C" void kernel_launch(void* const* d_in, const int* in_sizes, int n_in,
                              void* d_out, int out_size)
{
    (void)in_sizes; (void)n_in; (void)out_size;

    const float* x_fast      = (const float*)d_in[0];
    const float* x_slow      = (const float*)d_in[1];
    const float* fself_wqkv  = (const float*)d_in[2];
    const float* fself_bqkv  = (const float*)d_in[3];
    const float* fself_wo    = (const float*)d_in[4];
    const float* fself_bo    = (const float*)d_in[5];
    const float* fcross_wqkv = (const float*)d_in[6];
    const float* fcross_bqkv = (const float*)d_in[7];
    const float* fcross_wo   = (const float*)d_in[8];
    const float* fcross_bo   = (const float*)d_in[9];
    const float* sself_wqkv  = (const float*)d_in[10];
    const float* sself_bqkv  = (const float*)d_in[11];
    const float* sself_wo    = (const float*)d_in[12];
    const float* sself_bo    = (const float*)d_in[13];
    const float* scross_wqkv = (const float*)d_in[14];
    const float* scross_bqkv = (const float*)d_in[15];
    const float* scross_wo   = (const float*)d_in[16];
    const float* scross_bo   = (const float*)d_in[17];
    const float* lift_w      = (const float*)d_in[18];
    const float* lift_b      = (const float*)d_in[19];
    const float* pool_w1     = (const float*)d_in[20];
    const float* pool_b1     = (const float*)d_in[21];
    const float* pool_w2     = (const float*)d_in[22];
    const float* pool_b2     = (const float*)d_in[23];

    float* out = (float*)d_out;
    float* zf = out;
    float* zs = out + (size_t)B_ * LF_ * 1024;

    float* S0 = nullptr;
    cudaGetSymbolAddress((void**)&S0, g_scratch);
    u16* xf    = (u16*)(S0 + O_XF);
    u16* xs    = (u16*)(S0 + O_XS);
    u16* wfs   = (u16*)(S0 + O_WFS);
    u16* wfc   = (u16*)(S0 + O_WFC);
    u16* wss   = (u16*)(S0 + O_WSS);
    u16* wsc   = (u16*)(S0 + O_WSC);
    u16* wof   = (u16*)(S0 + O_WOF);
    u16* woc   = (u16*)(S0 + O_WOC);
    u16* wos   = (u16*)(S0 + O_WOS);
    u16* wosc  = (u16*)(S0 + O_WOSC);
    u16* wl    = (u16*)(S0 + O_WL);
    u16* wp1   = (u16*)(S0 + O_WP1);
    u16* wp2   = (u16*)(S0 + O_WP2);
    u16* y     = (u16*)(S0 + O_Y);
    u16* qkv_f = (u16*)(S0 + O_QKV_F);
    u16* q_fc  = (u16*)(S0 + O_Q_FC);
    u16* kv_fc = (u16*)(S0 + O_KV_FC);
    u16* o1    = (u16*)(S0 + O_O1);
    u16* o2    = (u16*)(S0 + O_O2);
    u16* h1    = (u16*)(S0 + O_H1);
    u16* s     = (u16*)(S0 + O_S);
    u16* qkv_s = (u16*)(S0 + O_QKV_S);
    u16* q_sc  = (u16*)(S0 + O_Q_SC);
    u16* kv_sc = (u16*)(S0 + O_KV_SC);
    u16* o3    = (u16*)(S0 + O_O3);
    u16* o4    = (u16*)(S0 + O_O4);

    const int P_XF   = 4194304, P_XS  = 1048576;
    const int P_WQKV = 786432,  P_WO  = 262144, P_WL = 524288;
    const int P_WP1  = 8388608, P_WP2 = 1048576;

    cudaFuncSetAttribute(gemm_batch_kernel,
                         cudaFuncAttributeMaxDynamicSharedMemorySize, SMEM_GEMM);
    cudaFuncSetAttribute(attn_batch_kernel,
                         cudaFuncAttributeMaxDynamicSharedMemorySize, SMEM_ATTN);

    // ---- L0: convert inputs + weights to fp16 ----
    {
        SplitBatch sb; int cur = 0;
        sb.d[0]  = mk_split(x_fast,      xf,   P_XF,   0, cur);
        sb.d[1]  = mk_split(x_slow,      xs,   P_XS,   0, cur);
        sb.d[2]  = mk_split(fself_wqkv,  wfs,  P_WQKV, 0, cur);
        sb.d[3]  = mk_split(fcross_wqkv, wfc,  P_WQKV, 0, cur);
        sb.d[4]  = mk_split(sself_wqkv,  wss,  P_WQKV, 0, cur);
        sb.d[5]  = mk_split(scross_wqkv, wsc,  P_WQKV, 0, cur);
        sb.d[6]  = mk_split(fself_wo,    wof,  P_WO,   0, cur);
        sb.d[7]  = mk_split(fcross_wo,   woc,  P_WO,   0, cur);
        sb.d[8]  = mk_split(sself_wo,    wos,  P_WO,   0, cur);
        sb.d[9]  = mk_split(scross_wo,   wosc, P_WO,   0, cur);
        sb.d[10] = mk_split(lift_w,      wl,   P_WL,   0, cur);
        sb.d[11] = mk_split(pool_w1,     wp1,  P_WP1,  0, cur);
        sb.d[12] = mk_split(pool_w2,     wp2,  P_WP2,  0, cur);
        sb.n = 13;
        split_kernel<<<cur, 256>>>(sb);
    }
    // ---- L1: input-only GEMMs ----
    {
        GemmBatch gb; int cur = 0;
        gb.d[0] = mk_gemm(xf, 1024, 0,   wfs, 1536, 0, fself_bqkv,  qkv_f, 1536, 0, 4096, 1536, 512,  0, 2, 512, 0, 0, cur);
        gb.d[1] = mk_gemm(xf, 4096, 0,   wp1, 2048, 0, pool_b1,     h1,    2048, 0, 1024, POOLH, 4096, 0, 3, 0,   0, 0, cur);
        gb.d[2] = mk_gemm(xf, 1024, 512, wfc, 1536, 0, fcross_bqkv, q_fc,  512,  0, 4096, 512,  512,  0, 2, 512, 0, 0, cur);
        gb.d[3] = mk_gemm(xs, 1024, 0,   wl,  512,  0, lift_b,      y,     512,  0, 1024, 512,  1024, 0, 2, 0,   0, 0, cur);
        gb.d[4] = mk_gemm(xs, 1024, 0,   wss, 1536, 0, sself_bqkv,  qkv_s, 1536, 0, 1024, 1536, 512,  0, 2, 512, 0, 0, cur);
        gb.d[5] = mk_gemm(xs, 1024, 512, wsc, 1536, 0, scross_bqkv, q_sc,  512,  0, 1024, 512,  512,  0, 2, 512, 0, 0, cur);
        gb.n = 6;
        gemm_batch_kernel<<<cur, 256, SMEM_GEMM>>>(gb);
    }
    // ---- L2: kv_fc (needs y) + pool2 (needs h1) ----
    {
        GemmBatch gb; int cur = 0;
        gb.d[0] = mk_gemm(y,  512,  0, wfc, 1536, 512, fcross_bqkv + 512, kv_fc, 1024, 0, 1024, 1024, 512,  0, 2, 0, 0, 0, cur);
        gb.d[1] = mk_gemm(h1, 2048, 0, wp2, 512,  0,   pool_b2,           s,     512,  0, 1024, 512,  2048, 0, 2, 0, 0, 0, cur);
        gb.n = 2;
        gemm_batch_kernel<<<cur, 256, SMEM_GEMM>>>(gb);
    }
    // ---- L3: kv_sc on shifted s ----
    {
        GemmBatch gb; int cur = 0;
        gb.d[0] = mk_gemm(s, 512, 0, wsc, 1536, 512, scross_bqkv + 512, kv_sc, 1024, 0, 1024, 1024, 512, 1, 2, 0, 0, 0, cur);
        gb.n = 1;
        gemm_batch_kernel<<<cur, 256, SMEM_GEMM>>>(gb);
    }
    // ---- L4: all four attentions ----
    {
        AttnBatch ab; int cur = 0;
        ab.d[0] = mk_attn(qkv_f, 1536, 0, qkv_f, 1536, 512, qkv_f, 1536, 1024, o1, 512, LF_, LF_, cur);
        ab.d[1] = mk_attn(q_fc,  512,  0, kv_fc, 1024, 0,   kv_fc, 1024, 512,  o2, 512, LF_, TS_, cur);
        ab.d[2] = mk_attn(qkv_s, 1536, 0, qkv_s, 1536, 512, qkv_s, 1536, 1024, o3, 512, TS_, TS_, cur);
        ab.d[3] = mk_attn(q_sc,  512,  0, kv_sc, 1024, 0,   kv_sc, 1024, 512,  o4, 512, TS_, TS_, cur);
        ab.n = 4;
        attn_batch_kernel<<<cur, 128, SMEM_ATTN>>>(ab);
    }
    // ---- L5: all four out-projections ----
    {
        GemmBatch gb; int cur = 0;
        gb.d[0] = mk_gemm(o1, 512, 0, wof,  512, 0, fself_bo,  zf, 1024, 0,   4096, 512, 512, 0, 0, 0, 0, 0, cur);
        gb.d[1] = mk_gemm(o2, 512, 0, woc,  512, 0, fcross_bo, zf, 1024, 512, 4096, 512, 512, 0, 0, 0, 0, 0, cur);
        gb.d[2] = mk_gemm(o3, 512, 0, wos,  512, 0, sself_bo,  zs, 1024, 0,   1024, 512, 512, 0, 0, 0, 0, 0, cur);
        gb.d[3] = mk_gemm(o4, 512, 0, wosc, 512, 0, scross_bo, zs, 1024, 512, 1024, 512, 512, 0, 0, 0, 0, 0, cur);
        gb.n = 4;
        gemm_batch_kernel<<<cur, 256, SMEM_GEMM>>>(gb);
    }
}